// round 13
// baseline (speedup 1.0000x reference)
#include <cuda_runtime.h>
#include <cuda_bf16.h>
#include <mma.h>
#include <cstdint>

using namespace nvcuda;

#define BATCH 2
#define SEQ   8192
#define DIMC  1024
#define NH    16
#define HD    64
#define CHUNK 128
#define NT    64
#define NROWS 16384
#define QKVN  3072
#define SCALE_ATTN 0.125f
#define EPS_BIT 1.1920929e-07f
#define EPS_OUT 1e-06f

// s8 tile-major padded layout: [rowblk][kt 16][row 128][80 bytes], cols 0..63 meaningful
#define TPAD8 80
#define TILE8_BYTES (128 * TPAD8)        // 10240 bytes per tile

// ---------------- static device scratch ----------------
__device__ int8_t        g_xq[(size_t)(NROWS / 128) * 16 * TILE8_BYTES];
__device__ float         g_adeq[NROWS];
__device__ int8_t        g_wq_qkv[(size_t)(QKVN / 128) * 16 * TILE8_BYTES];
__device__ int8_t        g_wq_proj[(size_t)(DIMC / 128) * 16 * TILE8_BYTES];
__device__ float         g_wdeq[2];
__device__ float         g_part[256];
__device__ float         g_q[(size_t)BATCH * NH * NT * CHUNK * HD];
__device__ float         g_k[(size_t)BATCH * NH * NT * CHUNK * HD];
__device__ float         g_v[(size_t)BATCH * NH * NT * CHUNK * HD];
__device__ float         g_kvsum[(size_t)BATCH * NH * NT * HD * HD];
__device__ float         g_kvpre[(size_t)BATCH * NH * NT * HD * HD];
__device__ float         g_attn[(size_t)NROWS * DIMC];
__device__ int8_t        g_xq2[(size_t)(NROWS / 128) * 16 * TILE8_BYTES];
__device__ float         g_adeq2[NROWS];

// ---------------- helpers ----------------
__device__ __forceinline__ uint32_t smem_u32(const void* smem_ptr) {
    uint32_t addr;
    asm("{ .reg .u64 tmp; cvta.to.shared.u64 tmp, %1; cvt.u32.u64 %0, tmp; }"
        : "=r"(addr) : "l"(smem_ptr));
    return addr;
}

#define MBAR_INIT(addr, cnt) \
    asm volatile("mbarrier.init.shared.b64 [%0], %1;" :: "r"((uint32_t)(addr)), "r"((uint32_t)(cnt)) : "memory")
#define MBAR_ARRIVE(addr) \
    asm volatile("mbarrier.arrive.shared.b64 _, [%0];" :: "r"((uint32_t)(addr)) : "memory")
#define MBAR_EXPECT_TX(addr, bytes) \
    asm volatile("mbarrier.arrive.expect_tx.shared.b64 _, [%0], %1;" :: "r"((uint32_t)(addr)), "r"((uint32_t)(bytes)) : "memory")
#define MBAR_WAIT_PARITY(mbar, parity) do { \
    uint32_t _mbar = (uint32_t)(mbar); \
    uint32_t _parity = (uint32_t)(parity); \
    uint32_t _done; \
    asm volatile( \
        "{\n\t.reg .pred p;\n\t" \
        "mbarrier.try_wait.parity.shared.b64 p, [%1], %2;\n\t" \
        "selp.b32 %0, 1, 0, p;\n\t}" \
        : "=r"(_done) : "r"(_mbar), "r"(_parity) : "memory"); \
    if (!_done) { \
        asm volatile( \
            "{\n\t.reg .pred P1;\n\t" \
            "WAIT_LOOP_%=:\n\t" \
            "mbarrier.try_wait.parity.shared.b64 P1, [%0], %1;\n\t" \
            "@P1 bra.uni WAIT_DONE_%=;\n\t" \
            "bra.uni WAIT_LOOP_%=;\n\t" \
            "WAIT_DONE_%=:\n\t}" \
            :: "r"(_mbar), "r"(_parity) : "memory"); \
    } \
} while(0)
#define BULK_G2S(dst, src, bytes, mbar) \
    asm volatile("cp.async.bulk.shared::cta.global.mbarrier::complete_tx::bytes [%0], [%1], %2, [%3];" \
        :: "r"((uint32_t)(dst)), "l"(src), "r"((uint32_t)(bytes)), "r"((uint32_t)(mbar)) : "memory")

__device__ __forceinline__ void ldm_x4(uint32_t addr, uint32_t& r0, uint32_t& r1,
                                       uint32_t& r2, uint32_t& r3) {
    asm volatile("ldmatrix.sync.aligned.m8n8.x4.shared.b16 {%0,%1,%2,%3}, [%4];"
        : "=r"(r0), "=r"(r1), "=r"(r2), "=r"(r3) : "r"(addr));
}
__device__ __forceinline__ void imma16832(int* c, uint32_t a0, uint32_t a1,
                                          uint32_t a2, uint32_t a3,
                                          uint32_t b0, uint32_t b1) {
    asm volatile("mma.sync.aligned.m16n8k32.row.col.s32.s8.s8.s32 "
        "{%0,%1,%2,%3}, {%4,%5,%6,%7}, {%8,%9}, {%0,%1,%2,%3};"
        : "+r"(c[0]), "+r"(c[1]), "+r"(c[2]), "+r"(c[3])
        : "r"(a0), "r"(a1), "r"(a2), "r"(a3), "r"(b0), "r"(b1));
}

__device__ __forceinline__ float fexp(float x) {
    x = fmaxf(x, -80.0f);
    float y = x * 1.4426950408889634f;
    float n = rintf(y);
    float g = fmaf(-n, 0.6931471805599453f, x);
    float p = 1.9841270e-4f;
    p = fmaf(p, g, 1.3888889e-3f);
    p = fmaf(p, g, 8.3333333e-3f);
    p = fmaf(p, g, 4.1666667e-2f);
    p = fmaf(p, g, 1.6666667e-1f);
    p = fmaf(p, g, 5.0e-1f);
    p = fmaf(p, g, 1.0f);
    p = fmaf(p, g, 1.0f);
    float s = __int_as_float(((int)n + 127) << 23);
    return p * s;
}
__device__ __forceinline__ void split2(float v, __nv_bfloat16& hi, __nv_bfloat16& lo) {
    hi = __float2bfloat16(v);
    lo = __float2bfloat16(v - __bfloat162float(hi));
}
__device__ __forceinline__ void split4(float4 v,
    __nv_bfloat162& h01, __nv_bfloat162& l01,
    __nv_bfloat162& h23, __nv_bfloat162& l23) {
    h01.x = __float2bfloat16(v.x); l01.x = __float2bfloat16(v.x - __bfloat162float(h01.x));
    h01.y = __float2bfloat16(v.y); l01.y = __float2bfloat16(v.y - __bfloat162float(h01.y));
    h23.x = __float2bfloat16(v.z); l23.x = __float2bfloat16(v.z - __bfloat162float(h23.x));
    h23.y = __float2bfloat16(v.w); l23.y = __float2bfloat16(v.w - __bfloat162float(h23.y));
}
// byte index in s8 tile-major padded layout for logical (row, col) of a [*,1024] matrix
__device__ __forceinline__ size_t tile_idx8(int row, int col) {
    return (((size_t)(row >> 7) * 16 + (col >> 6)) * 128 + (row & 127)) * TPAD8 + (col & 63);
}
// float (rounded+clamped) -> packed 4x s8 via int (aarch64: plain char is unsigned!)
__device__ __forceinline__ uint32_t pack_s8(float a, float b, float c, float d) {
    int ia = (int)a, ib = (int)b, ic = (int)c, id = (int)d;
    return (uint32_t)(ia & 0xFF) | ((uint32_t)(ib & 0xFF) << 8) |
           ((uint32_t)(ic & 0xFF) << 16) | ((uint32_t)(id & 0xFF) << 24);
}

// ---------------- weight quant ----------------
__global__ void absmean_partial(const float* __restrict__ w, int n) {
    __shared__ float red[256];
    int tid = threadIdx.x;
    float s = 0.f;
    for (int i = blockIdx.x * 256 + tid; i < n; i += 65536) s += fabsf(w[i]);
    red[tid] = s; __syncthreads();
    for (int st = 128; st > 0; st >>= 1) { if (tid < st) red[tid] += red[tid + st]; __syncthreads(); }
    if (tid == 0) g_part[blockIdx.x] = red[0];
}

__global__ void __launch_bounds__(256) quant_weight_fused(const float* __restrict__ w,
                                                          int8_t* __restrict__ wq,
                                                          int n, int slot) {
    __shared__ float red[256];
    int tid = threadIdx.x;
    red[tid] = g_part[tid]; __syncthreads();
    for (int st = 128; st > 0; st >>= 1) { if (tid < st) red[tid] += red[tid + st]; __syncthreads(); }
    float wdeq = fmaxf(red[0] / (float)n, 1e-5f);
    if (blockIdx.x == 0 && tid == 0) g_wdeq[slot] = wdeq;
    float s = 1.0f / wdeq;
    int i4 = (blockIdx.x * 256 + tid) * 4;
    if (i4 >= n) return;
    float4 wv = *(const float4*)(w + i4);
    float a = fminf(fmaxf(rintf(wv.x * s), -1.f), 1.f);
    float b = fminf(fmaxf(rintf(wv.y * s), -1.f), 1.f);
    float c = fminf(fmaxf(rintf(wv.z * s), -1.f), 1.f);
    float d = fminf(fmaxf(rintf(wv.w * s), -1.f), 1.f);
    int row = i4 >> 10, col = i4 & 1023;
    *(uint32_t*)(wq + tile_idx8(row, col)) = pack_s8(a, b, c, d);
}

// ---------------- activation quant for QKV input ----------------
__global__ void __launch_bounds__(256) act_quant_x(const float* __restrict__ x,
                                                   const float* __restrict__ nw) {
    __shared__ float red[256];
    __shared__ float bc;
    int row = blockIdx.x, tid = threadIdx.x;
    float4 xv = ((const float4*)(x + (size_t)row * DIMC))[tid];
    float4 wv = ((const float4*)nw)[tid];
    float ss = xv.x*xv.x + xv.y*xv.y + xv.z*xv.z + xv.w*xv.w;
    red[tid] = ss; __syncthreads();
    for (int st = 128; st > 0; st >>= 1) { if (tid < st) red[tid] += red[tid + st]; __syncthreads(); }
    if (tid == 0) bc = rsqrtf(red[0] * (1.0f / DIMC) + EPS_BIT);
    __syncthreads();
    float r = bc;
    float n0 = xv.x*r*wv.x, n1 = xv.y*r*wv.y, n2 = xv.z*r*wv.z, n3 = xv.w*r*wv.w;
    float amax = fmaxf(fmaxf(fabsf(n0), fabsf(n1)), fmaxf(fabsf(n2), fabsf(n3)));
    red[tid] = amax; __syncthreads();
    for (int st = 128; st > 0; st >>= 1) { if (tid < st) red[tid] = fmaxf(red[tid], red[tid + st]); __syncthreads(); }
    if (tid == 0) {
        float mx = fmaxf(red[0], 1e-5f);
        bc = 127.0f / mx;
        g_adeq[row] = mx * (1.0f / 127.0f);
    }
    __syncthreads();
    float sc = bc;
    float a = fminf(fmaxf(rintf(n0 * sc), -128.f), 127.f);
    float b = fminf(fmaxf(rintf(n1 * sc), -128.f), 127.f);
    float c = fminf(fmaxf(rintf(n2 * sc), -128.f), 127.f);
    float d = fminf(fmaxf(rintf(n3 * sc), -128.f), 127.f);
    *(uint32_t*)(g_xq + tile_idx8(row, tid * 4)) = pack_s8(a, b, c, d);
}

// ---------------- double-norm + act quant for proj input ----------------
__global__ void __launch_bounds__(256) norm2_quant(const float* __restrict__ nw,
                                                   const float* __restrict__ pnw) {
    __shared__ float red[256];
    __shared__ float bc;
    int row = blockIdx.x, tid = threadIdx.x;
    float4 xv = ((const float4*)(g_attn + (size_t)row * DIMC))[tid];
    float4 wv = ((const float4*)nw)[tid];
    float4 pv = ((const float4*)pnw)[tid];
    float ss = xv.x*xv.x + xv.y*xv.y + xv.z*xv.z + xv.w*xv.w;
    red[tid] = ss; __syncthreads();
    for (int st = 128; st > 0; st >>= 1) { if (tid < st) red[tid] += red[tid + st]; __syncthreads(); }
    if (tid == 0) bc = rsqrtf(red[0] * (1.0f / DIMC) + EPS_OUT);
    __syncthreads();
    float r1 = bc;
    float z0 = xv.x*r1*wv.x, z1 = xv.y*r1*wv.y, z2 = xv.z*r1*wv.z, z3 = xv.w*r1*wv.w;
    float ss2 = z0*z0 + z1*z1 + z2*z2 + z3*z3;
    red[tid] = ss2; __syncthreads();
    for (int st = 128; st > 0; st >>= 1) { if (tid < st) red[tid] += red[tid + st]; __syncthreads(); }
    if (tid == 0) bc = rsqrtf(red[0] * (1.0f / DIMC) + EPS_BIT);
    __syncthreads();
    float r2 = bc;
    float n0 = z0*r2*pv.x, n1 = z1*r2*pv.y, n2 = z2*r2*pv.z, n3 = z3*r2*pv.w;
    float amax = fmaxf(fmaxf(fabsf(n0), fabsf(n1)), fmaxf(fabsf(n2), fabsf(n3)));
    red[tid] = amax; __syncthreads();
    for (int st = 128; st > 0; st >>= 1) { if (tid < st) red[tid] = fmaxf(red[tid], red[tid + st]); __syncthreads(); }
    if (tid == 0) {
        float mx = fmaxf(red[0], 1e-5f);
        bc = 127.0f / mx;
        g_adeq2[row] = mx * (1.0f / 127.0f);
    }
    __syncthreads();
    float sc = bc;
    float a = fminf(fmaxf(rintf(n0 * sc), -128.f), 127.f);
    float b = fminf(fmaxf(rintf(n1 * sc), -128.f), 127.f);
    float c = fminf(fmaxf(rintf(n2 * sc), -128.f), 127.f);
    float d = fminf(fmaxf(rintf(n3 * sc), -128.f), 127.f);
    *(uint32_t*)(g_xq2 + tile_idx8(row, tid * 4)) = pack_s8(a, b, c, d);
}

// ---------------- s8 IMMA GEMM: block 128x256, warp tile 64x64 ----------------
// raw mma.sync.m16n8k32 + ldmatrix; bulk 3-stage ring with producer/consumer mbarriers.
#define BSTAGE (3 * TILE8_BYTES)              // A(1 tile) + B(2 tiles) = 30720
#define MBAR_OFF (3 * BSTAGE)                 // 92160; full[0..2] then empty[0..2]
#define GEMM_SMEM (MBAR_OFF + 128)
template<bool QKV>
__global__ void __launch_bounds__(256) gemm_s8_t(
    const int8_t* __restrict__ A, const int8_t* __restrict__ W,
    float* __restrict__ C, int N,
    const float* __restrict__ adeq, int wslot, const float* __restrict__ bias,
    const float* __restrict__ cosb, const float* __restrict__ sinb)
{
    extern __shared__ __align__(16) char gsm[];
    uint32_t sb = smem_u32(gsm);
    uint32_t fullb  = sb + MBAR_OFF;
    uint32_t emptyb = sb + MBAR_OFF + 24;

    int tid = threadIdx.x;
    int wid = tid >> 5, lane = tid & 31;
    int wm = wid >> 2, wn = wid & 3;            // warp tile 64(M) x 64(N)
    int bm = blockIdx.y * 128;
    int bn = blockIdx.x * 256;

    const int8_t* Asrc  = A + (size_t)blockIdx.y * 16 * TILE8_BYTES;
    const int8_t* Bsrc0 = W + (size_t)(2 * blockIdx.x)     * 16 * TILE8_BYTES;
    const int8_t* Bsrc1 = W + (size_t)(2 * blockIdx.x + 1) * 16 * TILE8_BYTES;

    int c[4][8][4];
    #pragma unroll
    for (int i = 0; i < 4; i++)
        #pragma unroll
        for (int j = 0; j < 8; j++)
            #pragma unroll
            for (int e = 0; e < 4; e++) c[i][j][e] = 0;

    if (tid == 0) {
        #pragma unroll
        for (int s = 0; s < 3; s++) {
            MBAR_INIT(fullb  + s * 8, 1);
            MBAR_INIT(emptyb + s * 8, 8);
        }
    }
    __syncthreads();
    if (tid == 0) {
        #pragma unroll
        for (int s = 0; s < 2; s++) {
            MBAR_EXPECT_TX(fullb + s * 8, BSTAGE);
            BULK_G2S(sb + s * BSTAGE,                   Asrc  + s * TILE8_BYTES, TILE8_BYTES, fullb + s * 8);
            BULK_G2S(sb + s * BSTAGE + TILE8_BYTES,     Bsrc0 + s * TILE8_BYTES, TILE8_BYTES, fullb + s * 8);
            BULK_G2S(sb + s * BSTAGE + 2 * TILE8_BYTES, Bsrc1 + s * TILE8_BYTES, TILE8_BYTES, fullb + s * 8);
        }
    }

    int m0 = wm * 64;
    int bhalf = (wn >> 1);
    int n0 = (wn & 1) * 64;
    // ldmatrix per-lane address components
    uint32_t aoff = (uint32_t)(m0 + (lane & 15)) * TPAD8 + (lane >> 4) * 16;
    uint32_t boff = (uint32_t)(n0 + (lane & 7))  * TPAD8 + (lane >> 3) * 16;

    for (int kt = 0; kt < 16; kt++) {
        int sRead = kt % 3;
        if (tid == 0 && kt + 2 < 16) {
            int sW = (kt + 2) % 3;
            if (kt >= 1) MBAR_WAIT_PARITY(emptyb + sW * 8, ((kt - 1) / 3) & 1);
            MBAR_EXPECT_TX(fullb + sW * 8, BSTAGE);
            BULK_G2S(sb + sW * BSTAGE,                   Asrc  + (kt + 2) * TILE8_BYTES, TILE8_BYTES, fullb + sW * 8);
            BULK_G2S(sb + sW * BSTAGE + TILE8_BYTES,     Bsrc0 + (kt + 2) * TILE8_BYTES, TILE8_BYTES, fullb + sW * 8);
            BULK_G2S(sb + sW * BSTAGE + 2 * TILE8_BYTES, Bsrc1 + (kt + 2) * TILE8_BYTES, TILE8_BYTES, fullb + sW * 8);
        }
        MBAR_WAIT_PARITY(fullb + sRead * 8, (kt / 3) & 1);
        uint32_t Abase = sb + sRead * BSTAGE + aoff;
        uint32_t Bbase = sb + sRead * BSTAGE + TILE8_BYTES + bhalf * TILE8_BYTES + boff;

        uint32_t a[4][2][4];
        #pragma unroll
        for (int i = 0; i < 4; i++)
            #pragma unroll
            for (int q = 0; q < 2; q++)
                ldm_x4(Abase + i * (16 * TPAD8) + q * 32,
                       a[i][q][0], a[i][q][1], a[i][q][2], a[i][q][3]);
        #pragma unroll
        for (int j = 0; j < 8; j++) {
            uint32_t b0, b1, b2, b3;
            ldm_x4(Bbase + j * (8 * TPAD8), b0, b1, b2, b3);
            #pragma unroll
            for (int i = 0; i < 4; i++) {
                imma16832(c[i][j], a[i][0][0], a[i][0][1], a[i][0][2], a[i][0][3], b0, b1);
                imma16832(c[i][j], a[i][1][0], a[i][1][1], a[i][1][2], a[i][1][3], b2, b3);
            }
        }
        if (lane == 0) MBAR_ARRIVE(emptyb + sRead * 8);
    }
    __syncthreads();   // all MMAs done; stage smem reusable for C staging

    float wdeq = g_wdeq[wslot];
    float* CsAll = (float*)gsm;
    float* Csw = &CsAll[wid * 320];
    int g = lane >> 2, t4 = lane & 3;
    #pragma unroll
    for (int i = 0; i < 4; i++) {
        #pragma unroll
        for (int jp = 0; jp < 4; jp++) {
            __syncwarp();
            #pragma unroll
            for (int which = 0; which < 2; which++) {
                int j = 2 * jp + which;
                int cb = which * 8 + 2 * t4;
                Csw[g * 20 + cb]            = (float)c[i][j][0];
                Csw[g * 20 + cb + 1]        = (float)c[i][j][1];
                Csw[(g + 8) * 20 + cb]      = (float)c[i][j][2];
                Csw[(g + 8) * 20 + cb + 1]  = (float)c[i][j][3];
            }
            __syncwarp();
            int r  = lane >> 1;
            int cc = (lane & 1) * 8;
            int grow = bm + wm * 64 + i * 16 + r;
            int gcol = bn + wn * 64 + jp * 16 + cc;
            float sc = adeq[grow] * wdeq;
            float v[8];
            #pragma unroll
            for (int u = 0; u < 8; u++)
                v[u] = Csw[r * 20 + cc + u] * sc + bias[gcol + u];
            if (QKV) {
                int which = gcol >> 10;
                int rem = gcol & 1023;
                int h = rem >> 6, d = rem & 63;
                int b = grow >> 13, n = grow & 8191;
                int t = n >> 7, rr = n & 127;
                if (which < 2) {
                    int i0 = d >> 1;
                    #pragma unroll
                    for (int m = 0; m < 4; m++) {
                        float cth = cosb[n * 32 + i0 + m];
                        float sth = sinb[n * 32 + i0 + m];
                        float e = v[2*m], o = v[2*m+1];
                        v[2*m]   = e * cth - o * sth;
                        v[2*m+1] = o * cth + e * sth;
                    }
                }
                float* dstbase = (which == 0) ? g_q : (which == 1) ? g_k : g_v;
                float* dst = dstbase + (((size_t)b * NH + h) * NT + t) * (CHUNK * HD)
                           + (size_t)rr * 64 + d;
                *(float4*)(dst)     = make_float4(v[0], v[1], v[2], v[3]);
                *(float4*)(dst + 4) = make_float4(v[4], v[5], v[6], v[7]);
            } else {
                float* dst = C + (size_t)grow * N + gcol;
                *(float4*)(dst)     = make_float4(v[0], v[1], v[2], v[3]);
                *(float4*)(dst + 4) = make_float4(v[4], v[5], v[6], v[7]);
            }
        }
    }
}

// ---------------- intra-chunk attention (split-bf16 tensor cores) ----------------
#define QHI_OFF 0
#define QLO_OFF (128*72)
#define KHI_OFF (2*128*72)
#define KLO_OFF (3*128*72)
#define PHI_OFF (4*128*72)
#define PLO_OFF (4*128*72 + 128*136)
#define BF_TOTAL (4*128*72 + 2*128*136)
#define SS_LD 132

__global__ void __launch_bounds__(512) attn_intra() {
    int t = blockIdx.x, h = blockIdx.y, b = blockIdx.z;
    extern __shared__ __align__(16) char smraw[];
    __nv_bfloat16* bfm = (__nv_bfloat16*)smraw;
    float* sS = (float*)(smraw + (size_t)BF_TOTAL * 2);
    float* rowsum = sS + 128 * SS_LD;

    __nv_bfloat16* sQhi = bfm + QHI_OFF;
    __nv_bfloat16* sQlo = bfm + QLO_OFF;
    __nv_bfloat16* sKhi = bfm + KHI_OFF;
    __nv_bfloat16* sKlo = bfm + KLO_OFF;
    __nv_bfloat16* sPhi = bfm + PHI_OFF;
    __nv_bfloat16* sPlo = bfm + PLO_OFF;
    __nv_bfloat16* sVhi = sQhi;
    __nv_bfloat16* sVlo = sQlo;

    size_t base = (((size_t)b * NH + h) * NT + t) * (CHUNK * HD);
    int tid = threadIdx.x;
    int wid = tid >> 5;

    #pragma unroll
    for (int u = 0; u < 4; u++) {
        int i = tid + u * 512;
        int r = i >> 4, c4 = (i & 15) * 4;
        float4 qv = *(const float4*)(g_q + base + (size_t)r * 64 + c4);
        float4 kv = *(const float4*)(g_k + base + (size_t)r * 64 + c4);
        __nv_bfloat162 h01, l01, h23, l23;
        split4(qv, h01, l01, h23, l23);
        *(__nv_bfloat162*)(sQhi + r*72 + c4)     = h01;
        *(__nv_bfloat162*)(sQhi + r*72 + c4 + 2) = h23;
        *(__nv_bfloat162*)(sQlo + r*72 + c4)     = l01;
        *(__nv_bfloat162*)(sQlo + r*72 + c4 + 2) = l23;
        split4(kv, h01, l01, h23, l23);
        *(__nv_bfloat162*)(sKhi + r*72 + c4)     = h01;
        *(__nv_bfloat162*)(sKhi + r*72 + c4 + 2) = h23;
        *(__nv_bfloat162*)(sKlo + r*72 + c4)     = l01;
        *(__nv_bfloat162*)(sKlo + r*72 + c4 + 2) = l23;
    }
    __syncthreads();

    // QK^T: 16 warps, warp tile 16 rows x 64 cols
    {
        int r0 = (wid >> 1) * 16;
        int cbase = (wid & 1) * 64;
        wmma::fragment<wmma::accumulator, 16, 16, 16, float> c[4];
        #pragma unroll
        for (int j = 0; j < 4; j++) wmma::fill_fragment(c[j], 0.0f);
        #pragma unroll
        for (int sk = 0; sk < 4; sk++) {
            int k0 = sk * 16;
            wmma::fragment<wmma::matrix_a, 16, 16, 16, __nv_bfloat16, wmma::row_major> ah, al;
            wmma::load_matrix_sync(ah, &sQhi[r0 * 72 + k0], 72);
            wmma::load_matrix_sync(al, &sQlo[r0 * 72 + k0], 72);
            #pragma unroll
            for (int j = 0; j < 4; j++) {
                int col0 = cbase + j * 16;
                wmma::fragment<wmma::matrix_b, 16, 16, 16, __nv_bfloat16, wmma::col_major> bh, bl;
                wmma::load_matrix_sync(bh, &sKhi[col0 * 72 + k0], 72);
                wmma::load_matrix_sync(bl, &sKlo[col0 * 72 + k0], 72);
                wmma::mma_sync(c[j], ah, bh, c[j]);
                wmma::mma_sync(c[j], ah, bl, c[j]);
                wmma::mma_sync(c[j], al, bh, c[j]);
            }
        }
        #pragma unroll
        for (int j = 0; j < 4; j++) {
            #pragma unroll
            for (int e = 0; e < c[j].num_elements; e++) c[j].x[e] *= SCALE_ATTN;
            wmma::store_matrix_sync(&sS[r0 * SS_LD + cbase + j * 16], c[j], SS_LD, wmma::mem_row_major);
        }
    }
    __syncthreads();

    // softmax: 4 threads per row
    {
        int r = tid >> 2;
        int c0 = (tid & 3) * 32;
        float mx = -3.0e38f;
        for (int c = c0; c < c0 + 32; c++)
            if (c <= r) mx = fmaxf(mx, sS[r * SS_LD + c]);
        mx = fmaxf(mx, __shfl_xor_sync(0xffffffffu, mx, 1));
        mx = fmaxf(mx, __shfl_xor_sync(0xffffffffu, mx, 2));
        float sum = 0.f;
        for (int c = c0; c < c0 + 32; c++) {
            float e = (c <= r) ? fexp(sS[r * SS_LD + c] - mx) : 0.f;
            sum += e;
            __nv_bfloat16 hi, lo;
            split2(e, hi, lo);
            sPhi[r * 136 + c] = hi;
            sPlo[r * 136 + c] = lo;
        }
        sum += __shfl_xor_sync(0xffffffffu, sum, 1);
        sum += __shfl_xor_sync(0xffffffffu, sum, 2);
        if ((tid & 3) == 0) rowsum[r] = sum;
    }
    // V load into Q slots
    #pragma unroll
    for (int u = 0; u < 4; u++) {
        int i = tid + u * 512;
        int r = i >> 4, c4 = (i & 15) * 4;
        float4 vv = *(const float4*)(g_v + base + (size_t)r * 64 + c4);
        __nv_bfloat162 h01, l01, h23, l23;
        split4(vv, h01, l01, h23, l23);
        *(__nv_bfloat162*)(sVhi + r*72 + c4)     = h01;
        *(__nv_bfloat162*)(sVhi + r*72 + c4 + 2) = h23;
        *(__nv_bfloat162*)(sVlo + r*72 + c4)     = l01;
        *(__nv_bfloat162*)(sVlo + r*72 + c4 + 2) = l23;
    }
    __syncthreads();

    // S_t = K^T V (64x64): one 16x16 tile per warp
    {
        int d0 = (wid >> 2) * 16;
        int e0 = (wid & 3) * 16;
        wmma::fragment<wmma::accumulator, 16, 16, 16, float> c;
        wmma::fill_fragment(c, 0.0f);
        #pragma unroll
        for (int sk = 0; sk < 8; sk++) {
            int r0 = sk * 16;
            wmma::fragment<wmma::matrix_a, 16, 16, 16, __nv_bfloat16, wmma::col_major> ah, al;
            wmma::fragment<wmma::matrix_b, 16, 16, 16, __nv_bfloat16, wmma::row_major> bh, bl;
            wmma::load_matrix_sync(ah, &sKhi[r0 * 72 + d0], 72);
            wmma::load_matrix_sync(al, &sKlo[r0 * 72 + d0], 72);
            wmma::load_matrix_sync(bh, &sVhi[r0 * 72 + e0], 72);
            wmma::load_matrix_sync(bl, &sVlo[r0 * 72 + e0], 72);
            wmma::mma_sync(c, ah, bh, c);
            wmma::mma_sync(c, ah, bl, c);
            wmma::mma_sync(c, al, bh, c);
        }
        size_t kb = (((size_t)b * NH + h) * NT + t) * (HD * HD);
        wmma::store_matrix_sync(g_kvsum + kb + (size_t)d0 * 64 + e0, c, 64, wmma::mem_row_major);
    }

    // o_intra = P @ V (128x64): warp tile 16x32
    {
        int r0 = (wid >> 1) * 16;
        int cbase = (wid & 1) * 32;
        wmma::fragment<wmma::accumulator, 16, 16, 16, float> c[2];
        #pragma unroll
        for (int j = 0; j < 2; j++) wmma::fill_fragment(c[j], 0.0f);
        #pragma unroll
        for (int sk = 0; sk < 8; sk++) {
            int k0 = sk * 16;
            wmma::fragment<wmma::matrix_a, 16, 16, 16, __nv_bfloat16, wmma::row_major> ah, al;
            wmma::load_matrix_sync(ah, &sPhi[r0 * 136 + k0], 136);
            wmma::load_matrix_sync(al, &sPlo[r0 * 136 + k0], 136);
            #pragma unroll
            for (int j = 0; j < 2; j++) {
                int col0 = cbase + j * 16;
                wmma::fragment<wmma::matrix_b, 16, 16, 16, __nv_bfloat16, wmma::row_major> bh, bl;
                wmma::load_matrix_sync(bh, &sVhi[k0 * 72 + col0], 72);
                wmma::load_matrix_sync(bl, &sVlo[k0 * 72 + col0], 72);
                wmma::mma_sync(c[j], ah, bh, c[j]);
                wmma::mma_sync(c[j], ah, bl, c[j]);
                wmma::mma_sync(c[j], al, bh, c[j]);
            }
        }
        __syncthreads();
        #pragma unroll
        for (int j = 0; j < 2; j++)
            wmma::store_matrix_sync(&sS[r0 * SS_LD + cbase + j * 16], c[j], SS_LD, wmma::mem_row_major);
    }
    __syncthreads();

    #pragma unroll
    for (int u = 0; u < 4; u++) {
        int i = tid + u * 512;
        int r = i >> 4, c4 = (i & 15) * 4;
        float inv = 1.0f / rowsum[r];
        float4 o;
        o.x = sS[r * SS_LD + c4 + 0] * inv;
        o.y = sS[r * SS_LD + c4 + 1] * inv;
        o.z = sS[r * SS_LD + c4 + 2] * inv;
        o.w = sS[r * SS_LD + c4 + 3] * inv;
        size_t grow = (size_t)b * SEQ + (size_t)t * CHUNK + r;
        *(float4*)(g_attn + grow * DIMC + h * 64 + c4) = o;
    }
}

// ---------------- exclusive prefix-sum of chunk KV matrices ----------------
__global__ void __launch_bounds__(256) kv_prefix() {
    int blk = blockIdx.x;
    int bh = blk >> 3, s = blk & 7;
    int tid = threadIdx.x;
    size_t base = (size_t)bh * NT * (HD * HD) + s * 512 + tid * 2;
    float2 acc = make_float2(0.f, 0.f);
    for (int t = 0; t < NT; t++) {
        size_t off = base + (size_t)t * (HD * HD);
        float2 v = *(const float2*)(g_kvsum + off);
        *(float2*)(g_kvpre + off) = acc;
        acc.x += v.x; acc.y += v.y;
    }
}

// ---------------- o_inter = q @ kv_prefix ----------------
#define IQHI 0
#define IQLO (128*72)
#define IKHI (2*128*72)
#define IKLO (2*128*72 + 64*72)
#define IBF_TOTAL (2*128*72 + 2*64*72)
__global__ void __launch_bounds__(256) attn_inter() {
    int t = blockIdx.x, h = blockIdx.y, b = blockIdx.z;
    extern __shared__ __align__(16) char smraw2[];
    __nv_bfloat16* bfm = (__nv_bfloat16*)smraw2;
    float* sO = (float*)(smraw2 + (size_t)IBF_TOTAL * 2);

    __nv_bfloat16* sQhi = bfm + IQHI;
    __nv_bfloat16* sQlo = bfm + IQLO;
    __nv_bfloat16* sKhi = bfm + IKHI;
    __nv_bfloat16* sKlo = bfm + IKLO;

    size_t base = (((size_t)b * NH + h) * NT + t) * (CHUNK * HD);
    size_t kb   = (((size_t)b * NH + h) * NT + t) * (HD * HD);
    int tid = threadIdx.x;
    int wid = tid >> 5;

    #pragma unroll
    for (int u = 0; u < 8; u++) {
        int i = tid + u * 256;
        int r = i >> 4, c4 = (i & 15) * 4;
        float4 qv = *(const float4*)(g_q + base + (size_t)r * 64 + c4);
        __nv_bfloat162 h01, l01, h23, l23;
        split4(qv, h01, l01, h23, l23);
        *(__nv_bfloat162*)(sQhi + r*72 + c4)     = h01;
        *(__nv_bfloat162*)(sQhi + r*72 + c4 + 2) = h23;
        *(__nv_bfloat162*)(sQlo + r*72 + c4)     = l01;
        *(__nv_bfloat162*)(sQlo + r*72 + c4 + 2) = l23;
    }
    #pragma unroll
    for (int u = 0; u < 4; u++) {
        int i = tid + u * 256;
        int r = i >> 4, c4 = (i & 15) * 4;
        float4 kv = *(const float4*)(g_kvpre + kb + (size_t)r * 64 + c4);
        __nv_bfloat162 h01, l01, h23, l23;
        split4(kv, h01, l01, h23, l23);
        *(__nv_bfloat162*)(sKhi + r*72 + c4)     = h01;
        *(__nv_bfloat162*)(sKhi + r*72 + c4 + 2) = h23;
        *(__nv_bfloat162*)(sKlo + r*72 + c4)     = l01;
        *(__nv_bfloat162*)(sKlo + r*72 + c4 + 2) = l23;
    }
    __syncthreads();

    {
        int r0 = wid * 16;
        wmma::fragment<wmma::accumulator, 16, 16, 16, float> c[4];
        #pragma unroll
        for (int j = 0; j < 4; j++) wmma::fill_fragment(c[j], 0.0f);
        #pragma unroll
        for (int sk = 0; sk < 4; sk++) {
            int k0 = sk * 16;
            wmma::fragment<wmma::matrix_a, 16, 16, 16, __nv_bfloat16, wmma::row_major> ah, al;
            wmma::load_matrix_sync(ah, &sQhi[r0 * 72 + k0], 72);
            wmma::load_matrix_sync(al, &sQlo[r0 * 72 + k0], 72);
            #pragma unroll
            for (int j = 0; j < 4; j++) {
                int col0 = j * 16;
                wmma::fragment<wmma::matrix_b, 16, 16, 16, __nv_bfloat16, wmma::row_major> bh, bl;
                wmma::load_matrix_sync(bh, &sKhi[k0 * 72 + col0], 72);
                wmma::load_matrix_sync(bl, &sKlo[k0 * 72 + col0], 72);
                wmma::mma_sync(c[j], ah, bh, c[j]);
                wmma::mma_sync(c[j], ah, bl, c[j]);
                wmma::mma_sync(c[j], al, bh, c[j]);
            }
        }
        #pragma unroll
        for (int j = 0; j < 4; j++)
            wmma::store_matrix_sync(&sO[r0 * 68 + j * 16], c[j], 68, wmma::mem_row_major);
    }
    __syncthreads();

    #pragma unroll
    for (int u = 0; u < 8; u++) {
        int i = tid + u * 256;
        int r = i >> 4, c4 = (i & 15) * 4;
        size_t grow = (size_t)b * SEQ + (size_t)t * CHUNK + r;
        float* dst = g_attn + grow * DIMC + h * 64 + c4;
        float4 old = *(float4*)dst;
        old.x += sO[r * 68 + c4 + 0];
        old.y += sO[r * 68 + c4 + 1];
        old.z += sO[r * 68 + c4 + 2];
        old.w += sO[r * 68 + c4 + 3];
        *(float4*)dst = old;
    }
}

// ---------------- launch ----------------
extern "C" void kernel_launch(void* const* d_in, const int* in_sizes, int n_in,
                              void* d_out, int out_size) {
    const float* x       = (const float*)d_in[0];
    const float* cosb    = (const float*)d_in[1];
    const float* sinb    = (const float*)d_in[2];
    const float* qkv_w   = (const float*)d_in[3];
    const float* qkv_b   = (const float*)d_in[4];
    const float* qkv_nw  = (const float*)d_in[5];
    const float* proj_w  = (const float*)d_in[6];
    const float* proj_b  = (const float*)d_in[7];
    const float* proj_nw = (const float*)d_in[8];
    const float* norm_w  = (const float*)d_in[9];
    float* out = (float*)d_out;

    size_t smem_intra = (size_t)BF_TOTAL * 2 + (128 * SS_LD + 128) * sizeof(float);
    size_t smem_inter = (size_t)IBF_TOTAL * 2 + (128 * 68) * sizeof(float);

    static bool attr_done = false;
    if (!attr_done) {
        cudaFuncSetAttribute(attn_intra, cudaFuncAttributeMaxDynamicSharedMemorySize, (int)smem_intra);
        cudaFuncSetAttribute(attn_inter, cudaFuncAttributeMaxDynamicSharedMemorySize, (int)smem_inter);
        cudaFuncSetAttribute(gemm_s8_t<true>,  cudaFuncAttributeMaxDynamicSharedMemorySize, GEMM_SMEM);
        cudaFuncSetAttribute(gemm_s8_t<false>, cudaFuncAttributeMaxDynamicSharedMemorySize, GEMM_SMEM);
        attr_done = true;
    }

    int8_t *xq_p, *wqkv_p, *wproj_p, *xq2_p;
    float *adeq_p, *adeq2_p;
    cudaGetSymbolAddress((void**)&xq_p,    g_xq);
    cudaGetSymbolAddress((void**)&wqkv_p,  g_wq_qkv);
    cudaGetSymbolAddress((void**)&wproj_p, g_wq_proj);
    cudaGetSymbolAddress((void**)&xq2_p,   g_xq2);
    cudaGetSymbolAddress((void**)&adeq_p,  g_adeq);
    cudaGetSymbolAddress((void**)&adeq2_p, g_adeq2);

    // Launch order: gemm<QKV> is launch #4 -> ncu capture slot.
    absmean_partial<<<256, 256>>>(qkv_w, QKVN * DIMC);                                    // 1
    quant_weight_fused<<<QKVN * DIMC / 1024, 256>>>(qkv_w, wqkv_p, QKVN * DIMC, 0);       // 2
    act_quant_x<<<NROWS, 256>>>(x, qkv_nw);                                               // 3
    {
        dim3 grid(QKVN / 256, NROWS / 128);
        gemm_s8_t<true><<<grid, 256, GEMM_SMEM>>>(xq_p, wqkv_p, nullptr, QKVN,
                                                  adeq_p, 0, qkv_b, cosb, sinb);          // 4 <- profiled
    }
    absmean_partial<<<256, 256>>>(proj_w, DIMC * DIMC);                                   // 5
    quant_weight_fused<<<DIMC * DIMC / 1024, 256>>>(proj_w, wproj_p, DIMC * DIMC, 1);     // 6

    {
        dim3 grid(NT, NH, BATCH);
        attn_intra<<<grid, 512, smem_intra>>>();                                          // 7
    }
    kv_prefix<<<256, 256>>>();                                                            // 8
    {
        dim3 grid(NT, NH, BATCH);
        attn_inter<<<grid, 256, smem_inter>>>();                                          // 9
    }

    norm2_quant<<<NROWS, 256>>>(norm_w, proj_nw);                                         // 10
    {
        dim3 grid(DIMC / 256, NROWS / 128);
        gemm_s8_t<false><<<grid, 256, GEMM_SMEM>>>(xq2_p, wproj_p, out, DIMC,
                                                   adeq2_p, 1, proj_b, cosb, sinb);       // 11
    }
}

// round 14
// speedup vs baseline: 1.6753x; 1.6753x over previous
#include <cuda_runtime.h>
#include <cuda_bf16.h>
#include <mma.h>
#include <cstdint>

using namespace nvcuda;

#define BATCH 2
#define SEQ   8192
#define DIMC  1024
#define NH    16
#define HD    64
#define CHUNK 128
#define NT    64
#define NROWS 16384
#define QKVN  3072
#define SCALE_ATTN 0.125f
#define EPS_BIT 1.1920929e-07f
#define EPS_OUT 1e-06f

// tile-major padded layout: [rowblk][kt 16][row 128][72], only cols 0..63 meaningful
#define TPAD 72
#define TILE_ELEMS (128 * TPAD)          // 9216 elems
#define TILE_BYTES (TILE_ELEMS * 2)      // 18432 bytes

// ---------------- static device scratch ----------------
__device__ __nv_bfloat16 g_xq[(size_t)NROWS * 16 * TILE_ELEMS / 128];
__device__ float         g_adeq[NROWS];
__device__ __nv_bfloat16 g_wq_qkv[(size_t)QKVN * 16 * TILE_ELEMS / 128];
__device__ __nv_bfloat16 g_wq_proj[(size_t)DIMC * 16 * TILE_ELEMS / 128];
__device__ float         g_wdeq[2];
__device__ float         g_part[256];
__device__ float         g_q[(size_t)BATCH * NH * NT * CHUNK * HD];
__device__ float         g_k[(size_t)BATCH * NH * NT * CHUNK * HD];
__device__ float         g_v[(size_t)BATCH * NH * NT * CHUNK * HD];
__device__ float         g_kvsum[(size_t)BATCH * NH * NT * HD * HD];
__device__ float         g_kvpre[(size_t)BATCH * NH * NT * HD * HD];
__device__ float         g_attn[(size_t)NROWS * DIMC];
__device__ __nv_bfloat16 g_xq2[(size_t)NROWS * 16 * TILE_ELEMS / 128];
__device__ float         g_adeq2[NROWS];

// ---------------- helpers ----------------
__device__ __forceinline__ uint32_t smem_u32(const void* smem_ptr) {
    uint32_t addr;
    asm("{ .reg .u64 tmp; cvta.to.shared.u64 tmp, %1; cvt.u32.u64 %0, tmp; }"
        : "=r"(addr) : "l"(smem_ptr));
    return addr;
}

#define MBAR_INIT(addr, cnt) \
    asm volatile("mbarrier.init.shared.b64 [%0], %1;" :: "r"((uint32_t)(addr)), "r"((uint32_t)(cnt)) : "memory")
#define MBAR_ARRIVE(addr) \
    asm volatile("mbarrier.arrive.shared.b64 _, [%0];" :: "r"((uint32_t)(addr)) : "memory")
#define MBAR_EXPECT_TX(addr, bytes) \
    asm volatile("mbarrier.arrive.expect_tx.shared.b64 _, [%0], %1;" :: "r"((uint32_t)(addr)), "r"((uint32_t)(bytes)) : "memory")
#define MBAR_WAIT_PARITY(mbar, parity) do { \
    uint32_t _mbar = (uint32_t)(mbar); \
    uint32_t _parity = (uint32_t)(parity); \
    uint32_t _done; \
    asm volatile( \
        "{\n\t.reg .pred p;\n\t" \
        "mbarrier.try_wait.parity.shared.b64 p, [%1], %2;\n\t" \
        "selp.b32 %0, 1, 0, p;\n\t}" \
        : "=r"(_done) : "r"(_mbar), "r"(_parity) : "memory"); \
    if (!_done) { \
        asm volatile( \
            "{\n\t.reg .pred P1;\n\t" \
            "WAIT_LOOP_%=:\n\t" \
            "mbarrier.try_wait.parity.shared.b64 P1, [%0], %1;\n\t" \
            "@P1 bra.uni WAIT_DONE_%=;\n\t" \
            "bra.uni WAIT_LOOP_%=;\n\t" \
            "WAIT_DONE_%=:\n\t}" \
            :: "r"(_mbar), "r"(_parity) : "memory"); \
    } \
} while(0)
#define BULK_G2S(dst, src, bytes, mbar) \
    asm volatile("cp.async.bulk.shared::cta.global.mbarrier::complete_tx::bytes [%0], [%1], %2, [%3];" \
        :: "r"((uint32_t)(dst)), "l"(src), "r"((uint32_t)(bytes)), "r"((uint32_t)(mbar)) : "memory")

__device__ __forceinline__ float fexp(float x) {
    x = fmaxf(x, -80.0f);
    float y = x * 1.4426950408889634f;
    float n = rintf(y);
    float g = fmaf(-n, 0.6931471805599453f, x);
    float p = 1.9841270e-4f;
    p = fmaf(p, g, 1.3888889e-3f);
    p = fmaf(p, g, 8.3333333e-3f);
    p = fmaf(p, g, 4.1666667e-2f);
    p = fmaf(p, g, 1.6666667e-1f);
    p = fmaf(p, g, 5.0e-1f);
    p = fmaf(p, g, 1.0f);
    p = fmaf(p, g, 1.0f);
    float s = __int_as_float(((int)n + 127) << 23);
    return p * s;
}
__device__ __forceinline__ void split2(float v, __nv_bfloat16& hi, __nv_bfloat16& lo) {
    hi = __float2bfloat16(v);
    lo = __float2bfloat16(v - __bfloat162float(hi));
}
__device__ __forceinline__ void split4(float4 v,
    __nv_bfloat162& h01, __nv_bfloat162& l01,
    __nv_bfloat162& h23, __nv_bfloat162& l23) {
    h01.x = __float2bfloat16(v.x); l01.x = __float2bfloat16(v.x - __bfloat162float(h01.x));
    h01.y = __float2bfloat16(v.y); l01.y = __float2bfloat16(v.y - __bfloat162float(h01.y));
    h23.x = __float2bfloat16(v.z); l23.x = __float2bfloat16(v.z - __bfloat162float(h23.x));
    h23.y = __float2bfloat16(v.w); l23.y = __float2bfloat16(v.w - __bfloat162float(h23.y));
}
__device__ __forceinline__ size_t tile_idx(int row, int col) {
    return (((size_t)(row >> 7) * 16 + (col >> 6)) * 128 + (row & 127)) * TPAD + (col & 63);
}

// ---------------- weight quant ----------------
__global__ void absmean_partial(const float* __restrict__ w, int n) {
    __shared__ float red[256];
    int tid = threadIdx.x;
    float s = 0.f;
    for (int i = blockIdx.x * 256 + tid; i < n; i += 65536) s += fabsf(w[i]);
    red[tid] = s; __syncthreads();
    for (int st = 128; st > 0; st >>= 1) { if (tid < st) red[tid] += red[tid + st]; __syncthreads(); }
    if (tid == 0) g_part[blockIdx.x] = red[0];
}

__global__ void __launch_bounds__(256) quant_weight_fused(const float* __restrict__ w,
                                                          __nv_bfloat16* __restrict__ wq,
                                                          int n, int slot) {
    __shared__ float red[256];
    int tid = threadIdx.x;
    red[tid] = g_part[tid]; __syncthreads();
    for (int st = 128; st > 0; st >>= 1) { if (tid < st) red[tid] += red[tid + st]; __syncthreads(); }
    float wdeq = fmaxf(red[0] / (float)n, 1e-5f);
    if (blockIdx.x == 0 && tid == 0) g_wdeq[slot] = wdeq;
    float s = 1.0f / wdeq;
    int i4 = (blockIdx.x * 256 + tid) * 4;
    if (i4 >= n) return;
    float4 wv = *(const float4*)(w + i4);
    __nv_bfloat162 p0, p1;
    p0.x = __float2bfloat16(fminf(fmaxf(rintf(wv.x * s), -1.f), 1.f));
    p0.y = __float2bfloat16(fminf(fmaxf(rintf(wv.y * s), -1.f), 1.f));
    p1.x = __float2bfloat16(fminf(fmaxf(rintf(wv.z * s), -1.f), 1.f));
    p1.y = __float2bfloat16(fminf(fmaxf(rintf(wv.w * s), -1.f), 1.f));
    int row = i4 >> 10, col = i4 & 1023;
    __nv_bfloat16* out = wq + tile_idx(row, col);
    *(__nv_bfloat162*)(out)     = p0;
    *(__nv_bfloat162*)(out + 2) = p1;
}

// ---------------- activation quant for QKV input ----------------
__global__ void __launch_bounds__(256) act_quant_x(const float* __restrict__ x,
                                                   const float* __restrict__ nw) {
    __shared__ float red[256];
    __shared__ float bc;
    int row = blockIdx.x, tid = threadIdx.x;
    float4 xv = ((const float4*)(x + (size_t)row * DIMC))[tid];
    float4 wv = ((const float4*)nw)[tid];
    float ss = xv.x*xv.x + xv.y*xv.y + xv.z*xv.z + xv.w*xv.w;
    red[tid] = ss; __syncthreads();
    for (int st = 128; st > 0; st >>= 1) { if (tid < st) red[tid] += red[tid + st]; __syncthreads(); }
    if (tid == 0) bc = rsqrtf(red[0] * (1.0f / DIMC) + EPS_BIT);
    __syncthreads();
    float r = bc;
    float n0 = xv.x*r*wv.x, n1 = xv.y*r*wv.y, n2 = xv.z*r*wv.z, n3 = xv.w*r*wv.w;
    float amax = fmaxf(fmaxf(fabsf(n0), fabsf(n1)), fmaxf(fabsf(n2), fabsf(n3)));
    red[tid] = amax; __syncthreads();
    for (int st = 128; st > 0; st >>= 1) { if (tid < st) red[tid] = fmaxf(red[tid], red[tid + st]); __syncthreads(); }
    if (tid == 0) {
        float mx = fmaxf(red[0], 1e-5f);
        bc = 127.0f / mx;
        g_adeq[row] = mx * (1.0f / 127.0f);
    }
    __syncthreads();
    float sc = bc;
    __nv_bfloat162 p0, p1;
    p0.x = __float2bfloat16(fminf(fmaxf(rintf(n0 * sc), -128.f), 127.f));
    p0.y = __float2bfloat16(fminf(fmaxf(rintf(n1 * sc), -128.f), 127.f));
    p1.x = __float2bfloat16(fminf(fmaxf(rintf(n2 * sc), -128.f), 127.f));
    p1.y = __float2bfloat16(fminf(fmaxf(rintf(n3 * sc), -128.f), 127.f));
    __nv_bfloat16* out = g_xq + tile_idx(row, tid * 4);
    *(__nv_bfloat162*)(out)     = p0;
    *(__nv_bfloat162*)(out + 2) = p1;
}

// ---------------- double-norm + act quant for proj input ----------------
__global__ void __launch_bounds__(256) norm2_quant(const float* __restrict__ nw,
                                                   const float* __restrict__ pnw) {
    __shared__ float red[256];
    __shared__ float bc;
    int row = blockIdx.x, tid = threadIdx.x;
    float4 xv = ((const float4*)(g_attn + (size_t)row * DIMC))[tid];
    float4 wv = ((const float4*)nw)[tid];
    float4 pv = ((const float4*)pnw)[tid];
    float ss = xv.x*xv.x + xv.y*xv.y + xv.z*xv.z + xv.w*xv.w;
    red[tid] = ss; __syncthreads();
    for (int st = 128; st > 0; st >>= 1) { if (tid < st) red[tid] += red[tid + st]; __syncthreads(); }
    if (tid == 0) bc = rsqrtf(red[0] * (1.0f / DIMC) + EPS_OUT);
    __syncthreads();
    float r1 = bc;
    float z0 = xv.x*r1*wv.x, z1 = xv.y*r1*wv.y, z2 = xv.z*r1*wv.z, z3 = xv.w*r1*wv.w;
    float ss2 = z0*z0 + z1*z1 + z2*z2 + z3*z3;
    red[tid] = ss2; __syncthreads();
    for (int st = 128; st > 0; st >>= 1) { if (tid < st) red[tid] += red[tid + st]; __syncthreads(); }
    if (tid == 0) bc = rsqrtf(red[0] * (1.0f / DIMC) + EPS_BIT);
    __syncthreads();
    float r2 = bc;
    float n0 = z0*r2*pv.x, n1 = z1*r2*pv.y, n2 = z2*r2*pv.z, n3 = z3*r2*pv.w;
    float amax = fmaxf(fmaxf(fabsf(n0), fabsf(n1)), fmaxf(fabsf(n2), fabsf(n3)));
    red[tid] = amax; __syncthreads();
    for (int st = 128; st > 0; st >>= 1) { if (tid < st) red[tid] = fmaxf(red[tid], red[tid + st]); __syncthreads(); }
    if (tid == 0) {
        float mx = fmaxf(red[0], 1e-5f);
        bc = 127.0f / mx;
        g_adeq2[row] = mx * (1.0f / 127.0f);
    }
    __syncthreads();
    float sc = bc;
    __nv_bfloat162 p0, p1;
    p0.x = __float2bfloat16(fminf(fmaxf(rintf(n0 * sc), -128.f), 127.f));
    p0.y = __float2bfloat16(fminf(fmaxf(rintf(n1 * sc), -128.f), 127.f));
    p1.x = __float2bfloat16(fminf(fmaxf(rintf(n2 * sc), -128.f), 127.f));
    p1.y = __float2bfloat16(fminf(fmaxf(rintf(n3 * sc), -128.f), 127.f));
    __nv_bfloat16* out = g_xq2 + tile_idx(row, tid * 4);
    *(__nv_bfloat162*)(out)     = p0;
    *(__nv_bfloat162*)(out + 2) = p1;
}

// ---------------- bf16 HMMA GEMM: block 128x128, warp 64x32, 2 CTAs/SM ----------------
// bulk 3-stage ring with producer/consumer mbarriers, NO per-K-tile __syncthreads.
#define GLD TPAD
#define BSTAGE (2 * TILE_BYTES)               // A + B per stage = 36864
#define MBAR_OFF (3 * BSTAGE)                 // 110592; full[0..2] then empty[0..2]
#define GEMM_SMEM (MBAR_OFF + 128)
template<bool QKV>
__global__ void __launch_bounds__(256, 2) gemm_bf16_t(
    const __nv_bfloat16* __restrict__ A, const __nv_bfloat16* __restrict__ W,
    float* __restrict__ C, int N,
    const float* __restrict__ adeq, int wslot, const float* __restrict__ bias,
    const float* __restrict__ cosb, const float* __restrict__ sinb)
{
    extern __shared__ __align__(16) char gsm[];
    uint32_t sb = smem_u32(gsm);
    uint32_t fullb  = sb + MBAR_OFF;
    uint32_t emptyb = sb + MBAR_OFF + 24;

    int tid = threadIdx.x;
    int wid = tid >> 5, lane = tid & 31;
    int wm = wid >> 2, wn = wid & 3;            // warp tile 64(M) x 32(N)
    int bm = blockIdx.y * 128;
    int bn = blockIdx.x * 128;

    const __nv_bfloat16* Asrc = A + (size_t)blockIdx.y * 16 * TILE_ELEMS;
    const __nv_bfloat16* Bsrc = W + (size_t)blockIdx.x * 16 * TILE_ELEMS;

    wmma::fragment<wmma::accumulator, 16, 16, 16, float> c[4][2];
    #pragma unroll
    for (int i = 0; i < 4; i++)
        #pragma unroll
        for (int j = 0; j < 2; j++) wmma::fill_fragment(c[i][j], 0.0f);

    if (tid == 0) {
        #pragma unroll
        for (int s = 0; s < 3; s++) {
            MBAR_INIT(fullb  + s * 8, 1);
            MBAR_INIT(emptyb + s * 8, 8);   // one arrive per warp
        }
    }
    __syncthreads();
    if (tid == 0) {
        #pragma unroll
        for (int s = 0; s < 2; s++) {
            MBAR_EXPECT_TX(fullb + s * 8, BSTAGE);
            BULK_G2S(sb + s * BSTAGE,              Asrc + s * TILE_ELEMS, TILE_BYTES, fullb + s * 8);
            BULK_G2S(sb + s * BSTAGE + TILE_BYTES, Bsrc + s * TILE_ELEMS, TILE_BYTES, fullb + s * 8);
        }
    }

    int m0 = wm * 64, n0 = wn * 32;
    for (int kt = 0; kt < 16; kt++) {
        int sRead = kt % 3;
        // producer: refill stage (kt+2)%3 once iteration kt-1's readers release it
        if (tid == 0 && kt + 2 < 16) {
            int sW = (kt + 2) % 3;
            if (kt >= 1) MBAR_WAIT_PARITY(emptyb + sW * 8, ((kt - 1) / 3) & 1);
            MBAR_EXPECT_TX(fullb + sW * 8, BSTAGE);
            BULK_G2S(sb + sW * BSTAGE,              Asrc + (kt + 2) * TILE_ELEMS, TILE_BYTES, fullb + sW * 8);
            BULK_G2S(sb + sW * BSTAGE + TILE_BYTES, Bsrc + (kt + 2) * TILE_ELEMS, TILE_BYTES, fullb + sW * 8);
        }
        // consumer: wait stage full (per-warp; no CTA barrier)
        MBAR_WAIT_PARITY(fullb + sRead * 8, (kt / 3) & 1);
        const __nv_bfloat16* as = (const __nv_bfloat16*)(gsm + sRead * BSTAGE);
        const __nv_bfloat16* bs = (const __nv_bfloat16*)(gsm + sRead * BSTAGE + TILE_BYTES);
        #pragma unroll
        for (int sk = 0; sk < 4; sk++) {
            int k0 = sk * 16;
            wmma::fragment<wmma::matrix_a, 16, 16, 16, __nv_bfloat16, wmma::row_major> af[4];
            wmma::fragment<wmma::matrix_b, 16, 16, 16, __nv_bfloat16, wmma::col_major> bf[2];
            #pragma unroll
            for (int i = 0; i < 4; i++)
                wmma::load_matrix_sync(af[i], &as[(m0 + i * 16) * GLD + k0], GLD);
            #pragma unroll
            for (int j = 0; j < 2; j++)
                wmma::load_matrix_sync(bf[j], &bs[(n0 + j * 16) * GLD + k0], GLD);
            #pragma unroll
            for (int i = 0; i < 4; i++)
                #pragma unroll
                for (int j = 0; j < 2; j++)
                    wmma::mma_sync(c[i][j], af[i], bf[j], c[i][j]);
        }
        // release the stage (one arrive per warp)
        if (lane == 0) MBAR_ARRIVE(emptyb + sRead * 8);
    }
    __syncthreads();   // all MMAs done; stage smem reusable for C staging

    float wdeq = g_wdeq[wslot];
    float* CsAll = (float*)gsm;
    float* Csw = &CsAll[wid * 320];
    #pragma unroll
    for (int i = 0; i < 4; i++) {
        #pragma unroll
        for (int j = 0; j < 2; j++) {
            __syncwarp();
            wmma::store_matrix_sync(Csw, c[i][j], 20, wmma::mem_row_major);
            __syncwarp();
            int r  = lane >> 1;
            int cc = (lane & 1) * 8;
            int grow = bm + wm * 64 + i * 16 + r;
            int gcol = bn + wn * 32 + j * 16 + cc;
            float sc = adeq[grow] * wdeq;
            float v[8];
            #pragma unroll
            for (int u = 0; u < 8; u++)
                v[u] = Csw[r * 20 + cc + u] * sc + bias[gcol + u];
            if (QKV) {
                int which = gcol >> 10;
                int rem = gcol & 1023;
                int h = rem >> 6, d = rem & 63;
                int b = grow >> 13, n = grow & 8191;
                int t = n >> 7, rr = n & 127;
                if (which < 2) {
                    int i0 = d >> 1;
                    #pragma unroll
                    for (int m = 0; m < 4; m++) {
                        float cth = cosb[n * 32 + i0 + m];
                        float sth = sinb[n * 32 + i0 + m];
                        float e = v[2*m], o = v[2*m+1];
                        v[2*m]   = e * cth - o * sth;
                        v[2*m+1] = o * cth + e * sth;
                    }
                }
                float* dstbase = (which == 0) ? g_q : (which == 1) ? g_k : g_v;
                float* dst = dstbase + (((size_t)b * NH + h) * NT + t) * (CHUNK * HD)
                           + (size_t)rr * 64 + d;
                *(float4*)(dst)     = make_float4(v[0], v[1], v[2], v[3]);
                *(float4*)(dst + 4) = make_float4(v[4], v[5], v[6], v[7]);
            } else {
                float* dst = C + (size_t)grow * N + gcol;
                *(float4*)(dst)     = make_float4(v[0], v[1], v[2], v[3]);
                *(float4*)(dst + 4) = make_float4(v[4], v[5], v[6], v[7]);
            }
        }
    }
}

// ---------------- intra-chunk attention (split-bf16 tensor cores) ----------------
#define QHI_OFF 0
#define QLO_OFF (128*72)
#define KHI_OFF (2*128*72)
#define KLO_OFF (3*128*72)
#define PHI_OFF (4*128*72)
#define PLO_OFF (4*128*72 + 128*136)
#define BF_TOTAL (4*128*72 + 2*128*136)
#define SS_LD 132

__global__ void __launch_bounds__(512) attn_intra() {
    int t = blockIdx.x, h = blockIdx.y, b = blockIdx.z;
    extern __shared__ __align__(16) char smraw[];
    __nv_bfloat16* bfm = (__nv_bfloat16*)smraw;
    float* sS = (float*)(smraw + (size_t)BF_TOTAL * 2);
    float* rowsum = sS + 128 * SS_LD;

    __nv_bfloat16* sQhi = bfm + QHI_OFF;
    __nv_bfloat16* sQlo = bfm + QLO_OFF;
    __nv_bfloat16* sKhi = bfm + KHI_OFF;
    __nv_bfloat16* sKlo = bfm + KLO_OFF;
    __nv_bfloat16* sPhi = bfm + PHI_OFF;
    __nv_bfloat16* sPlo = bfm + PLO_OFF;
    __nv_bfloat16* sVhi = sQhi;
    __nv_bfloat16* sVlo = sQlo;

    size_t base = (((size_t)b * NH + h) * NT + t) * (CHUNK * HD);
    int tid = threadIdx.x;
    int wid = tid >> 5;

    #pragma unroll
    for (int u = 0; u < 4; u++) {
        int i = tid + u * 512;
        int r = i >> 4, c4 = (i & 15) * 4;
        float4 qv = *(const float4*)(g_q + base + (size_t)r * 64 + c4);
        float4 kv = *(const float4*)(g_k + base + (size_t)r * 64 + c4);
        __nv_bfloat162 h01, l01, h23, l23;
        split4(qv, h01, l01, h23, l23);
        *(__nv_bfloat162*)(sQhi + r*72 + c4)     = h01;
        *(__nv_bfloat162*)(sQhi + r*72 + c4 + 2) = h23;
        *(__nv_bfloat162*)(sQlo + r*72 + c4)     = l01;
        *(__nv_bfloat162*)(sQlo + r*72 + c4 + 2) = l23;
        split4(kv, h01, l01, h23, l23);
        *(__nv_bfloat162*)(sKhi + r*72 + c4)     = h01;
        *(__nv_bfloat162*)(sKhi + r*72 + c4 + 2) = h23;
        *(__nv_bfloat162*)(sKlo + r*72 + c4)     = l01;
        *(__nv_bfloat162*)(sKlo + r*72 + c4 + 2) = l23;
    }
    __syncthreads();

    // QK^T: 16 warps, warp tile 16 rows x 64 cols
    {
        int r0 = (wid >> 1) * 16;
        int cbase = (wid & 1) * 64;
        wmma::fragment<wmma::accumulator, 16, 16, 16, float> c[4];
        #pragma unroll
        for (int j = 0; j < 4; j++) wmma::fill_fragment(c[j], 0.0f);
        #pragma unroll
        for (int sk = 0; sk < 4; sk++) {
            int k0 = sk * 16;
            wmma::fragment<wmma::matrix_a, 16, 16, 16, __nv_bfloat16, wmma::row_major> ah, al;
            wmma::load_matrix_sync(ah, &sQhi[r0 * 72 + k0], 72);
            wmma::load_matrix_sync(al, &sQlo[r0 * 72 + k0], 72);
            #pragma unroll
            for (int j = 0; j < 4; j++) {
                int col0 = cbase + j * 16;
                wmma::fragment<wmma::matrix_b, 16, 16, 16, __nv_bfloat16, wmma::col_major> bh, bl;
                wmma::load_matrix_sync(bh, &sKhi[col0 * 72 + k0], 72);
                wmma::load_matrix_sync(bl, &sKlo[col0 * 72 + k0], 72);
                wmma::mma_sync(c[j], ah, bh, c[j]);
                wmma::mma_sync(c[j], ah, bl, c[j]);
                wmma::mma_sync(c[j], al, bh, c[j]);
            }
        }
        #pragma unroll
        for (int j = 0; j < 4; j++) {
            #pragma unroll
            for (int e = 0; e < c[j].num_elements; e++) c[j].x[e] *= SCALE_ATTN;
            wmma::store_matrix_sync(&sS[r0 * SS_LD + cbase + j * 16], c[j], SS_LD, wmma::mem_row_major);
        }
    }
    __syncthreads();

    // softmax: 4 threads per row
    {
        int r = tid >> 2;
        int c0 = (tid & 3) * 32;
        float mx = -3.0e38f;
        for (int c = c0; c < c0 + 32; c++)
            if (c <= r) mx = fmaxf(mx, sS[r * SS_LD + c]);
        mx = fmaxf(mx, __shfl_xor_sync(0xffffffffu, mx, 1));
        mx = fmaxf(mx, __shfl_xor_sync(0xffffffffu, mx, 2));
        float sum = 0.f;
        for (int c = c0; c < c0 + 32; c++) {
            float e = (c <= r) ? fexp(sS[r * SS_LD + c] - mx) : 0.f;
            sum += e;
            __nv_bfloat16 hi, lo;
            split2(e, hi, lo);
            sPhi[r * 136 + c] = hi;
            sPlo[r * 136 + c] = lo;
        }
        sum += __shfl_xor_sync(0xffffffffu, sum, 1);
        sum += __shfl_xor_sync(0xffffffffu, sum, 2);
        if ((tid & 3) == 0) rowsum[r] = sum;
    }
    // V load into Q slots
    #pragma unroll
    for (int u = 0; u < 4; u++) {
        int i = tid + u * 512;
        int r = i >> 4, c4 = (i & 15) * 4;
        float4 vv = *(const float4*)(g_v + base + (size_t)r * 64 + c4);
        __nv_bfloat162 h01, l01, h23, l23;
        split4(vv, h01, l01, h23, l23);
        *(__nv_bfloat162*)(sVhi + r*72 + c4)     = h01;
        *(__nv_bfloat162*)(sVhi + r*72 + c4 + 2) = h23;
        *(__nv_bfloat162*)(sVlo + r*72 + c4)     = l01;
        *(__nv_bfloat162*)(sVlo + r*72 + c4 + 2) = l23;
    }
    __syncthreads();

    // S_t = K^T V (64x64): one 16x16 tile per warp
    {
        int d0 = (wid >> 2) * 16;
        int e0 = (wid & 3) * 16;
        wmma::fragment<wmma::accumulator, 16, 16, 16, float> c;
        wmma::fill_fragment(c, 0.0f);
        #pragma unroll
        for (int sk = 0; sk < 8; sk++) {
            int r0 = sk * 16;
            wmma::fragment<wmma::matrix_a, 16, 16, 16, __nv_bfloat16, wmma::col_major> ah, al;
            wmma::fragment<wmma::matrix_b, 16, 16, 16, __nv_bfloat16, wmma::row_major> bh, bl;
            wmma::load_matrix_sync(ah, &sKhi[r0 * 72 + d0], 72);
            wmma::load_matrix_sync(al, &sKlo[r0 * 72 + d0], 72);
            wmma::load_matrix_sync(bh, &sVhi[r0 * 72 + e0], 72);
            wmma::load_matrix_sync(bl, &sVlo[r0 * 72 + e0], 72);
            wmma::mma_sync(c, ah, bh, c);
            wmma::mma_sync(c, ah, bl, c);
            wmma::mma_sync(c, al, bh, c);
        }
        size_t kb = (((size_t)b * NH + h) * NT + t) * (HD * HD);
        wmma::store_matrix_sync(g_kvsum + kb + (size_t)d0 * 64 + e0, c, 64, wmma::mem_row_major);
    }

    // o_intra = P @ V (128x64): warp tile 16x32
    {
        int r0 = (wid >> 1) * 16;
        int cbase = (wid & 1) * 32;
        wmma::fragment<wmma::accumulator, 16, 16, 16, float> c[2];
        #pragma unroll
        for (int j = 0; j < 2; j++) wmma::fill_fragment(c[j], 0.0f);
        #pragma unroll
        for (int sk = 0; sk < 8; sk++) {
            int k0 = sk * 16;
            wmma::fragment<wmma::matrix_a, 16, 16, 16, __nv_bfloat16, wmma::row_major> ah, al;
            wmma::load_matrix_sync(ah, &sPhi[r0 * 136 + k0], 136);
            wmma::load_matrix_sync(al, &sPlo[r0 * 136 + k0], 136);
            #pragma unroll
            for (int j = 0; j < 2; j++) {
                int col0 = cbase + j * 16;
                wmma::fragment<wmma::matrix_b, 16, 16, 16, __nv_bfloat16, wmma::row_major> bh, bl;
                wmma::load_matrix_sync(bh, &sVhi[k0 * 72 + col0], 72);
                wmma::load_matrix_sync(bl, &sVlo[k0 * 72 + col0], 72);
                wmma::mma_sync(c[j], ah, bh, c[j]);
                wmma::mma_sync(c[j], ah, bl, c[j]);
                wmma::mma_sync(c[j], al, bh, c[j]);
            }
        }
        __syncthreads();
        #pragma unroll
        for (int j = 0; j < 2; j++)
            wmma::store_matrix_sync(&sS[r0 * SS_LD + cbase + j * 16], c[j], SS_LD, wmma::mem_row_major);
    }
    __syncthreads();

    #pragma unroll
    for (int u = 0; u < 4; u++) {
        int i = tid + u * 512;
        int r = i >> 4, c4 = (i & 15) * 4;
        float inv = 1.0f / rowsum[r];
        float4 o;
        o.x = sS[r * SS_LD + c4 + 0] * inv;
        o.y = sS[r * SS_LD + c4 + 1] * inv;
        o.z = sS[r * SS_LD + c4 + 2] * inv;
        o.w = sS[r * SS_LD + c4 + 3] * inv;
        size_t grow = (size_t)b * SEQ + (size_t)t * CHUNK + r;
        *(float4*)(g_attn + grow * DIMC + h * 64 + c4) = o;
    }
}

// ---------------- exclusive prefix-sum of chunk KV matrices ----------------
__global__ void __launch_bounds__(256) kv_prefix() {
    int blk = blockIdx.x;
    int bh = blk >> 3, s = blk & 7;
    int tid = threadIdx.x;
    size_t base = (size_t)bh * NT * (HD * HD) + s * 512 + tid * 2;
    float2 acc = make_float2(0.f, 0.f);
    for (int t = 0; t < NT; t++) {
        size_t off = base + (size_t)t * (HD * HD);
        float2 v = *(const float2*)(g_kvsum + off);
        *(float2*)(g_kvpre + off) = acc;
        acc.x += v.x; acc.y += v.y;
    }
}

// ---------------- o_inter = q @ kv_prefix ----------------
#define IQHI 0
#define IQLO (128*72)
#define IKHI (2*128*72)
#define IKLO (2*128*72 + 64*72)
#define IBF_TOTAL (2*128*72 + 2*64*72)
__global__ void __launch_bounds__(256) attn_inter() {
    int t = blockIdx.x, h = blockIdx.y, b = blockIdx.z;
    extern __shared__ __align__(16) char smraw2[];
    __nv_bfloat16* bfm = (__nv_bfloat16*)smraw2;
    float* sO = (float*)(smraw2 + (size_t)IBF_TOTAL * 2);

    __nv_bfloat16* sQhi = bfm + IQHI;
    __nv_bfloat16* sQlo = bfm + IQLO;
    __nv_bfloat16* sKhi = bfm + IKHI;
    __nv_bfloat16* sKlo = bfm + IKLO;

    size_t base = (((size_t)b * NH + h) * NT + t) * (CHUNK * HD);
    size_t kb   = (((size_t)b * NH + h) * NT + t) * (HD * HD);
    int tid = threadIdx.x;
    int wid = tid >> 5;

    #pragma unroll
    for (int u = 0; u < 8; u++) {
        int i = tid + u * 256;
        int r = i >> 4, c4 = (i & 15) * 4;
        float4 qv = *(const float4*)(g_q + base + (size_t)r * 64 + c4);
        __nv_bfloat162 h01, l01, h23, l23;
        split4(qv, h01, l01, h23, l23);
        *(__nv_bfloat162*)(sQhi + r*72 + c4)     = h01;
        *(__nv_bfloat162*)(sQhi + r*72 + c4 + 2) = h23;
        *(__nv_bfloat162*)(sQlo + r*72 + c4)     = l01;
        *(__nv_bfloat162*)(sQlo + r*72 + c4 + 2) = l23;
    }
    #pragma unroll
    for (int u = 0; u < 4; u++) {
        int i = tid + u * 256;
        int r = i >> 4, c4 = (i & 15) * 4;
        float4 kv = *(const float4*)(g_kvpre + kb + (size_t)r * 64 + c4);
        __nv_bfloat162 h01, l01, h23, l23;
        split4(kv, h01, l01, h23, l23);
        *(__nv_bfloat162*)(sKhi + r*72 + c4)     = h01;
        *(__nv_bfloat162*)(sKhi + r*72 + c4 + 2) = h23;
        *(__nv_bfloat162*)(sKlo + r*72 + c4)     = l01;
        *(__nv_bfloat162*)(sKlo + r*72 + c4 + 2) = l23;
    }
    __syncthreads();

    {
        int r0 = wid * 16;
        wmma::fragment<wmma::accumulator, 16, 16, 16, float> c[4];
        #pragma unroll
        for (int j = 0; j < 4; j++) wmma::fill_fragment(c[j], 0.0f);
        #pragma unroll
        for (int sk = 0; sk < 4; sk++) {
            int k0 = sk * 16;
            wmma::fragment<wmma::matrix_a, 16, 16, 16, __nv_bfloat16, wmma::row_major> ah, al;
            wmma::load_matrix_sync(ah, &sQhi[r0 * 72 + k0], 72);
            wmma::load_matrix_sync(al, &sQlo[r0 * 72 + k0], 72);
            #pragma unroll
            for (int j = 0; j < 4; j++) {
                int col0 = j * 16;
                wmma::fragment<wmma::matrix_b, 16, 16, 16, __nv_bfloat16, wmma::row_major> bh, bl;
                wmma::load_matrix_sync(bh, &sKhi[k0 * 72 + col0], 72);
                wmma::load_matrix_sync(bl, &sKlo[k0 * 72 + col0], 72);
                wmma::mma_sync(c[j], ah, bh, c[j]);
                wmma::mma_sync(c[j], ah, bl, c[j]);
                wmma::mma_sync(c[j], al, bh, c[j]);
            }
        }
        #pragma unroll
        for (int j = 0; j < 4; j++)
            wmma::store_matrix_sync(&sO[r0 * 68 + j * 16], c[j], 68, wmma::mem_row_major);
    }
    __syncthreads();

    #pragma unroll
    for (int u = 0; u < 8; u++) {
        int i = tid + u * 256;
        int r = i >> 4, c4 = (i & 15) * 4;
        size_t grow = (size_t)b * SEQ + (size_t)t * CHUNK + r;
        float* dst = g_attn + grow * DIMC + h * 64 + c4;
        float4 old = *(float4*)dst;
        old.x += sO[r * 68 + c4 + 0];
        old.y += sO[r * 68 + c4 + 1];
        old.z += sO[r * 68 + c4 + 2];
        old.w += sO[r * 68 + c4 + 3];
        *(float4*)dst = old;
    }
}

// ---------------- launch ----------------
extern "C" void kernel_launch(void* const* d_in, const int* in_sizes, int n_in,
                              void* d_out, int out_size) {
    const float* x       = (const float*)d_in[0];
    const float* cosb    = (const float*)d_in[1];
    const float* sinb    = (const float*)d_in[2];
    const float* qkv_w   = (const float*)d_in[3];
    const float* qkv_b   = (const float*)d_in[4];
    const float* qkv_nw  = (const float*)d_in[5];
    const float* proj_w  = (const float*)d_in[6];
    const float* proj_b  = (const float*)d_in[7];
    const float* proj_nw = (const float*)d_in[8];
    const float* norm_w  = (const float*)d_in[9];
    float* out = (float*)d_out;

    size_t smem_intra = (size_t)BF_TOTAL * 2 + (128 * SS_LD + 128) * sizeof(float);
    size_t smem_inter = (size_t)IBF_TOTAL * 2 + (128 * 68) * sizeof(float);

    static bool attr_done = false;
    if (!attr_done) {
        cudaFuncSetAttribute(attn_intra, cudaFuncAttributeMaxDynamicSharedMemorySize, (int)smem_intra);
        cudaFuncSetAttribute(attn_inter, cudaFuncAttributeMaxDynamicSharedMemorySize, (int)smem_inter);
        cudaFuncSetAttribute(gemm_bf16_t<true>,  cudaFuncAttributeMaxDynamicSharedMemorySize, GEMM_SMEM);
        cudaFuncSetAttribute(gemm_bf16_t<false>, cudaFuncAttributeMaxDynamicSharedMemorySize, GEMM_SMEM);
        attr_done = true;
    }

    __nv_bfloat16 *xq_p, *wqkv_p, *wproj_p, *xq2_p;
    float *adeq_p, *adeq2_p;
    cudaGetSymbolAddress((void**)&xq_p,    g_xq);
    cudaGetSymbolAddress((void**)&wqkv_p,  g_wq_qkv);
    cudaGetSymbolAddress((void**)&wproj_p, g_wq_proj);
    cudaGetSymbolAddress((void**)&xq2_p,   g_xq2);
    cudaGetSymbolAddress((void**)&adeq_p,  g_adeq);
    cudaGetSymbolAddress((void**)&adeq2_p, g_adeq2);

    // Launch order: gemm<QKV> is launch #4 -> ncu capture slot.
    absmean_partial<<<256, 256>>>(qkv_w, QKVN * DIMC);                                    // 1
    quant_weight_fused<<<QKVN * DIMC / 1024, 256>>>(qkv_w, wqkv_p, QKVN * DIMC, 0);       // 2
    act_quant_x<<<NROWS, 256>>>(x, qkv_nw);                                               // 3
    {
        dim3 grid(QKVN / 128, NROWS / 128);
        gemm_bf16_t<true><<<grid, 256, GEMM_SMEM>>>(xq_p, wqkv_p, nullptr, QKVN,
                                                    adeq_p, 0, qkv_b, cosb, sinb);        // 4 <- profiled
    }
    absmean_partial<<<256, 256>>>(proj_w, DIMC * DIMC);                                   // 5
    quant_weight_fused<<<DIMC * DIMC / 1024, 256>>>(proj_w, wproj_p, DIMC * DIMC, 1);     // 6

    {
        dim3 grid(NT, NH, BATCH);
        attn_intra<<<grid, 512, smem_intra>>>();                                          // 7
    }
    kv_prefix<<<256, 256>>>();                                                            // 8
    {
        dim3 grid(NT, NH, BATCH);
        attn_inter<<<grid, 256, smem_inter>>>();                                          // 9
    }

    norm2_quant<<<NROWS, 256>>>(norm_w, proj_nw);                                         // 10
    {
        dim3 grid(DIMC / 128, NROWS / 128);
        gemm_bf16_t<false><<<grid, 256, GEMM_SMEM>>>(xq2_p, wproj_p, out, DIMC,
                                                     adeq2_p, 1, proj_b, cosb, sinb);     // 11
    }
}

// round 15
// speedup vs baseline: 1.7361x; 1.0363x over previous
#include <cuda_runtime.h>
#include <cuda_bf16.h>
#include <mma.h>
#include <cstdint>

using namespace nvcuda;

#define BATCH 2
#define SEQ   8192
#define DIMC  1024
#define NH    16
#define HD    64
#define CHUNK 128
#define NT    64
#define NROWS 16384
#define QKVN  3072
#define SCALE_ATTN 0.125f
#define EPS_BIT 1.1920929e-07f
#define EPS_OUT 1e-06f

// tile-major padded layout: [rowblk][kt 16][row 128][72], only cols 0..63 meaningful
#define TPAD 72
#define TILE_ELEMS (128 * TPAD)          // 9216 elems
#define TILE_BYTES (TILE_ELEMS * 2)      // 18432 bytes

// ---------------- static device scratch ----------------
__device__ __nv_bfloat16 g_xq[(size_t)NROWS * 16 * TILE_ELEMS / 128];
__device__ float         g_adeq[NROWS];
__device__ __nv_bfloat16 g_wq_qkv[(size_t)QKVN * 16 * TILE_ELEMS / 128];
__device__ __nv_bfloat16 g_wq_proj[(size_t)DIMC * 16 * TILE_ELEMS / 128];
__device__ float         g_wdeq[2];
__device__ float         g_part[256];
__device__ float         g_q[(size_t)BATCH * NH * NT * CHUNK * HD];
__device__ float         g_k[(size_t)BATCH * NH * NT * CHUNK * HD];
__device__ float         g_v[(size_t)BATCH * NH * NT * CHUNK * HD];
__device__ float         g_kvsum[(size_t)BATCH * NH * NT * HD * HD];
__device__ float         g_kvpre[(size_t)BATCH * NH * NT * HD * HD];
__device__ float         g_attn[(size_t)NROWS * DIMC];
__device__ __nv_bfloat16 g_xq2[(size_t)NROWS * 16 * TILE_ELEMS / 128];
__device__ float         g_adeq2[NROWS];

// ---------------- helpers ----------------
__device__ __forceinline__ uint32_t smem_u32(const void* smem_ptr) {
    uint32_t addr;
    asm("{ .reg .u64 tmp; cvta.to.shared.u64 tmp, %1; cvt.u32.u64 %0, tmp; }"
        : "=r"(addr) : "l"(smem_ptr));
    return addr;
}

#define MBAR_INIT(addr, cnt) \
    asm volatile("mbarrier.init.shared.b64 [%0], %1;" :: "r"((uint32_t)(addr)), "r"((uint32_t)(cnt)) : "memory")
#define MBAR_ARRIVE(addr) \
    asm volatile("mbarrier.arrive.shared.b64 _, [%0];" :: "r"((uint32_t)(addr)) : "memory")
#define MBAR_EXPECT_TX(addr, bytes) \
    asm volatile("mbarrier.arrive.expect_tx.shared.b64 _, [%0], %1;" :: "r"((uint32_t)(addr)), "r"((uint32_t)(bytes)) : "memory")
#define MBAR_WAIT_PARITY(mbar, parity) do { \
    uint32_t _mbar = (uint32_t)(mbar); \
    uint32_t _parity = (uint32_t)(parity); \
    uint32_t _done; \
    asm volatile( \
        "{\n\t.reg .pred p;\n\t" \
        "mbarrier.try_wait.parity.shared.b64 p, [%1], %2;\n\t" \
        "selp.b32 %0, 1, 0, p;\n\t}" \
        : "=r"(_done) : "r"(_mbar), "r"(_parity) : "memory"); \
    if (!_done) { \
        asm volatile( \
            "{\n\t.reg .pred P1;\n\t" \
            "WAIT_LOOP_%=:\n\t" \
            "mbarrier.try_wait.parity.shared.b64 P1, [%0], %1;\n\t" \
            "@P1 bra.uni WAIT_DONE_%=;\n\t" \
            "bra.uni WAIT_LOOP_%=;\n\t" \
            "WAIT_DONE_%=:\n\t}" \
            :: "r"(_mbar), "r"(_parity) : "memory"); \
    } \
} while(0)
#define BULK_G2S(dst, src, bytes, mbar) \
    asm volatile("cp.async.bulk.shared::cta.global.mbarrier::complete_tx::bytes [%0], [%1], %2, [%3];" \
        :: "r"((uint32_t)(dst)), "l"(src), "r"((uint32_t)(bytes)), "r"((uint32_t)(mbar)) : "memory")

__device__ __forceinline__ float fexp(float x) {
    x = fmaxf(x, -80.0f);
    float y = x * 1.4426950408889634f;
    float n = rintf(y);
    float g = fmaf(-n, 0.6931471805599453f, x);
    float p = 1.9841270e-4f;
    p = fmaf(p, g, 1.3888889e-3f);
    p = fmaf(p, g, 8.3333333e-3f);
    p = fmaf(p, g, 4.1666667e-2f);
    p = fmaf(p, g, 1.6666667e-1f);
    p = fmaf(p, g, 5.0e-1f);
    p = fmaf(p, g, 1.0f);
    p = fmaf(p, g, 1.0f);
    float s = __int_as_float(((int)n + 127) << 23);
    return p * s;
}
__device__ __forceinline__ void split2(float v, __nv_bfloat16& hi, __nv_bfloat16& lo) {
    hi = __float2bfloat16(v);
    lo = __float2bfloat16(v - __bfloat162float(hi));
}
__device__ __forceinline__ void split4(float4 v,
    __nv_bfloat162& h01, __nv_bfloat162& l01,
    __nv_bfloat162& h23, __nv_bfloat162& l23) {
    h01.x = __float2bfloat16(v.x); l01.x = __float2bfloat16(v.x - __bfloat162float(h01.x));
    h01.y = __float2bfloat16(v.y); l01.y = __float2bfloat16(v.y - __bfloat162float(h01.y));
    h23.x = __float2bfloat16(v.z); l23.x = __float2bfloat16(v.z - __bfloat162float(h23.x));
    h23.y = __float2bfloat16(v.w); l23.y = __float2bfloat16(v.w - __bfloat162float(h23.y));
}
__device__ __forceinline__ size_t tile_idx(int row, int col) {
    return (((size_t)(row >> 7) * 16 + (col >> 6)) * 128 + (row & 127)) * TPAD + (col & 63);
}

// ---------------- weight quant ----------------
__global__ void absmean_partial(const float* __restrict__ w, int n) {
    __shared__ float red[256];
    int tid = threadIdx.x;
    float s = 0.f;
    for (int i = blockIdx.x * 256 + tid; i < n; i += 65536) s += fabsf(w[i]);
    red[tid] = s; __syncthreads();
    for (int st = 128; st > 0; st >>= 1) { if (tid < st) red[tid] += red[tid + st]; __syncthreads(); }
    if (tid == 0) g_part[blockIdx.x] = red[0];
}

__global__ void __launch_bounds__(256) quant_weight_fused(const float* __restrict__ w,
                                                          __nv_bfloat16* __restrict__ wq,
                                                          int n, int slot) {
    __shared__ float red[256];
    int tid = threadIdx.x;
    red[tid] = g_part[tid]; __syncthreads();
    for (int st = 128; st > 0; st >>= 1) { if (tid < st) red[tid] += red[tid + st]; __syncthreads(); }
    float wdeq = fmaxf(red[0] / (float)n, 1e-5f);
    if (blockIdx.x == 0 && tid == 0) g_wdeq[slot] = wdeq;
    float s = 1.0f / wdeq;
    int i4 = (blockIdx.x * 256 + tid) * 4;
    if (i4 >= n) return;
    float4 wv = *(const float4*)(w + i4);
    __nv_bfloat162 p0, p1;
    p0.x = __float2bfloat16(fminf(fmaxf(rintf(wv.x * s), -1.f), 1.f));
    p0.y = __float2bfloat16(fminf(fmaxf(rintf(wv.y * s), -1.f), 1.f));
    p1.x = __float2bfloat16(fminf(fmaxf(rintf(wv.z * s), -1.f), 1.f));
    p1.y = __float2bfloat16(fminf(fmaxf(rintf(wv.w * s), -1.f), 1.f));
    int row = i4 >> 10, col = i4 & 1023;
    __nv_bfloat16* out = wq + tile_idx(row, col);
    *(__nv_bfloat162*)(out)     = p0;
    *(__nv_bfloat162*)(out + 2) = p1;
}

// ---------------- activation quant for QKV input ----------------
__global__ void __launch_bounds__(256) act_quant_x(const float* __restrict__ x,
                                                   const float* __restrict__ nw) {
    __shared__ float red[256];
    __shared__ float bc;
    int row = blockIdx.x, tid = threadIdx.x;
    float4 xv = ((const float4*)(x + (size_t)row * DIMC))[tid];
    float4 wv = ((const float4*)nw)[tid];
    float ss = xv.x*xv.x + xv.y*xv.y + xv.z*xv.z + xv.w*xv.w;
    red[tid] = ss; __syncthreads();
    for (int st = 128; st > 0; st >>= 1) { if (tid < st) red[tid] += red[tid + st]; __syncthreads(); }
    if (tid == 0) bc = rsqrtf(red[0] * (1.0f / DIMC) + EPS_BIT);
    __syncthreads();
    float r = bc;
    float n0 = xv.x*r*wv.x, n1 = xv.y*r*wv.y, n2 = xv.z*r*wv.z, n3 = xv.w*r*wv.w;
    float amax = fmaxf(fmaxf(fabsf(n0), fabsf(n1)), fmaxf(fabsf(n2), fabsf(n3)));
    red[tid] = amax; __syncthreads();
    for (int st = 128; st > 0; st >>= 1) { if (tid < st) red[tid] = fmaxf(red[tid], red[tid + st]); __syncthreads(); }
    if (tid == 0) {
        float mx = fmaxf(red[0], 1e-5f);
        bc = 127.0f / mx;
        g_adeq[row] = mx * (1.0f / 127.0f);
    }
    __syncthreads();
    float sc = bc;
    __nv_bfloat162 p0, p1;
    p0.x = __float2bfloat16(fminf(fmaxf(rintf(n0 * sc), -128.f), 127.f));
    p0.y = __float2bfloat16(fminf(fmaxf(rintf(n1 * sc), -128.f), 127.f));
    p1.x = __float2bfloat16(fminf(fmaxf(rintf(n2 * sc), -128.f), 127.f));
    p1.y = __float2bfloat16(fminf(fmaxf(rintf(n3 * sc), -128.f), 127.f));
    __nv_bfloat16* out = g_xq + tile_idx(row, tid * 4);
    *(__nv_bfloat162*)(out)     = p0;
    *(__nv_bfloat162*)(out + 2) = p1;
}

// ---------------- double-norm + act quant for proj input ----------------
__global__ void __launch_bounds__(256) norm2_quant(const float* __restrict__ nw,
                                                   const float* __restrict__ pnw) {
    __shared__ float red[256];
    __shared__ float bc;
    int row = blockIdx.x, tid = threadIdx.x;
    float4 xv = ((const float4*)(g_attn + (size_t)row * DIMC))[tid];
    float4 wv = ((const float4*)nw)[tid];
    float4 pv = ((const float4*)pnw)[tid];
    float ss = xv.x*xv.x + xv.y*xv.y + xv.z*xv.z + xv.w*xv.w;
    red[tid] = ss; __syncthreads();
    for (int st = 128; st > 0; st >>= 1) { if (tid < st) red[tid] += red[tid + st]; __syncthreads(); }
    if (tid == 0) bc = rsqrtf(red[0] * (1.0f / DIMC) + EPS_OUT);
    __syncthreads();
    float r1 = bc;
    float z0 = xv.x*r1*wv.x, z1 = xv.y*r1*wv.y, z2 = xv.z*r1*wv.z, z3 = xv.w*r1*wv.w;
    float ss2 = z0*z0 + z1*z1 + z2*z2 + z3*z3;
    red[tid] = ss2; __syncthreads();
    for (int st = 128; st > 0; st >>= 1) { if (tid < st) red[tid] += red[tid + st]; __syncthreads(); }
    if (tid == 0) bc = rsqrtf(red[0] * (1.0f / DIMC) + EPS_BIT);
    __syncthreads();
    float r2 = bc;
    float n0 = z0*r2*pv.x, n1 = z1*r2*pv.y, n2 = z2*r2*pv.z, n3 = z3*r2*pv.w;
    float amax = fmaxf(fmaxf(fabsf(n0), fabsf(n1)), fmaxf(fabsf(n2), fabsf(n3)));
    red[tid] = amax; __syncthreads();
    for (int st = 128; st > 0; st >>= 1) { if (tid < st) red[tid] = fmaxf(red[tid], red[tid + st]); __syncthreads(); }
    if (tid == 0) {
        float mx = fmaxf(red[0], 1e-5f);
        bc = 127.0f / mx;
        g_adeq2[row] = mx * (1.0f / 127.0f);
    }
    __syncthreads();
    float sc = bc;
    __nv_bfloat162 p0, p1;
    p0.x = __float2bfloat16(fminf(fmaxf(rintf(n0 * sc), -128.f), 127.f));
    p0.y = __float2bfloat16(fminf(fmaxf(rintf(n1 * sc), -128.f), 127.f));
    p1.x = __float2bfloat16(fminf(fmaxf(rintf(n2 * sc), -128.f), 127.f));
    p1.y = __float2bfloat16(fminf(fmaxf(rintf(n3 * sc), -128.f), 127.f));
    __nv_bfloat16* out = g_xq2 + tile_idx(row, tid * 4);
    *(__nv_bfloat162*)(out)     = p0;
    *(__nv_bfloat162*)(out + 2) = p1;
}

// ---------------- bf16 HMMA GEMM: block 128x256, warp tile 64x64 ----------------
// bulk 3-stage ring, producer/consumer mbarriers, NO per-K-tile __syncthreads. (R12 config)
#define GLD TPAD
#define BSTAGE (3 * TILE_BYTES)               // A(1 tile) + B(2 tiles) = 55296
#define MBAR_OFF (3 * BSTAGE)                 // 165888; full[0..2] then empty[0..2]
#define GEMM_SMEM (MBAR_OFF + 128)
template<bool QKV>
__global__ void __launch_bounds__(256) gemm_bf16_t(
    const __nv_bfloat16* __restrict__ A, const __nv_bfloat16* __restrict__ W,
    float* __restrict__ C, int N,
    const float* __restrict__ adeq, int wslot, const float* __restrict__ bias,
    const float* __restrict__ cosb, const float* __restrict__ sinb)
{
    extern __shared__ __align__(16) char gsm[];
    uint32_t sb = smem_u32(gsm);
    uint32_t fullb  = sb + MBAR_OFF;
    uint32_t emptyb = sb + MBAR_OFF + 24;

    int tid = threadIdx.x;
    int wid = tid >> 5, lane = tid & 31;
    int wm = wid >> 2, wn = wid & 3;            // warp tile 64(M) x 64(N)
    int bm = blockIdx.y * 128;
    int bn = blockIdx.x * 256;

    const __nv_bfloat16* Asrc  = A + (size_t)blockIdx.y * 16 * TILE_ELEMS;
    const __nv_bfloat16* Bsrc0 = W + (size_t)(2 * blockIdx.x)     * 16 * TILE_ELEMS;
    const __nv_bfloat16* Bsrc1 = W + (size_t)(2 * blockIdx.x + 1) * 16 * TILE_ELEMS;

    wmma::fragment<wmma::accumulator, 16, 16, 16, float> c[4][4];
    #pragma unroll
    for (int i = 0; i < 4; i++)
        #pragma unroll
        for (int j = 0; j < 4; j++) wmma::fill_fragment(c[i][j], 0.0f);

    if (tid == 0) {
        #pragma unroll
        for (int s = 0; s < 3; s++) {
            MBAR_INIT(fullb  + s * 8, 1);
            MBAR_INIT(emptyb + s * 8, 8);   // one arrive per warp
        }
    }
    __syncthreads();
    if (tid == 0) {
        #pragma unroll
        for (int s = 0; s < 2; s++) {
            MBAR_EXPECT_TX(fullb + s * 8, BSTAGE);
            BULK_G2S(sb + s * BSTAGE,                  Asrc  + s * TILE_ELEMS, TILE_BYTES, fullb + s * 8);
            BULK_G2S(sb + s * BSTAGE + TILE_BYTES,     Bsrc0 + s * TILE_ELEMS, TILE_BYTES, fullb + s * 8);
            BULK_G2S(sb + s * BSTAGE + 2 * TILE_BYTES, Bsrc1 + s * TILE_ELEMS, TILE_BYTES, fullb + s * 8);
        }
    }

    int m0 = wm * 64;
    int bhalf = (wn >> 1);
    int n0 = (wn & 1) * 64;
    for (int kt = 0; kt < 16; kt++) {
        int sRead = kt % 3;
        if (tid == 0 && kt + 2 < 16) {
            int sW = (kt + 2) % 3;
            if (kt >= 1) MBAR_WAIT_PARITY(emptyb + sW * 8, ((kt - 1) / 3) & 1);
            MBAR_EXPECT_TX(fullb + sW * 8, BSTAGE);
            BULK_G2S(sb + sW * BSTAGE,                  Asrc  + (kt + 2) * TILE_ELEMS, TILE_BYTES, fullb + sW * 8);
            BULK_G2S(sb + sW * BSTAGE + TILE_BYTES,     Bsrc0 + (kt + 2) * TILE_ELEMS, TILE_BYTES, fullb + sW * 8);
            BULK_G2S(sb + sW * BSTAGE + 2 * TILE_BYTES, Bsrc1 + (kt + 2) * TILE_ELEMS, TILE_BYTES, fullb + sW * 8);
        }
        MBAR_WAIT_PARITY(fullb + sRead * 8, (kt / 3) & 1);
        const __nv_bfloat16* as = (const __nv_bfloat16*)(gsm + sRead * BSTAGE);
        const __nv_bfloat16* bs = (const __nv_bfloat16*)(gsm + sRead * BSTAGE + TILE_BYTES
                                                         + bhalf * TILE_BYTES);
        #pragma unroll
        for (int sk = 0; sk < 4; sk++) {
            int k0 = sk * 16;
            wmma::fragment<wmma::matrix_a, 16, 16, 16, __nv_bfloat16, wmma::row_major> af[4];
            wmma::fragment<wmma::matrix_b, 16, 16, 16, __nv_bfloat16, wmma::col_major> bf[4];
            #pragma unroll
            for (int i = 0; i < 4; i++)
                wmma::load_matrix_sync(af[i], &as[(m0 + i * 16) * GLD + k0], GLD);
            #pragma unroll
            for (int j = 0; j < 4; j++)
                wmma::load_matrix_sync(bf[j], &bs[(n0 + j * 16) * GLD + k0], GLD);
            #pragma unroll
            for (int i = 0; i < 4; i++)
                #pragma unroll
                for (int j = 0; j < 4; j++)
                    wmma::mma_sync(c[i][j], af[i], bf[j], c[i][j]);
        }
        if (lane == 0) MBAR_ARRIVE(emptyb + sRead * 8);
    }
    __syncthreads();   // all MMAs done; stage smem reusable for C staging

    float wdeq = g_wdeq[wslot];
    float* CsAll = (float*)gsm;
    float* Csw = &CsAll[wid * 320];
    #pragma unroll
    for (int i = 0; i < 4; i++) {
        #pragma unroll
        for (int j = 0; j < 4; j++) {
            __syncwarp();
            wmma::store_matrix_sync(Csw, c[i][j], 20, wmma::mem_row_major);
            __syncwarp();
            int r  = lane >> 1;
            int cc = (lane & 1) * 8;
            int grow = bm + wm * 64 + i * 16 + r;
            int gcol = bn + wn * 64 + j * 16 + cc;
            float sc = adeq[grow] * wdeq;
            float v[8];
            #pragma unroll
            for (int u = 0; u < 8; u++)
                v[u] = Csw[r * 20 + cc + u] * sc + bias[gcol + u];
            if (QKV) {
                int which = gcol >> 10;
                int rem = gcol & 1023;
                int h = rem >> 6, d = rem & 63;
                int b = grow >> 13, n = grow & 8191;
                int t = n >> 7, rr = n & 127;
                if (which < 2) {
                    int i0 = d >> 1;
                    #pragma unroll
                    for (int m = 0; m < 4; m++) {
                        float cth = cosb[n * 32 + i0 + m];
                        float sth = sinb[n * 32 + i0 + m];
                        float e = v[2*m], o = v[2*m+1];
                        v[2*m]   = e * cth - o * sth;
                        v[2*m+1] = o * cth + e * sth;
                    }
                }
                float* dstbase = (which == 0) ? g_q : (which == 1) ? g_k : g_v;
                float* dst = dstbase + (((size_t)b * NH + h) * NT + t) * (CHUNK * HD)
                           + (size_t)rr * 64 + d;
                *(float4*)(dst)     = make_float4(v[0], v[1], v[2], v[3]);
                *(float4*)(dst + 4) = make_float4(v[4], v[5], v[6], v[7]);
            } else {
                float* dst = C + (size_t)grow * N + gcol;
                *(float4*)(dst)     = make_float4(v[0], v[1], v[2], v[3]);
                *(float4*)(dst + 4) = make_float4(v[4], v[5], v[6], v[7]);
            }
        }
    }
}

// ---------------- intra-chunk attention (split-bf16 tensor cores, causal-skip) ----------------
#define QHI_OFF 0
#define QLO_OFF (128*72)
#define KHI_OFF (2*128*72)
#define KLO_OFF (3*128*72)
#define PHI_OFF (4*128*72)
#define PLO_OFF (4*128*72 + 128*136)
#define BF_TOTAL (4*128*72 + 2*128*136)
#define SS_LD 132

__global__ void __launch_bounds__(512) attn_intra() {
    int t = blockIdx.x, h = blockIdx.y, b = blockIdx.z;
    extern __shared__ __align__(16) char smraw[];
    __nv_bfloat16* bfm = (__nv_bfloat16*)smraw;
    float* sS = (float*)(smraw + (size_t)BF_TOTAL * 2);
    float* rowsum = sS + 128 * SS_LD;

    __nv_bfloat16* sQhi = bfm + QHI_OFF;
    __nv_bfloat16* sQlo = bfm + QLO_OFF;
    __nv_bfloat16* sKhi = bfm + KHI_OFF;
    __nv_bfloat16* sKlo = bfm + KLO_OFF;
    __nv_bfloat16* sPhi = bfm + PHI_OFF;
    __nv_bfloat16* sPlo = bfm + PLO_OFF;
    __nv_bfloat16* sVhi = sQhi;
    __nv_bfloat16* sVlo = sQlo;

    size_t base = (((size_t)b * NH + h) * NT + t) * (CHUNK * HD);
    int tid = threadIdx.x;
    int wid = tid >> 5;

    #pragma unroll
    for (int u = 0; u < 4; u++) {
        int i = tid + u * 512;
        int r = i >> 4, c4 = (i & 15) * 4;
        float4 qv = *(const float4*)(g_q + base + (size_t)r * 64 + c4);
        float4 kv = *(const float4*)(g_k + base + (size_t)r * 64 + c4);
        __nv_bfloat162 h01, l01, h23, l23;
        split4(qv, h01, l01, h23, l23);
        *(__nv_bfloat162*)(sQhi + r*72 + c4)     = h01;
        *(__nv_bfloat162*)(sQhi + r*72 + c4 + 2) = h23;
        *(__nv_bfloat162*)(sQlo + r*72 + c4)     = l01;
        *(__nv_bfloat162*)(sQlo + r*72 + c4 + 2) = l23;
        split4(kv, h01, l01, h23, l23);
        *(__nv_bfloat162*)(sKhi + r*72 + c4)     = h01;
        *(__nv_bfloat162*)(sKhi + r*72 + c4 + 2) = h23;
        *(__nv_bfloat162*)(sKlo + r*72 + c4)     = l01;
        *(__nv_bfloat162*)(sKlo + r*72 + c4 + 2) = l23;
    }
    __syncthreads();

    // QK^T: 16 warps, warp tile 16 rows x 64 cols; tiles fully above the diagonal skipped
    {
        int r0 = (wid >> 1) * 16;
        int cbase = (wid & 1) * 64;
        wmma::fragment<wmma::accumulator, 16, 16, 16, float> c[4];
        #pragma unroll
        for (int j = 0; j < 4; j++) wmma::fill_fragment(c[j], 0.0f);
        if (cbase <= r0 + 15) {
            #pragma unroll
            for (int sk = 0; sk < 4; sk++) {
                int k0 = sk * 16;
                wmma::fragment<wmma::matrix_a, 16, 16, 16, __nv_bfloat16, wmma::row_major> ah, al;
                wmma::load_matrix_sync(ah, &sQhi[r0 * 72 + k0], 72);
                wmma::load_matrix_sync(al, &sQlo[r0 * 72 + k0], 72);
                #pragma unroll
                for (int j = 0; j < 4; j++) {
                    int col0 = cbase + j * 16;
                    if (col0 <= r0 + 15) {
                        wmma::fragment<wmma::matrix_b, 16, 16, 16, __nv_bfloat16, wmma::col_major> bh, bl;
                        wmma::load_matrix_sync(bh, &sKhi[col0 * 72 + k0], 72);
                        wmma::load_matrix_sync(bl, &sKlo[col0 * 72 + k0], 72);
                        wmma::mma_sync(c[j], ah, bh, c[j]);
                        wmma::mma_sync(c[j], ah, bl, c[j]);
                        wmma::mma_sync(c[j], al, bh, c[j]);
                    }
                }
            }
            #pragma unroll
            for (int j = 0; j < 4; j++) {
                int col0 = cbase + j * 16;
                if (col0 <= r0 + 15) {
                    #pragma unroll
                    for (int e = 0; e < c[j].num_elements; e++) c[j].x[e] *= SCALE_ATTN;
                    wmma::store_matrix_sync(&sS[r0 * SS_LD + col0], c[j], SS_LD, wmma::mem_row_major);
                }
            }
        }
    }
    __syncthreads();

    // softmax: 4 threads per row; segments entirely beyond (r|15) never read -> skip
    {
        int r = tid >> 2;
        int c0 = (tid & 3) * 32;
        float mx = -3.0e38f;
        for (int c = c0; c < c0 + 32; c++)
            if (c <= r) mx = fmaxf(mx, sS[r * SS_LD + c]);
        mx = fmaxf(mx, __shfl_xor_sync(0xffffffffu, mx, 1));
        mx = fmaxf(mx, __shfl_xor_sync(0xffffffffu, mx, 2));
        float sum = 0.f;
        if (c0 <= (r | 15)) {
            for (int c = c0; c < c0 + 32; c++) {
                float e = (c <= r) ? fexp(sS[r * SS_LD + c] - mx) : 0.f;
                sum += e;
                __nv_bfloat16 hi, lo;
                split2(e, hi, lo);
                sPhi[r * 136 + c] = hi;
                sPlo[r * 136 + c] = lo;
            }
        }
        sum += __shfl_xor_sync(0xffffffffu, sum, 1);
        sum += __shfl_xor_sync(0xffffffffu, sum, 2);
        if ((tid & 3) == 0) rowsum[r] = sum;
    }
    // V load into Q slots
    #pragma unroll
    for (int u = 0; u < 4; u++) {
        int i = tid + u * 512;
        int r = i >> 4, c4 = (i & 15) * 4;
        float4 vv = *(const float4*)(g_v + base + (size_t)r * 64 + c4);
        __nv_bfloat162 h01, l01, h23, l23;
        split4(vv, h01, l01, h23, l23);
        *(__nv_bfloat162*)(sVhi + r*72 + c4)     = h01;
        *(__nv_bfloat162*)(sVhi + r*72 + c4 + 2) = h23;
        *(__nv_bfloat162*)(sVlo + r*72 + c4)     = l01;
        *(__nv_bfloat162*)(sVlo + r*72 + c4 + 2) = l23;
    }
    __syncthreads();

    // S_t = K^T V (64x64): one 16x16 tile per warp (full, not masked)
    {
        int d0 = (wid >> 2) * 16;
        int e0 = (wid & 3) * 16;
        wmma::fragment<wmma::accumulator, 16, 16, 16, float> c;
        wmma::fill_fragment(c, 0.0f);
        #pragma unroll
        for (int sk = 0; sk < 8; sk++) {
            int r0 = sk * 16;
            wmma::fragment<wmma::matrix_a, 16, 16, 16, __nv_bfloat16, wmma::col_major> ah, al;
            wmma::fragment<wmma::matrix_b, 16, 16, 16, __nv_bfloat16, wmma::row_major> bh, bl;
            wmma::load_matrix_sync(ah, &sKhi[r0 * 72 + d0], 72);
            wmma::load_matrix_sync(al, &sKlo[r0 * 72 + d0], 72);
            wmma::load_matrix_sync(bh, &sVhi[r0 * 72 + e0], 72);
            wmma::load_matrix_sync(bl, &sVlo[r0 * 72 + e0], 72);
            wmma::mma_sync(c, ah, bh, c);
            wmma::mma_sync(c, ah, bl, c);
            wmma::mma_sync(c, al, bh, c);
        }
        size_t kb = (((size_t)b * NH + h) * NT + t) * (HD * HD);
        wmma::store_matrix_sync(g_kvsum + kb + (size_t)d0 * 64 + e0, c, 64, wmma::mem_row_major);
    }

    // o_intra = P @ V (128x64): warp tile 16x32; P tiles with k0 > r0+15 are exactly zero -> skip
    {
        int r0 = (wid >> 1) * 16;
        int cbase = (wid & 1) * 32;
        wmma::fragment<wmma::accumulator, 16, 16, 16, float> c[2];
        #pragma unroll
        for (int j = 0; j < 2; j++) wmma::fill_fragment(c[j], 0.0f);
        int skmax = (r0 >> 4) + 1;
        for (int sk = 0; sk < skmax; sk++) {
            int k0 = sk * 16;
            wmma::fragment<wmma::matrix_a, 16, 16, 16, __nv_bfloat16, wmma::row_major> ah, al;
            wmma::load_matrix_sync(ah, &sPhi[r0 * 136 + k0], 136);
            wmma::load_matrix_sync(al, &sPlo[r0 * 136 + k0], 136);
            #pragma unroll
            for (int j = 0; j < 2; j++) {
                int col0 = cbase + j * 16;
                wmma::fragment<wmma::matrix_b, 16, 16, 16, __nv_bfloat16, wmma::row_major> bh, bl;
                wmma::load_matrix_sync(bh, &sVhi[k0 * 72 + col0], 72);
                wmma::load_matrix_sync(bl, &sVlo[k0 * 72 + col0], 72);
                wmma::mma_sync(c[j], ah, bh, c[j]);
                wmma::mma_sync(c[j], ah, bl, c[j]);
                wmma::mma_sync(c[j], al, bh, c[j]);
            }
        }
        __syncthreads();
        #pragma unroll
        for (int j = 0; j < 2; j++)
            wmma::store_matrix_sync(&sS[r0 * SS_LD + cbase + j * 16], c[j], SS_LD, wmma::mem_row_major);
    }
    __syncthreads();

    #pragma unroll
    for (int u = 0; u < 4; u++) {
        int i = tid + u * 512;
        int r = i >> 4, c4 = (i & 15) * 4;
        float inv = 1.0f / rowsum[r];
        float4 o;
        o.x = sS[r * SS_LD + c4 + 0] * inv;
        o.y = sS[r * SS_LD + c4 + 1] * inv;
        o.z = sS[r * SS_LD + c4 + 2] * inv;
        o.w = sS[r * SS_LD + c4 + 3] * inv;
        size_t grow = (size_t)b * SEQ + (size_t)t * CHUNK + r;
        *(float4*)(g_attn + grow * DIMC + h * 64 + c4) = o;
    }
}

// ---------------- exclusive prefix-sum of chunk KV matrices ----------------
__global__ void __launch_bounds__(256) kv_prefix() {
    int blk = blockIdx.x;
    int bh = blk >> 3, s = blk & 7;
    int tid = threadIdx.x;
    size_t base = (size_t)bh * NT * (HD * HD) + s * 512 + tid * 2;
    float2 acc = make_float2(0.f, 0.f);
    for (int t = 0; t < NT; t++) {
        size_t off = base + (size_t)t * (HD * HD);
        float2 v = *(const float2*)(g_kvsum + off);
        *(float2*)(g_kvpre + off) = acc;
        acc.x += v.x; acc.y += v.y;
    }
}

// ---------------- o_inter = q @ kv_prefix ----------------
#define IQHI 0
#define IQLO (128*72)
#define IKHI (2*128*72)
#define IKLO (2*128*72 + 64*72)
#define IBF_TOTAL (2*128*72 + 2*64*72)
__global__ void __launch_bounds__(256) attn_inter() {
    int t = blockIdx.x, h = blockIdx.y, b = blockIdx.z;
    extern __shared__ __align__(16) char smraw2[];
    __nv_bfloat16* bfm = (__nv_bfloat16*)smraw2;
    float* sO = (float*)(smraw2 + (size_t)IBF_TOTAL * 2);

    __nv_bfloat16* sQhi = bfm + IQHI;
    __nv_bfloat16* sQlo = bfm + IQLO;
    __nv_bfloat16* sKhi = bfm + IKHI;
    __nv_bfloat16* sKlo = bfm + IKLO;

    size_t base = (((size_t)b * NH + h) * NT + t) * (CHUNK * HD);
    size_t kb   = (((size_t)b * NH + h) * NT + t) * (HD * HD);
    int tid = threadIdx.x;
    int wid = tid >> 5;

    #pragma unroll
    for (int u = 0; u < 8; u++) {
        int i = tid + u * 256;
        int r = i >> 4, c4 = (i & 15) * 4;
        float4 qv = *(const float4*)(g_q + base + (size_t)r * 64 + c4);
        __nv_bfloat162 h01, l01, h23, l23;
        split4(qv, h01, l01, h23, l23);
        *(__nv_bfloat162*)(sQhi + r*72 + c4)     = h01;
        *(__nv_bfloat162*)(sQhi + r*72 + c4 + 2) = h23;
        *(__nv_bfloat162*)(sQlo + r*72 + c4)     = l01;
        *(__nv_bfloat162*)(sQlo + r*72 + c4 + 2) = l23;
    }
    #pragma unroll
    for (int u = 0; u < 4; u++) {
        int i = tid + u * 256;
        int r = i >> 4, c4 = (i & 15) * 4;
        float4 kv = *(const float4*)(g_kvpre + kb + (size_t)r * 64 + c4);
        __nv_bfloat162 h01, l01, h23, l23;
        split4(kv, h01, l01, h23, l23);
        *(__nv_bfloat162*)(sKhi + r*72 + c4)     = h01;
        *(__nv_bfloat162*)(sKhi + r*72 + c4 + 2) = h23;
        *(__nv_bfloat162*)(sKlo + r*72 + c4)     = l01;
        *(__nv_bfloat162*)(sKlo + r*72 + c4 + 2) = l23;
    }
    __syncthreads();

    {
        int r0 = wid * 16;
        wmma::fragment<wmma::accumulator, 16, 16, 16, float> c[4];
        #pragma unroll
        for (int j = 0; j < 4; j++) wmma::fill_fragment(c[j], 0.0f);
        #pragma unroll
        for (int sk = 0; sk < 4; sk++) {
            int k0 = sk * 16;
            wmma::fragment<wmma::matrix_a, 16, 16, 16, __nv_bfloat16, wmma::row_major> ah, al;
            wmma::load_matrix_sync(ah, &sQhi[r0 * 72 + k0], 72);
            wmma::load_matrix_sync(al, &sQlo[r0 * 72 + k0], 72);
            #pragma unroll
            for (int j = 0; j < 4; j++) {
                int col0 = j * 16;
                wmma::fragment<wmma::matrix_b, 16, 16, 16, __nv_bfloat16, wmma::row_major> bh, bl;
                wmma::load_matrix_sync(bh, &sKhi[k0 * 72 + col0], 72);
                wmma::load_matrix_sync(bl, &sKlo[k0 * 72 + col0], 72);
                wmma::mma_sync(c[j], ah, bh, c[j]);
                wmma::mma_sync(c[j], ah, bl, c[j]);
                wmma::mma_sync(c[j], al, bh, c[j]);
            }
        }
        #pragma unroll
        for (int j = 0; j < 4; j++)
            wmma::store_matrix_sync(&sO[r0 * 68 + j * 16], c[j], 68, wmma::mem_row_major);
    }
    __syncthreads();

    #pragma unroll
    for (int u = 0; u < 8; u++) {
        int i = tid + u * 256;
        int r = i >> 4, c4 = (i & 15) * 4;
        size_t grow = (size_t)b * SEQ + (size_t)t * CHUNK + r;
        float* dst = g_attn + grow * DIMC + h * 64 + c4;
        float4 old = *(float4*)dst;
        old.x += sO[r * 68 + c4 + 0];
        old.y += sO[r * 68 + c4 + 1];
        old.z += sO[r * 68 + c4 + 2];
        old.w += sO[r * 68 + c4 + 3];
        *(float4*)dst = old;
    }
}

// ---------------- launch ----------------
extern "C" void kernel_launch(void* const* d_in, const int* in_sizes, int n_in,
                              void* d_out, int out_size) {
    const float* x       = (const float*)d_in[0];
    const float* cosb    = (const float*)d_in[1];
    const float* sinb    = (const float*)d_in[2];
    const float* qkv_w   = (const float*)d_in[3];
    const float* qkv_b   = (const float*)d_in[4];
    const float* qkv_nw  = (const float*)d_in[5];
    const float* proj_w  = (const float*)d_in[6];
    const float* proj_b  = (const float*)d_in[7];
    const float* proj_nw = (const float*)d_in[8];
    const float* norm_w  = (const float*)d_in[9];
    float* out = (float*)d_out;

    size_t smem_intra = (size_t)BF_TOTAL * 2 + (128 * SS_LD + 128) * sizeof(float);
    size_t smem_inter = (size_t)IBF_TOTAL * 2 + (128 * 68) * sizeof(float);

    static bool attr_done = false;
    if (!attr_done) {
        cudaFuncSetAttribute(attn_intra, cudaFuncAttributeMaxDynamicSharedMemorySize, (int)smem_intra);
        cudaFuncSetAttribute(attn_inter, cudaFuncAttributeMaxDynamicSharedMemorySize, (int)smem_inter);
        cudaFuncSetAttribute(gemm_bf16_t<true>,  cudaFuncAttributeMaxDynamicSharedMemorySize, GEMM_SMEM);
        cudaFuncSetAttribute(gemm_bf16_t<false>, cudaFuncAttributeMaxDynamicSharedMemorySize, GEMM_SMEM);
        attr_done = true;
    }

    __nv_bfloat16 *xq_p, *wqkv_p, *wproj_p, *xq2_p;
    float *adeq_p, *adeq2_p;
    cudaGetSymbolAddress((void**)&xq_p,    g_xq);
    cudaGetSymbolAddress((void**)&wqkv_p,  g_wq_qkv);
    cudaGetSymbolAddress((void**)&wproj_p, g_wq_proj);
    cudaGetSymbolAddress((void**)&xq2_p,   g_xq2);
    cudaGetSymbolAddress((void**)&adeq_p,  g_adeq);
    cudaGetSymbolAddress((void**)&adeq2_p, g_adeq2);

    // Launch order: gemm<QKV> is launch #4 -> ncu capture slot.
    absmean_partial<<<256, 256>>>(qkv_w, QKVN * DIMC);                                    // 1
    quant_weight_fused<<<QKVN * DIMC / 1024, 256>>>(qkv_w, wqkv_p, QKVN * DIMC, 0);       // 2
    act_quant_x<<<NROWS, 256>>>(x, qkv_nw);                                               // 3
    {
        dim3 grid(QKVN / 256, NROWS / 128);
        gemm_bf16_t<true><<<grid, 256, GEMM_SMEM>>>(xq_p, wqkv_p, nullptr, QKVN,
                                                    adeq_p, 0, qkv_b, cosb, sinb);        // 4 <- profiled
    }
    absmean_partial<<<256, 256>>>(proj_w, DIMC * DIMC);                                   // 5
    quant_weight_fused<<<DIMC * DIMC / 1024, 256>>>(proj_w, wproj_p, DIMC * DIMC, 1);     // 6

    {
        dim3 grid(NT, NH, BATCH);
        attn_intra<<<grid, 512, smem_intra>>>();                                          // 7
    }
    kv_prefix<<<256, 256>>>();                                                            // 8
    {
        dim3 grid(NT, NH, BATCH);
        attn_inter<<<grid, 256, smem_inter>>>();                                          // 9
    }

    norm2_quant<<<NROWS, 256>>>(norm_w, proj_nw);                                         // 10
    {
        dim3 grid(DIMC / 256, NROWS / 128);
        gemm_bf16_t<false><<<grid, 256, GEMM_SMEM>>>(xq2_p, wproj_p, out, DIMC,
                                                     adeq2_p, 1, proj_b, cosb, sinb);     // 11
    }
}

// round 16
// speedup vs baseline: 1.9639x; 1.1312x over previous
#include <cuda_runtime.h>
#include <cuda_bf16.h>
#include <mma.h>
#include <cstdint>

using namespace nvcuda;

#define BATCH 2
#define SEQ   8192
#define DIMC  1024
#define NH    16
#define HD    64
#define CHUNK 128
#define NT    64
#define NROWS 16384
#define QKVN  3072
#define SCALE_ATTN 0.125f
#define EPS_BIT 1.1920929e-07f
#define EPS_OUT 1e-06f

// tile-major padded layout: [rowblk][kt 16][row 128][72], only cols 0..63 meaningful
#define TPAD 72
#define TILE_ELEMS (128 * TPAD)          // 9216 elems
#define TILE_BYTES (TILE_ELEMS * 2)      // 18432 bytes

// ---------------- static device scratch ----------------
__device__ __nv_bfloat16 g_xq[(size_t)NROWS * 16 * TILE_ELEMS / 128];
__device__ float         g_adeq[NROWS];
__device__ __nv_bfloat16 g_wq_qkv[(size_t)QKVN * 16 * TILE_ELEMS / 128];
__device__ __nv_bfloat16 g_wq_proj[(size_t)DIMC * 16 * TILE_ELEMS / 128];
__device__ float         g_wdeq[2];
__device__ float         g_part[256];
__device__ float         g_q[(size_t)BATCH * NH * NT * CHUNK * HD];
__device__ float         g_k[(size_t)BATCH * NH * NT * CHUNK * HD];
__device__ float         g_v[(size_t)BATCH * NH * NT * CHUNK * HD];
__device__ float         g_kvsum[(size_t)BATCH * NH * NT * HD * HD];
__device__ float         g_kvpre[(size_t)BATCH * NH * NT * HD * HD];
__device__ float         g_attn[(size_t)NROWS * DIMC];
__device__ __nv_bfloat16 g_xq2[(size_t)NROWS * 16 * TILE_ELEMS / 128];
__device__ float         g_adeq2[NROWS];

// ---------------- helpers ----------------
__device__ __forceinline__ uint32_t smem_u32(const void* smem_ptr) {
    uint32_t addr;
    asm("{ .reg .u64 tmp; cvta.to.shared.u64 tmp, %1; cvt.u32.u64 %0, tmp; }"
        : "=r"(addr) : "l"(smem_ptr));
    return addr;
}

#define MBAR_INIT(addr, cnt) \
    asm volatile("mbarrier.init.shared.b64 [%0], %1;" :: "r"((uint32_t)(addr)), "r"((uint32_t)(cnt)) : "memory")
#define MBAR_ARRIVE(addr) \
    asm volatile("mbarrier.arrive.shared.b64 _, [%0];" :: "r"((uint32_t)(addr)) : "memory")
#define MBAR_EXPECT_TX(addr, bytes) \
    asm volatile("mbarrier.arrive.expect_tx.shared.b64 _, [%0], %1;" :: "r"((uint32_t)(addr)), "r"((uint32_t)(bytes)) : "memory")
#define MBAR_WAIT_PARITY(mbar, parity) do { \
    uint32_t _mbar = (uint32_t)(mbar); \
    uint32_t _parity = (uint32_t)(parity); \
    uint32_t _done; \
    asm volatile( \
        "{\n\t.reg .pred p;\n\t" \
        "mbarrier.try_wait.parity.shared.b64 p, [%1], %2;\n\t" \
        "selp.b32 %0, 1, 0, p;\n\t}" \
        : "=r"(_done) : "r"(_mbar), "r"(_parity) : "memory"); \
    if (!_done) { \
        asm volatile( \
            "{\n\t.reg .pred P1;\n\t" \
            "WAIT_LOOP_%=:\n\t" \
            "mbarrier.try_wait.parity.shared.b64 P1, [%0], %1;\n\t" \
            "@P1 bra.uni WAIT_DONE_%=;\n\t" \
            "bra.uni WAIT_LOOP_%=;\n\t" \
            "WAIT_DONE_%=:\n\t}" \
            :: "r"(_mbar), "r"(_parity) : "memory"); \
    } \
} while(0)
#define BULK_G2S(dst, src, bytes, mbar) \
    asm volatile("cp.async.bulk.shared::cta.global.mbarrier::complete_tx::bytes [%0], [%1], %2, [%3];" \
        :: "r"((uint32_t)(dst)), "l"(src), "r"((uint32_t)(bytes)), "r"((uint32_t)(mbar)) : "memory")

__device__ __forceinline__ void ldm_x4(uint32_t addr, uint32_t* r) {
    asm volatile("ldmatrix.sync.aligned.m8n8.x4.shared.b16 {%0,%1,%2,%3}, [%4];"
        : "=r"(r[0]), "=r"(r[1]), "=r"(r[2]), "=r"(r[3]) : "r"(addr));
}
__device__ __forceinline__ void ldm_x4_t(uint32_t addr, uint32_t* r) {
    asm volatile("ldmatrix.sync.aligned.m8n8.x4.trans.shared.b16 {%0,%1,%2,%3}, [%4];"
        : "=r"(r[0]), "=r"(r[1]), "=r"(r[2]), "=r"(r[3]) : "r"(addr));
}
__device__ __forceinline__ void mma_bf16(float* c, const uint32_t* a, uint32_t b0, uint32_t b1) {
    asm volatile("mma.sync.aligned.m16n8k16.row.col.f32.bf16.bf16.f32 "
        "{%0,%1,%2,%3}, {%4,%5,%6,%7}, {%8,%9}, {%0,%1,%2,%3};"
        : "+f"(c[0]), "+f"(c[1]), "+f"(c[2]), "+f"(c[3])
        : "r"(a[0]), "r"(a[1]), "r"(a[2]), "r"(a[3]), "r"(b0), "r"(b1));
}

__device__ __forceinline__ float fexp(float x) {
    x = fmaxf(x, -80.0f);
    float y = x * 1.4426950408889634f;
    float n = rintf(y);
    float g = fmaf(-n, 0.6931471805599453f, x);
    float p = 1.9841270e-4f;
    p = fmaf(p, g, 1.3888889e-3f);
    p = fmaf(p, g, 8.3333333e-3f);
    p = fmaf(p, g, 4.1666667e-2f);
    p = fmaf(p, g, 1.6666667e-1f);
    p = fmaf(p, g, 5.0e-1f);
    p = fmaf(p, g, 1.0f);
    p = fmaf(p, g, 1.0f);
    float s = __int_as_float(((int)n + 127) << 23);
    return p * s;
}
__device__ __forceinline__ void split4(float4 v,
    __nv_bfloat162& h01, __nv_bfloat162& l01,
    __nv_bfloat162& h23, __nv_bfloat162& l23) {
    h01.x = __float2bfloat16(v.x); l01.x = __float2bfloat16(v.x - __bfloat162float(h01.x));
    h01.y = __float2bfloat16(v.y); l01.y = __float2bfloat16(v.y - __bfloat162float(h01.y));
    h23.x = __float2bfloat16(v.z); l23.x = __float2bfloat16(v.z - __bfloat162float(h23.x));
    h23.y = __float2bfloat16(v.w); l23.y = __float2bfloat16(v.w - __bfloat162float(h23.y));
}
__device__ __forceinline__ void split2(float v, __nv_bfloat16& hi, __nv_bfloat16& lo) {
    hi = __float2bfloat16(v);
    lo = __float2bfloat16(v - __bfloat162float(hi));
}
__device__ __forceinline__ uint32_t packbf2(float x, float y) {
    __nv_bfloat162 p;
    p.x = __float2bfloat16(x);
    p.y = __float2bfloat16(y);
    return *(uint32_t*)&p;
}
__device__ __forceinline__ size_t tile_idx(int row, int col) {
    return (((size_t)(row >> 7) * 16 + (col >> 6)) * 128 + (row & 127)) * TPAD + (col & 63);
}

// ---------------- weight quant ----------------
__global__ void absmean_partial(const float* __restrict__ w, int n) {
    __shared__ float red[256];
    int tid = threadIdx.x;
    float s = 0.f;
    for (int i = blockIdx.x * 256 + tid; i < n; i += 65536) s += fabsf(w[i]);
    red[tid] = s; __syncthreads();
    for (int st = 128; st > 0; st >>= 1) { if (tid < st) red[tid] += red[tid + st]; __syncthreads(); }
    if (tid == 0) g_part[blockIdx.x] = red[0];
}

__global__ void __launch_bounds__(256) quant_weight_fused(const float* __restrict__ w,
                                                          __nv_bfloat16* __restrict__ wq,
                                                          int n, int slot) {
    __shared__ float red[256];
    int tid = threadIdx.x;
    red[tid] = g_part[tid]; __syncthreads();
    for (int st = 128; st > 0; st >>= 1) { if (tid < st) red[tid] += red[tid + st]; __syncthreads(); }
    float wdeq = fmaxf(red[0] / (float)n, 1e-5f);
    if (blockIdx.x == 0 && tid == 0) g_wdeq[slot] = wdeq;
    float s = 1.0f / wdeq;
    int i4 = (blockIdx.x * 256 + tid) * 4;
    if (i4 >= n) return;
    float4 wv = *(const float4*)(w + i4);
    __nv_bfloat162 p0, p1;
    p0.x = __float2bfloat16(fminf(fmaxf(rintf(wv.x * s), -1.f), 1.f));
    p0.y = __float2bfloat16(fminf(fmaxf(rintf(wv.y * s), -1.f), 1.f));
    p1.x = __float2bfloat16(fminf(fmaxf(rintf(wv.z * s), -1.f), 1.f));
    p1.y = __float2bfloat16(fminf(fmaxf(rintf(wv.w * s), -1.f), 1.f));
    int row = i4 >> 10, col = i4 & 1023;
    __nv_bfloat16* out = wq + tile_idx(row, col);
    *(__nv_bfloat162*)(out)     = p0;
    *(__nv_bfloat162*)(out + 2) = p1;
}

// ---------------- activation quant for QKV input ----------------
__global__ void __launch_bounds__(256) act_quant_x(const float* __restrict__ x,
                                                   const float* __restrict__ nw) {
    __shared__ float red[256];
    __shared__ float bc;
    int row = blockIdx.x, tid = threadIdx.x;
    float4 xv = ((const float4*)(x + (size_t)row * DIMC))[tid];
    float4 wv = ((const float4*)nw)[tid];
    float ss = xv.x*xv.x + xv.y*xv.y + xv.z*xv.z + xv.w*xv.w;
    red[tid] = ss; __syncthreads();
    for (int st = 128; st > 0; st >>= 1) { if (tid < st) red[tid] += red[tid + st]; __syncthreads(); }
    if (tid == 0) bc = rsqrtf(red[0] * (1.0f / DIMC) + EPS_BIT);
    __syncthreads();
    float r = bc;
    float n0 = xv.x*r*wv.x, n1 = xv.y*r*wv.y, n2 = xv.z*r*wv.z, n3 = xv.w*r*wv.w;
    float amax = fmaxf(fmaxf(fabsf(n0), fabsf(n1)), fmaxf(fabsf(n2), fabsf(n3)));
    red[tid] = amax; __syncthreads();
    for (int st = 128; st > 0; st >>= 1) { if (tid < st) red[tid] = fmaxf(red[tid], red[tid + st]); __syncthreads(); }
    if (tid == 0) {
        float mx = fmaxf(red[0], 1e-5f);
        bc = 127.0f / mx;
        g_adeq[row] = mx * (1.0f / 127.0f);
    }
    __syncthreads();
    float sc = bc;
    __nv_bfloat162 p0, p1;
    p0.x = __float2bfloat16(fminf(fmaxf(rintf(n0 * sc), -128.f), 127.f));
    p0.y = __float2bfloat16(fminf(fmaxf(rintf(n1 * sc), -128.f), 127.f));
    p1.x = __float2bfloat16(fminf(fmaxf(rintf(n2 * sc), -128.f), 127.f));
    p1.y = __float2bfloat16(fminf(fmaxf(rintf(n3 * sc), -128.f), 127.f));
    __nv_bfloat16* out = g_xq + tile_idx(row, tid * 4);
    *(__nv_bfloat162*)(out)     = p0;
    *(__nv_bfloat162*)(out + 2) = p1;
}

// ---------------- double-norm + act quant for proj input ----------------
__global__ void __launch_bounds__(256) norm2_quant(const float* __restrict__ nw,
                                                   const float* __restrict__ pnw) {
    __shared__ float red[256];
    __shared__ float bc;
    int row = blockIdx.x, tid = threadIdx.x;
    float4 xv = ((const float4*)(g_attn + (size_t)row * DIMC))[tid];
    float4 wv = ((const float4*)nw)[tid];
    float4 pv = ((const float4*)pnw)[tid];
    float ss = xv.x*xv.x + xv.y*xv.y + xv.z*xv.z + xv.w*xv.w;
    red[tid] = ss; __syncthreads();
    for (int st = 128; st > 0; st >>= 1) { if (tid < st) red[tid] += red[tid + st]; __syncthreads(); }
    if (tid == 0) bc = rsqrtf(red[0] * (1.0f / DIMC) + EPS_OUT);
    __syncthreads();
    float r1 = bc;
    float z0 = xv.x*r1*wv.x, z1 = xv.y*r1*wv.y, z2 = xv.z*r1*wv.z, z3 = xv.w*r1*wv.w;
    float ss2 = z0*z0 + z1*z1 + z2*z2 + z3*z3;
    red[tid] = ss2; __syncthreads();
    for (int st = 128; st > 0; st >>= 1) { if (tid < st) red[tid] += red[tid + st]; __syncthreads(); }
    if (tid == 0) bc = rsqrtf(red[0] * (1.0f / DIMC) + EPS_BIT);
    __syncthreads();
    float r2 = bc;
    float n0 = z0*r2*pv.x, n1 = z1*r2*pv.y, n2 = z2*r2*pv.z, n3 = z3*r2*pv.w;
    float amax = fmaxf(fmaxf(fabsf(n0), fabsf(n1)), fmaxf(fabsf(n2), fabsf(n3)));
    red[tid] = amax; __syncthreads();
    for (int st = 128; st > 0; st >>= 1) { if (tid < st) red[tid] = fmaxf(red[tid], red[tid + st]); __syncthreads(); }
    if (tid == 0) {
        float mx = fmaxf(red[0], 1e-5f);
        bc = 127.0f / mx;
        g_adeq2[row] = mx * (1.0f / 127.0f);
    }
    __syncthreads();
    float sc = bc;
    __nv_bfloat162 p0, p1;
    p0.x = __float2bfloat16(fminf(fmaxf(rintf(n0 * sc), -128.f), 127.f));
    p0.y = __float2bfloat16(fminf(fmaxf(rintf(n1 * sc), -128.f), 127.f));
    p1.x = __float2bfloat16(fminf(fmaxf(rintf(n2 * sc), -128.f), 127.f));
    p1.y = __float2bfloat16(fminf(fmaxf(rintf(n3 * sc), -128.f), 127.f));
    __nv_bfloat16* out = g_xq2 + tile_idx(row, tid * 4);
    *(__nv_bfloat162*)(out)     = p0;
    *(__nv_bfloat162*)(out + 2) = p1;
}

// ---------------- bf16 HMMA GEMM: block 128x256, warp tile 64x64 (R12 config) ----------------
#define GLD TPAD
#define BSTAGE (3 * TILE_BYTES)
#define MBAR_OFF (3 * BSTAGE)
#define GEMM_SMEM (MBAR_OFF + 128)
template<bool QKV>
__global__ void __launch_bounds__(256) gemm_bf16_t(
    const __nv_bfloat16* __restrict__ A, const __nv_bfloat16* __restrict__ W,
    float* __restrict__ C, int N,
    const float* __restrict__ adeq, int wslot, const float* __restrict__ bias,
    const float* __restrict__ cosb, const float* __restrict__ sinb)
{
    extern __shared__ __align__(16) char gsm[];
    uint32_t sb = smem_u32(gsm);
    uint32_t fullb  = sb + MBAR_OFF;
    uint32_t emptyb = sb + MBAR_OFF + 24;

    int tid = threadIdx.x;
    int wid = tid >> 5, lane = tid & 31;
    int wm = wid >> 2, wn = wid & 3;
    int bm = blockIdx.y * 128;
    int bn = blockIdx.x * 256;

    const __nv_bfloat16* Asrc  = A + (size_t)blockIdx.y * 16 * TILE_ELEMS;
    const __nv_bfloat16* Bsrc0 = W + (size_t)(2 * blockIdx.x)     * 16 * TILE_ELEMS;
    const __nv_bfloat16* Bsrc1 = W + (size_t)(2 * blockIdx.x + 1) * 16 * TILE_ELEMS;

    wmma::fragment<wmma::accumulator, 16, 16, 16, float> c[4][4];
    #pragma unroll
    for (int i = 0; i < 4; i++)
        #pragma unroll
        for (int j = 0; j < 4; j++) wmma::fill_fragment(c[i][j], 0.0f);

    if (tid == 0) {
        #pragma unroll
        for (int s = 0; s < 3; s++) {
            MBAR_INIT(fullb  + s * 8, 1);
            MBAR_INIT(emptyb + s * 8, 8);
        }
    }
    __syncthreads();
    if (tid == 0) {
        #pragma unroll
        for (int s = 0; s < 2; s++) {
            MBAR_EXPECT_TX(fullb + s * 8, BSTAGE);
            BULK_G2S(sb + s * BSTAGE,                  Asrc  + s * TILE_ELEMS, TILE_BYTES, fullb + s * 8);
            BULK_G2S(sb + s * BSTAGE + TILE_BYTES,     Bsrc0 + s * TILE_ELEMS, TILE_BYTES, fullb + s * 8);
            BULK_G2S(sb + s * BSTAGE + 2 * TILE_BYTES, Bsrc1 + s * TILE_ELEMS, TILE_BYTES, fullb + s * 8);
        }
    }

    int m0 = wm * 64;
    int bhalf = (wn >> 1);
    int n0 = (wn & 1) * 64;
    for (int kt = 0; kt < 16; kt++) {
        int sRead = kt % 3;
        if (tid == 0 && kt + 2 < 16) {
            int sW = (kt + 2) % 3;
            if (kt >= 1) MBAR_WAIT_PARITY(emptyb + sW * 8, ((kt - 1) / 3) & 1);
            MBAR_EXPECT_TX(fullb + sW * 8, BSTAGE);
            BULK_G2S(sb + sW * BSTAGE,                  Asrc  + (kt + 2) * TILE_ELEMS, TILE_BYTES, fullb + sW * 8);
            BULK_G2S(sb + sW * BSTAGE + TILE_BYTES,     Bsrc0 + (kt + 2) * TILE_ELEMS, TILE_BYTES, fullb + sW * 8);
            BULK_G2S(sb + sW * BSTAGE + 2 * TILE_BYTES, Bsrc1 + (kt + 2) * TILE_ELEMS, TILE_BYTES, fullb + sW * 8);
        }
        MBAR_WAIT_PARITY(fullb + sRead * 8, (kt / 3) & 1);
        const __nv_bfloat16* as = (const __nv_bfloat16*)(gsm + sRead * BSTAGE);
        const __nv_bfloat16* bs = (const __nv_bfloat16*)(gsm + sRead * BSTAGE + TILE_BYTES
                                                         + bhalf * TILE_BYTES);
        #pragma unroll
        for (int sk = 0; sk < 4; sk++) {
            int k0 = sk * 16;
            wmma::fragment<wmma::matrix_a, 16, 16, 16, __nv_bfloat16, wmma::row_major> af[4];
            wmma::fragment<wmma::matrix_b, 16, 16, 16, __nv_bfloat16, wmma::col_major> bf[4];
            #pragma unroll
            for (int i = 0; i < 4; i++)
                wmma::load_matrix_sync(af[i], &as[(m0 + i * 16) * GLD + k0], GLD);
            #pragma unroll
            for (int j = 0; j < 4; j++)
                wmma::load_matrix_sync(bf[j], &bs[(n0 + j * 16) * GLD + k0], GLD);
            #pragma unroll
            for (int i = 0; i < 4; i++)
                #pragma unroll
                for (int j = 0; j < 4; j++)
                    wmma::mma_sync(c[i][j], af[i], bf[j], c[i][j]);
        }
        if (lane == 0) MBAR_ARRIVE(emptyb + sRead * 8);
    }
    __syncthreads();

    float wdeq = g_wdeq[wslot];
    float* CsAll = (float*)gsm;
    float* Csw = &CsAll[wid * 320];
    #pragma unroll
    for (int i = 0; i < 4; i++) {
        #pragma unroll
        for (int j = 0; j < 4; j++) {
            __syncwarp();
            wmma::store_matrix_sync(Csw, c[i][j], 20, wmma::mem_row_major);
            __syncwarp();
            int r  = lane >> 1;
            int cc = (lane & 1) * 8;
            int grow = bm + wm * 64 + i * 16 + r;
            int gcol = bn + wn * 64 + j * 16 + cc;
            float sc = adeq[grow] * wdeq;
            float v[8];
            #pragma unroll
            for (int u = 0; u < 8; u++)
                v[u] = Csw[r * 20 + cc + u] * sc + bias[gcol + u];
            if (QKV) {
                int which = gcol >> 10;
                int rem = gcol & 1023;
                int h = rem >> 6, d = rem & 63;
                int b = grow >> 13, n = grow & 8191;
                int t = n >> 7, rr = n & 127;
                if (which < 2) {
                    int i0 = d >> 1;
                    #pragma unroll
                    for (int m = 0; m < 4; m++) {
                        float cth = cosb[n * 32 + i0 + m];
                        float sth = sinb[n * 32 + i0 + m];
                        float e = v[2*m], o = v[2*m+1];
                        v[2*m]   = e * cth - o * sth;
                        v[2*m+1] = o * cth + e * sth;
                    }
                }
                float* dstbase = (which == 0) ? g_q : (which == 1) ? g_k : g_v;
                float* dst = dstbase + (((size_t)b * NH + h) * NT + t) * (CHUNK * HD)
                           + (size_t)rr * 64 + d;
                *(float4*)(dst)     = make_float4(v[0], v[1], v[2], v[3]);
                *(float4*)(dst + 4) = make_float4(v[4], v[5], v[6], v[7]);
            } else {
                float* dst = C + (size_t)grow * N + gcol;
                *(float4*)(dst)     = make_float4(v[0], v[1], v[2], v[3]);
                *(float4*)(dst + 4) = make_float4(v[4], v[5], v[6], v[7]);
            }
        }
    }
}

// ---------------- intra-chunk attention: raw mma, S/P register-resident ----------------
// 256 threads, 8 warps; warp owns 16 rows x 128 cols of S. smem = Q,K,V hi/lo only (72KB).
#define ATT_SMEM (4 * 128 * 72 * 2)
__global__ void __launch_bounds__(256, 2) attn_intra() {
    int t = blockIdx.x, h = blockIdx.y, b = blockIdx.z;
    extern __shared__ __align__(16) char smraw[];
    __nv_bfloat16* sQhi = (__nv_bfloat16*)smraw;
    __nv_bfloat16* sQlo = sQhi + 128 * 72;
    __nv_bfloat16* sKhi = sQhi + 2 * 128 * 72;
    __nv_bfloat16* sKlo = sQhi + 3 * 128 * 72;
    uint32_t qhi = smem_u32(sQhi), qlo = qhi + TILE_BYTES;
    uint32_t khi = qhi + 2 * TILE_BYTES, klo = qhi + 3 * TILE_BYTES;

    size_t base = (((size_t)b * NH + h) * NT + t) * (CHUNK * HD);
    int tid = threadIdx.x;
    int wid = tid >> 5, lane = tid & 31;
    int g = lane >> 2, tq = lane & 3;

    // load Q,K and split hi/lo
    #pragma unroll
    for (int u = 0; u < 8; u++) {
        int i = tid + u * 256;
        int r = i >> 4, c4 = (i & 15) * 4;
        float4 qv = *(const float4*)(g_q + base + (size_t)r * 64 + c4);
        float4 kv = *(const float4*)(g_k + base + (size_t)r * 64 + c4);
        __nv_bfloat162 h01, l01, h23, l23;
        split4(qv, h01, l01, h23, l23);
        *(__nv_bfloat162*)(sQhi + r*72 + c4)     = h01;
        *(__nv_bfloat162*)(sQhi + r*72 + c4 + 2) = h23;
        *(__nv_bfloat162*)(sQlo + r*72 + c4)     = l01;
        *(__nv_bfloat162*)(sQlo + r*72 + c4 + 2) = l23;
        split4(kv, h01, l01, h23, l23);
        *(__nv_bfloat162*)(sKhi + r*72 + c4)     = h01;
        *(__nv_bfloat162*)(sKhi + r*72 + c4 + 2) = h23;
        *(__nv_bfloat162*)(sKlo + r*72 + c4)     = l01;
        *(__nv_bfloat162*)(sKlo + r*72 + c4 + 2) = l23;
    }
    __syncthreads();

    int r0 = wid * 16;
    int row_lo = r0 + g, row_hi = r0 + g + 8;
    float sacc[16][4];
    #pragma unroll
    for (int nt = 0; nt < 16; nt++)
        #pragma unroll
        for (int e = 0; e < 4; e++) sacc[nt][e] = 0.0f;

    // ---- QK^T (causal: tile col0 <= r0+15 -> nt2 <= wid) ----
    uint32_t a_off = (uint32_t)(r0 + (lane & 15)) * 144 + (lane >> 4) * 16;
    uint32_t b_off = (uint32_t)(((lane >> 4) & 1) * 8 + (lane & 7)) * 144 + ((lane >> 3) & 1) * 16;
    #pragma unroll
    for (int kc = 0; kc < 4; kc++) {
        uint32_t kb2 = kc * 32;                 // k0*2 bytes
        uint32_t ah[4], al[4];
        ldm_x4(qhi + a_off + kb2, ah);
        ldm_x4(qlo + a_off + kb2, al);
        #pragma unroll
        for (int nt2 = 0; nt2 < 8; nt2++) {
            if (nt2 <= wid) {
                uint32_t baddr = (uint32_t)(nt2 * 16) * 144 + b_off + kb2;
                uint32_t bh[4], bl[4];
                ldm_x4(khi + baddr, bh);
                ldm_x4(klo + baddr, bl);
                mma_bf16(sacc[2*nt2],   ah, bh[0], bh[1]);
                mma_bf16(sacc[2*nt2],   ah, bl[0], bl[1]);
                mma_bf16(sacc[2*nt2],   al, bh[0], bh[1]);
                mma_bf16(sacc[2*nt2+1], ah, bh[2], bh[3]);
                mma_bf16(sacc[2*nt2+1], ah, bl[2], bl[3]);
                mma_bf16(sacc[2*nt2+1], al, bh[2], bh[3]);
            }
        }
    }

    // ---- softmax in registers ----
    float mx_lo = -3.0e38f, mx_hi = -3.0e38f;
    #pragma unroll
    for (int nt = 0; nt < 16; nt++) {
        if ((nt >> 1) <= wid) {
            int c0 = nt * 8 + 2 * tq;
            if (c0     <= row_lo) mx_lo = fmaxf(mx_lo, sacc[nt][0] * SCALE_ATTN);
            if (c0 + 1 <= row_lo) mx_lo = fmaxf(mx_lo, sacc[nt][1] * SCALE_ATTN);
            if (c0     <= row_hi) mx_hi = fmaxf(mx_hi, sacc[nt][2] * SCALE_ATTN);
            if (c0 + 1 <= row_hi) mx_hi = fmaxf(mx_hi, sacc[nt][3] * SCALE_ATTN);
        }
    }
    mx_lo = fmaxf(mx_lo, __shfl_xor_sync(0xffffffffu, mx_lo, 1));
    mx_lo = fmaxf(mx_lo, __shfl_xor_sync(0xffffffffu, mx_lo, 2));
    mx_hi = fmaxf(mx_hi, __shfl_xor_sync(0xffffffffu, mx_hi, 1));
    mx_hi = fmaxf(mx_hi, __shfl_xor_sync(0xffffffffu, mx_hi, 2));

    float sum_lo = 0.f, sum_hi = 0.f;
    #pragma unroll
    for (int nt = 0; nt < 16; nt++) {
        if ((nt >> 1) <= wid) {
            int c0 = nt * 8 + 2 * tq;
            float e0 = (c0     <= row_lo) ? fexp(sacc[nt][0] * SCALE_ATTN - mx_lo) : 0.f;
            float e1 = (c0 + 1 <= row_lo) ? fexp(sacc[nt][1] * SCALE_ATTN - mx_lo) : 0.f;
            float e2 = (c0     <= row_hi) ? fexp(sacc[nt][2] * SCALE_ATTN - mx_hi) : 0.f;
            float e3 = (c0 + 1 <= row_hi) ? fexp(sacc[nt][3] * SCALE_ATTN - mx_hi) : 0.f;
            sum_lo += e0 + e1;
            sum_hi += e2 + e3;
            // repack P in place: [0]=hi(e0,e1) [1]=lo(e0,e1) [2]=hi(e2,e3) [3]=lo(e2,e3)
            __nv_bfloat16 h0, l0, h1, l1;
            split2(e0, h0, l0); split2(e1, h1, l1);
            __nv_bfloat162 ph; ph.x = h0; ph.y = h1;
            __nv_bfloat162 pl; pl.x = l0; pl.y = l1;
            sacc[nt][0] = __uint_as_float(*(uint32_t*)&ph);
            sacc[nt][1] = __uint_as_float(*(uint32_t*)&pl);
            split2(e2, h0, l0); split2(e3, h1, l1);
            ph.x = h0; ph.y = h1; pl.x = l0; pl.y = l1;
            sacc[nt][2] = __uint_as_float(*(uint32_t*)&ph);
            sacc[nt][3] = __uint_as_float(*(uint32_t*)&pl);
        }
    }
    sum_lo += __shfl_xor_sync(0xffffffffu, sum_lo, 1);
    sum_lo += __shfl_xor_sync(0xffffffffu, sum_lo, 2);
    sum_hi += __shfl_xor_sync(0xffffffffu, sum_hi, 1);
    sum_hi += __shfl_xor_sync(0xffffffffu, sum_hi, 2);

    __syncthreads();   // all warps done reading Q (ldmatrix) -> safe to overwrite with V
    // load V into Q slot
    #pragma unroll
    for (int u = 0; u < 8; u++) {
        int i = tid + u * 256;
        int r = i >> 4, c4 = (i & 15) * 4;
        float4 vv = *(const float4*)(g_v + base + (size_t)r * 64 + c4);
        __nv_bfloat162 h01, l01, h23, l23;
        split4(vv, h01, l01, h23, l23);
        *(__nv_bfloat162*)(sQhi + r*72 + c4)     = h01;
        *(__nv_bfloat162*)(sQhi + r*72 + c4 + 2) = h23;
        *(__nv_bfloat162*)(sQlo + r*72 + c4)     = l01;
        *(__nv_bfloat162*)(sQlo + r*72 + c4 + 2) = l23;
    }
    __syncthreads();
    uint32_t vhi = qhi, vlo = qlo;

    // ---- o = P @ V (k chunks <= wid) ----
    uint32_t vt_off = (uint32_t)(((lane >> 3) & 1) * 8 + (lane & 7)) * 144 + ((lane >> 4) & 1) * 16;
    float o[8][4];
    #pragma unroll
    for (int j = 0; j < 8; j++)
        #pragma unroll
        for (int e = 0; e < 4; e++) o[j][e] = 0.f;
    #pragma unroll
    for (int q = 0; q < 8; q++) {
        if (q <= wid) {
            uint32_t pa_h[4] = { __float_as_uint(sacc[2*q][0]), __float_as_uint(sacc[2*q][2]),
                                 __float_as_uint(sacc[2*q+1][0]), __float_as_uint(sacc[2*q+1][2]) };
            uint32_t pa_l[4] = { __float_as_uint(sacc[2*q][1]), __float_as_uint(sacc[2*q][3]),
                                 __float_as_uint(sacc[2*q+1][1]), __float_as_uint(sacc[2*q+1][3]) };
            uint32_t kbytes = (uint32_t)(q * 16) * 144;
            #pragma unroll
            for (int nt2 = 0; nt2 < 4; nt2++) {
                uint32_t vaddr = kbytes + vt_off + (nt2 * 16) * 2;
                uint32_t vh[4], vl[4];
                ldm_x4_t(vhi + vaddr, vh);
                ldm_x4_t(vlo + vaddr, vl);
                mma_bf16(o[2*nt2],   pa_h, vh[0], vh[1]);
                mma_bf16(o[2*nt2],   pa_h, vl[0], vl[1]);
                mma_bf16(o[2*nt2],   pa_l, vh[0], vh[1]);
                mma_bf16(o[2*nt2+1], pa_h, vh[2], vh[3]);
                mma_bf16(o[2*nt2+1], pa_h, vl[2], vl[3]);
                mma_bf16(o[2*nt2+1], pa_l, vh[2], vh[3]);
            }
        }
    }
    {
        float inv_lo = 1.0f / sum_lo, inv_hi = 1.0f / sum_hi;
        float* dlo = g_attn + ((size_t)b * SEQ + (size_t)t * CHUNK + row_lo) * DIMC + h * 64;
        float* dhi = g_attn + ((size_t)b * SEQ + (size_t)t * CHUNK + row_hi) * DIMC + h * 64;
        #pragma unroll
        for (int j = 0; j < 8; j++) {
            int col = j * 8 + 2 * tq;
            *(float2*)(dlo + col) = make_float2(o[j][0] * inv_lo, o[j][1] * inv_lo);
            *(float2*)(dhi + col) = make_float2(o[j][2] * inv_hi, o[j][3] * inv_hi);
        }
    }

    // ---- S_t = K^T V (64x64): warp tile 16(d) x 32(e) ----
    {
        int d0 = (wid >> 1) * 16;
        int e0 = (wid & 1) * 32;
        float kv[4][4];
        #pragma unroll
        for (int j = 0; j < 4; j++)
            #pragma unroll
            for (int e = 0; e < 4; e++) kv[j][e] = 0.f;
        uint32_t kt_off = (uint32_t)(((lane >> 4) & 1) * 8 + (lane & 7)) * 144 + ((lane >> 3) & 1) * 16;
        #pragma unroll
        for (int kc = 0; kc < 8; kc++) {
            uint32_t kbytes = (uint32_t)(kc * 16) * 144;
            uint32_t ah[4], al[4];
            ldm_x4_t(khi + kbytes + kt_off + d0 * 2, ah);
            ldm_x4_t(klo + kbytes + kt_off + d0 * 2, al);
            #pragma unroll
            for (int nt2 = 0; nt2 < 2; nt2++) {
                uint32_t vaddr = kbytes + vt_off + (e0 + nt2 * 16) * 2;
                uint32_t vh[4], vl[4];
                ldm_x4_t(vhi + vaddr, vh);
                ldm_x4_t(vlo + vaddr, vl);
                mma_bf16(kv[2*nt2],   ah, vh[0], vh[1]);
                mma_bf16(kv[2*nt2],   ah, vl[0], vl[1]);
                mma_bf16(kv[2*nt2],   al, vh[0], vh[1]);
                mma_bf16(kv[2*nt2+1], ah, vh[2], vh[3]);
                mma_bf16(kv[2*nt2+1], ah, vl[2], vl[3]);
                mma_bf16(kv[2*nt2+1], al, vh[2], vh[3]);
            }
        }
        size_t kb = (((size_t)b * NH + h) * NT + t) * (HD * HD);
        float* klo_p = g_kvsum + kb + (size_t)(d0 + g) * 64 + e0;
        float* khi_p = g_kvsum + kb + (size_t)(d0 + g + 8) * 64 + e0;
        #pragma unroll
        for (int j = 0; j < 4; j++) {
            int col = j * 8 + 2 * tq;
            *(float2*)(klo_p + col) = make_float2(kv[j][0], kv[j][1]);
            *(float2*)(khi_p + col) = make_float2(kv[j][2], kv[j][3]);
        }
    }
}

// ---------------- exclusive prefix-sum of chunk KV matrices ----------------
__global__ void __launch_bounds__(256) kv_prefix() {
    int blk = blockIdx.x;
    int bh = blk >> 3, s = blk & 7;
    int tid = threadIdx.x;
    size_t base = (size_t)bh * NT * (HD * HD) + s * 512 + tid * 2;
    float2 acc = make_float2(0.f, 0.f);
    for (int t = 0; t < NT; t++) {
        size_t off = base + (size_t)t * (HD * HD);
        float2 v = *(const float2*)(g_kvsum + off);
        *(float2*)(g_kvpre + off) = acc;
        acc.x += v.x; acc.y += v.y;
    }
}

// ---------------- o_inter = q @ kv_prefix ----------------
#define IQHI 0
#define IQLO (128*72)
#define IKHI (2*128*72)
#define IKLO (2*128*72 + 64*72)
#define IBF_TOTAL (2*128*72 + 2*64*72)
__global__ void __launch_bounds__(256) attn_inter() {
    int t = blockIdx.x, h = blockIdx.y, b = blockIdx.z;
    extern __shared__ __align__(16) char smraw2[];
    __nv_bfloat16* bfm = (__nv_bfloat16*)smraw2;
    float* sO = (float*)(smraw2 + (size_t)IBF_TOTAL * 2);

    __nv_bfloat16* sQhi = bfm + IQHI;
    __nv_bfloat16* sQlo = bfm + IQLO;
    __nv_bfloat16* sKhi = bfm + IKHI;
    __nv_bfloat16* sKlo = bfm + IKLO;

    size_t base = (((size_t)b * NH + h) * NT + t) * (CHUNK * HD);
    size_t kb   = (((size_t)b * NH + h) * NT + t) * (HD * HD);
    int tid = threadIdx.x;
    int wid = tid >> 5;

    #pragma unroll
    for (int u = 0; u < 8; u++) {
        int i = tid + u * 256;
        int r = i >> 4, c4 = (i & 15) * 4;
        float4 qv = *(const float4*)(g_q + base + (size_t)r * 64 + c4);
        __nv_bfloat162 h01, l01, h23, l23;
        split4(qv, h01, l01, h23, l23);
        *(__nv_bfloat162*)(sQhi + r*72 + c4)     = h01;
        *(__nv_bfloat162*)(sQhi + r*72 + c4 + 2) = h23;
        *(__nv_bfloat162*)(sQlo + r*72 + c4)     = l01;
        *(__nv_bfloat162*)(sQlo + r*72 + c4 + 2) = l23;
    }
    #pragma unroll
    for (int u = 0; u < 4; u++) {
        int i = tid + u * 256;
        int r = i >> 4, c4 = (i & 15) * 4;
        float4 kv = *(const float4*)(g_kvpre + kb + (size_t)r * 64 + c4);
        __nv_bfloat162 h01, l01, h23, l23;
        split4(kv, h01, l01, h23, l23);
        *(__nv_bfloat162*)(sKhi + r*72 + c4)     = h01;
        *(__nv_bfloat162*)(sKhi + r*72 + c4 + 2) = h23;
        *(__nv_bfloat162*)(sKlo + r*72 + c4)     = l01;
        *(__nv_bfloat162*)(sKlo + r*72 + c4 + 2) = l23;
    }
    __syncthreads();

    {
        int r0 = wid * 16;
        wmma::fragment<wmma::accumulator, 16, 16, 16, float> c[4];
        #pragma unroll
        for (int j = 0; j < 4; j++) wmma::fill_fragment(c[j], 0.0f);
        #pragma unroll
        for (int sk = 0; sk < 4; sk++) {
            int k0 = sk * 16;
            wmma::fragment<wmma::matrix_a, 16, 16, 16, __nv_bfloat16, wmma::row_major> ah, al;
            wmma::load_matrix_sync(ah, &sQhi[r0 * 72 + k0], 72);
            wmma::load_matrix_sync(al, &sQlo[r0 * 72 + k0], 72);
            #pragma unroll
            for (int j = 0; j < 4; j++) {
                int col0 = j * 16;
                wmma::fragment<wmma::matrix_b, 16, 16, 16, __nv_bfloat16, wmma::row_major> bh, bl;
                wmma::load_matrix_sync(bh, &sKhi[k0 * 72 + col0], 72);
                wmma::load_matrix_sync(bl, &sKlo[k0 * 72 + col0], 72);
                wmma::mma_sync(c[j], ah, bh, c[j]);
                wmma::mma_sync(c[j], ah, bl, c[j]);
                wmma::mma_sync(c[j], al, bh, c[j]);
            }
        }
        #pragma unroll
        for (int j = 0; j < 4; j++)
            wmma::store_matrix_sync(&sO[r0 * 68 + j * 16], c[j], 68, wmma::mem_row_major);
    }
    __syncthreads();

    #pragma unroll
    for (int u = 0; u < 8; u++) {
        int i = tid + u * 256;
        int r = i >> 4, c4 = (i & 15) * 4;
        size_t grow = (size_t)b * SEQ + (size_t)t * CHUNK + r;
        float* dst = g_attn + grow * DIMC + h * 64 + c4;
        float4 old = *(float4*)dst;
        old.x += sO[r * 68 + c4 + 0];
        old.y += sO[r * 68 + c4 + 1];
        old.z += sO[r * 68 + c4 + 2];
        old.w += sO[r * 68 + c4 + 3];
        *(float4*)dst = old;
    }
}

// ---------------- launch ----------------
extern "C" void kernel_launch(void* const* d_in, const int* in_sizes, int n_in,
                              void* d_out, int out_size) {
    const float* x       = (const float*)d_in[0];
    const float* cosb    = (const float*)d_in[1];
    const float* sinb    = (const float*)d_in[2];
    const float* qkv_w   = (const float*)d_in[3];
    const float* qkv_b   = (const float*)d_in[4];
    const float* qkv_nw  = (const float*)d_in[5];
    const float* proj_w  = (const float*)d_in[6];
    const float* proj_b  = (const float*)d_in[7];
    const float* proj_nw = (const float*)d_in[8];
    const float* norm_w  = (const float*)d_in[9];
    float* out = (float*)d_out;

    size_t smem_inter = (size_t)IBF_TOTAL * 2 + (128 * 68) * sizeof(float);

    static bool attr_done = false;
    if (!attr_done) {
        cudaFuncSetAttribute(attn_intra, cudaFuncAttributeMaxDynamicSharedMemorySize, ATT_SMEM);
        cudaFuncSetAttribute(attn_inter, cudaFuncAttributeMaxDynamicSharedMemorySize, (int)smem_inter);
        cudaFuncSetAttribute(gemm_bf16_t<true>,  cudaFuncAttributeMaxDynamicSharedMemorySize, GEMM_SMEM);
        cudaFuncSetAttribute(gemm_bf16_t<false>, cudaFuncAttributeMaxDynamicSharedMemorySize, GEMM_SMEM);
        attr_done = true;
    }

    __nv_bfloat16 *xq_p, *wqkv_p, *wproj_p, *xq2_p;
    float *adeq_p, *adeq2_p;
    cudaGetSymbolAddress((void**)&xq_p,    g_xq);
    cudaGetSymbolAddress((void**)&wqkv_p,  g_wq_qkv);
    cudaGetSymbolAddress((void**)&wproj_p, g_wq_proj);
    cudaGetSymbolAddress((void**)&xq2_p,   g_xq2);
    cudaGetSymbolAddress((void**)&adeq_p,  g_adeq);
    cudaGetSymbolAddress((void**)&adeq2_p, g_adeq2);

    // Launch order: gemm<QKV> is launch #4 -> ncu capture slot.
    absmean_partial<<<256, 256>>>(qkv_w, QKVN * DIMC);                                    // 1
    quant_weight_fused<<<QKVN * DIMC / 1024, 256>>>(qkv_w, wqkv_p, QKVN * DIMC, 0);       // 2
    act_quant_x<<<NROWS, 256>>>(x, qkv_nw);                                               // 3
    {
        dim3 grid(QKVN / 256, NROWS / 128);
        gemm_bf16_t<true><<<grid, 256, GEMM_SMEM>>>(xq_p, wqkv_p, nullptr, QKVN,
                                                    adeq_p, 0, qkv_b, cosb, sinb);        // 4 <- profiled
    }
    absmean_partial<<<256, 256>>>(proj_w, DIMC * DIMC);                                   // 5
    quant_weight_fused<<<DIMC * DIMC / 1024, 256>>>(proj_w, wproj_p, DIMC * DIMC, 1);     // 6

    {
        dim3 grid(NT, NH, BATCH);
        attn_intra<<<grid, 256, ATT_SMEM>>>();                                            // 7
    }
    kv_prefix<<<256, 256>>>();                                                            // 8
    {
        dim3 grid(NT, NH, BATCH);
        attn_inter<<<grid, 256, smem_inter>>>();                                          // 9
    }

    norm2_quant<<<NROWS, 256>>>(norm_w, proj_nw);                                         // 10
    {
        dim3 grid(DIMC / 256, NROWS / 128);
        gemm_bf16_t<false><<<grid, 256, GEMM_SMEM>>>(xq2_p, wproj_p, out, DIMC,
                                                     adeq2_p, 1, proj_b, cosb, sinb);     // 11
    }
}

// round 17
// speedup vs baseline: 2.2751x; 1.1585x over previous
#include <cuda_runtime.h>
#include <cuda_bf16.h>
#include <mma.h>
#include <cstdint>

using namespace nvcuda;

#define BATCH 2
#define SEQ   8192
#define DIMC  1024
#define NH    16
#define HD    64
#define CHUNK 128
#define NT    64
#define NROWS 16384
#define QKVN  3072
#define SCALE_ATTN 0.125f
#define EPS_BIT 1.1920929e-07f
#define EPS_OUT 1e-06f

// tile-major padded layout: [rowblk][kt 16][row 128][72], only cols 0..63 meaningful
#define TPAD 72
#define TILE_ELEMS (128 * TPAD)          // 9216 elems
#define TILE_BYTES (TILE_ELEMS * 2)      // 18432 bytes

// ---------------- static device scratch ----------------
__device__ __nv_bfloat16 g_xq[(size_t)NROWS * 16 * TILE_ELEMS / 128];
__device__ float         g_adeq[NROWS];
__device__ __nv_bfloat16 g_wq_qkv[(size_t)QKVN * 16 * TILE_ELEMS / 128];
__device__ __nv_bfloat16 g_wq_proj[(size_t)DIMC * 16 * TILE_ELEMS / 128];
__device__ float         g_wdeq[2];
__device__ float         g_part[256];
__device__ float         g_q[(size_t)BATCH * NH * NT * CHUNK * HD];
__device__ float         g_k[(size_t)BATCH * NH * NT * CHUNK * HD];
__device__ float         g_v[(size_t)BATCH * NH * NT * CHUNK * HD];
__device__ float         g_kvsum[(size_t)BATCH * NH * NT * HD * HD];
__device__ float         g_kvpre[(size_t)BATCH * NH * NT * HD * HD];
__device__ float         g_attn[(size_t)NROWS * DIMC];
__device__ __nv_bfloat16 g_xq2[(size_t)NROWS * 16 * TILE_ELEMS / 128];
__device__ float         g_adeq2[NROWS];

// ---------------- helpers ----------------
__device__ __forceinline__ uint32_t smem_u32(const void* smem_ptr) {
    uint32_t addr;
    asm("{ .reg .u64 tmp; cvta.to.shared.u64 tmp, %1; cvt.u32.u64 %0, tmp; }"
        : "=r"(addr) : "l"(smem_ptr));
    return addr;
}

#define MBAR_INIT(addr, cnt) \
    asm volatile("mbarrier.init.shared.b64 [%0], %1;" :: "r"((uint32_t)(addr)), "r"((uint32_t)(cnt)) : "memory")
#define MBAR_ARRIVE(addr) \
    asm volatile("mbarrier.arrive.shared.b64 _, [%0];" :: "r"((uint32_t)(addr)) : "memory")
#define MBAR_EXPECT_TX(addr, bytes) \
    asm volatile("mbarrier.arrive.expect_tx.shared.b64 _, [%0], %1;" :: "r"((uint32_t)(addr)), "r"((uint32_t)(bytes)) : "memory")
#define MBAR_WAIT_PARITY(mbar, parity) do { \
    uint32_t _mbar = (uint32_t)(mbar); \
    uint32_t _parity = (uint32_t)(parity); \
    uint32_t _done; \
    asm volatile( \
        "{\n\t.reg .pred p;\n\t" \
        "mbarrier.try_wait.parity.shared.b64 p, [%1], %2;\n\t" \
        "selp.b32 %0, 1, 0, p;\n\t}" \
        : "=r"(_done) : "r"(_mbar), "r"(_parity) : "memory"); \
    if (!_done) { \
        asm volatile( \
            "{\n\t.reg .pred P1;\n\t" \
            "WAIT_LOOP_%=:\n\t" \
            "mbarrier.try_wait.parity.shared.b64 P1, [%0], %1;\n\t" \
            "@P1 bra.uni WAIT_DONE_%=;\n\t" \
            "bra.uni WAIT_LOOP_%=;\n\t" \
            "WAIT_DONE_%=:\n\t}" \
            :: "r"(_mbar), "r"(_parity) : "memory"); \
    } \
} while(0)
#define BULK_G2S(dst, src, bytes, mbar) \
    asm volatile("cp.async.bulk.shared::cta.global.mbarrier::complete_tx::bytes [%0], [%1], %2, [%3];" \
        :: "r"((uint32_t)(dst)), "l"(src), "r"((uint32_t)(bytes)), "r"((uint32_t)(mbar)) : "memory")

__device__ __forceinline__ void ldm_x4(uint32_t addr, uint32_t* r) {
    asm volatile("ldmatrix.sync.aligned.m8n8.x4.shared.b16 {%0,%1,%2,%3}, [%4];"
        : "=r"(r[0]), "=r"(r[1]), "=r"(r[2]), "=r"(r[3]) : "r"(addr));
}
__device__ __forceinline__ void ldm_x4_t(uint32_t addr, uint32_t* r) {
    asm volatile("ldmatrix.sync.aligned.m8n8.x4.trans.shared.b16 {%0,%1,%2,%3}, [%4];"
        : "=r"(r[0]), "=r"(r[1]), "=r"(r[2]), "=r"(r[3]) : "r"(addr));
}
__device__ __forceinline__ void mma_bf16(float* c, const uint32_t* a, uint32_t b0, uint32_t b1) {
    asm volatile("mma.sync.aligned.m16n8k16.row.col.f32.bf16.bf16.f32 "
        "{%0,%1,%2,%3}, {%4,%5,%6,%7}, {%8,%9}, {%0,%1,%2,%3};"
        : "+f"(c[0]), "+f"(c[1]), "+f"(c[2]), "+f"(c[3])
        : "r"(a[0]), "r"(a[1]), "r"(a[2]), "r"(a[3]), "r"(b0), "r"(b1));
}

__device__ __forceinline__ float fexp(float x) {
    x = fmaxf(x, -80.0f);
    float y = x * 1.4426950408889634f;
    float n = rintf(y);
    float g = fmaf(-n, 0.6931471805599453f, x);
    float p = 1.9841270e-4f;
    p = fmaf(p, g, 1.3888889e-3f);
    p = fmaf(p, g, 8.3333333e-3f);
    p = fmaf(p, g, 4.1666667e-2f);
    p = fmaf(p, g, 1.6666667e-1f);
    p = fmaf(p, g, 5.0e-1f);
    p = fmaf(p, g, 1.0f);
    p = fmaf(p, g, 1.0f);
    float s = __int_as_float(((int)n + 127) << 23);
    return p * s;
}
__device__ __forceinline__ void split4(float4 v,
    __nv_bfloat162& h01, __nv_bfloat162& l01,
    __nv_bfloat162& h23, __nv_bfloat162& l23) {
    h01.x = __float2bfloat16(v.x); l01.x = __float2bfloat16(v.x - __bfloat162float(h01.x));
    h01.y = __float2bfloat16(v.y); l01.y = __float2bfloat16(v.y - __bfloat162float(h01.y));
    h23.x = __float2bfloat16(v.z); l23.x = __float2bfloat16(v.z - __bfloat162float(h23.x));
    h23.y = __float2bfloat16(v.w); l23.y = __float2bfloat16(v.w - __bfloat162float(h23.y));
}
__device__ __forceinline__ void split2(float v, __nv_bfloat16& hi, __nv_bfloat16& lo) {
    hi = __float2bfloat16(v);
    lo = __float2bfloat16(v - __bfloat162float(hi));
}
__device__ __forceinline__ size_t tile_idx(int row, int col) {
    return (((size_t)(row >> 7) * 16 + (col >> 6)) * 128 + (row & 127)) * TPAD + (col & 63);
}

// ---------------- weight quant ----------------
__global__ void absmean_partial(const float* __restrict__ w, int n) {
    __shared__ float red[256];
    int tid = threadIdx.x;
    float s = 0.f;
    for (int i = blockIdx.x * 256 + tid; i < n; i += 65536) s += fabsf(w[i]);
    red[tid] = s; __syncthreads();
    for (int st = 128; st > 0; st >>= 1) { if (tid < st) red[tid] += red[tid + st]; __syncthreads(); }
    if (tid == 0) g_part[blockIdx.x] = red[0];
}

__global__ void __launch_bounds__(256) quant_weight_fused(const float* __restrict__ w,
                                                          __nv_bfloat16* __restrict__ wq,
                                                          int n, int slot) {
    __shared__ float red[256];
    int tid = threadIdx.x;
    red[tid] = g_part[tid]; __syncthreads();
    for (int st = 128; st > 0; st >>= 1) { if (tid < st) red[tid] += red[tid + st]; __syncthreads(); }
    float wdeq = fmaxf(red[0] / (float)n, 1e-5f);
    if (blockIdx.x == 0 && tid == 0) g_wdeq[slot] = wdeq;
    float s = 1.0f / wdeq;
    int i4 = (blockIdx.x * 256 + tid) * 4;
    if (i4 >= n) return;
    float4 wv = *(const float4*)(w + i4);
    __nv_bfloat162 p0, p1;
    p0.x = __float2bfloat16(fminf(fmaxf(rintf(wv.x * s), -1.f), 1.f));
    p0.y = __float2bfloat16(fminf(fmaxf(rintf(wv.y * s), -1.f), 1.f));
    p1.x = __float2bfloat16(fminf(fmaxf(rintf(wv.z * s), -1.f), 1.f));
    p1.y = __float2bfloat16(fminf(fmaxf(rintf(wv.w * s), -1.f), 1.f));
    int row = i4 >> 10, col = i4 & 1023;
    __nv_bfloat16* out = wq + tile_idx(row, col);
    *(__nv_bfloat162*)(out)     = p0;
    *(__nv_bfloat162*)(out + 2) = p1;
}

// ---------------- activation quant for QKV input ----------------
__global__ void __launch_bounds__(256) act_quant_x(const float* __restrict__ x,
                                                   const float* __restrict__ nw) {
    __shared__ float red[256];
    __shared__ float bc;
    int row = blockIdx.x, tid = threadIdx.x;
    float4 xv = ((const float4*)(x + (size_t)row * DIMC))[tid];
    float4 wv = ((const float4*)nw)[tid];
    float ss = xv.x*xv.x + xv.y*xv.y + xv.z*xv.z + xv.w*xv.w;
    red[tid] = ss; __syncthreads();
    for (int st = 128; st > 0; st >>= 1) { if (tid < st) red[tid] += red[tid + st]; __syncthreads(); }
    if (tid == 0) bc = rsqrtf(red[0] * (1.0f / DIMC) + EPS_BIT);
    __syncthreads();
    float r = bc;
    float n0 = xv.x*r*wv.x, n1 = xv.y*r*wv.y, n2 = xv.z*r*wv.z, n3 = xv.w*r*wv.w;
    float amax = fmaxf(fmaxf(fabsf(n0), fabsf(n1)), fmaxf(fabsf(n2), fabsf(n3)));
    red[tid] = amax; __syncthreads();
    for (int st = 128; st > 0; st >>= 1) { if (tid < st) red[tid] = fmaxf(red[tid], red[tid + st]); __syncthreads(); }
    if (tid == 0) {
        float mx = fmaxf(red[0], 1e-5f);
        bc = 127.0f / mx;
        g_adeq[row] = mx * (1.0f / 127.0f);
    }
    __syncthreads();
    float sc = bc;
    __nv_bfloat162 p0, p1;
    p0.x = __float2bfloat16(fminf(fmaxf(rintf(n0 * sc), -128.f), 127.f));
    p0.y = __float2bfloat16(fminf(fmaxf(rintf(n1 * sc), -128.f), 127.f));
    p1.x = __float2bfloat16(fminf(fmaxf(rintf(n2 * sc), -128.f), 127.f));
    p1.y = __float2bfloat16(fminf(fmaxf(rintf(n3 * sc), -128.f), 127.f));
    __nv_bfloat16* out = g_xq + tile_idx(row, tid * 4);
    *(__nv_bfloat162*)(out)     = p0;
    *(__nv_bfloat162*)(out + 2) = p1;
}

// ---------------- double-norm + act quant for proj input ----------------
__global__ void __launch_bounds__(256) norm2_quant(const float* __restrict__ nw,
                                                   const float* __restrict__ pnw) {
    __shared__ float red[256];
    __shared__ float bc;
    int row = blockIdx.x, tid = threadIdx.x;
    float4 xv = ((const float4*)(g_attn + (size_t)row * DIMC))[tid];
    float4 wv = ((const float4*)nw)[tid];
    float4 pv = ((const float4*)pnw)[tid];
    float ss = xv.x*xv.x + xv.y*xv.y + xv.z*xv.z + xv.w*xv.w;
    red[tid] = ss; __syncthreads();
    for (int st = 128; st > 0; st >>= 1) { if (tid < st) red[tid] += red[tid + st]; __syncthreads(); }
    if (tid == 0) bc = rsqrtf(red[0] * (1.0f / DIMC) + EPS_OUT);
    __syncthreads();
    float r1 = bc;
    float z0 = xv.x*r1*wv.x, z1 = xv.y*r1*wv.y, z2 = xv.z*r1*wv.z, z3 = xv.w*r1*wv.w;
    float ss2 = z0*z0 + z1*z1 + z2*z2 + z3*z3;
    red[tid] = ss2; __syncthreads();
    for (int st = 128; st > 0; st >>= 1) { if (tid < st) red[tid] += red[tid + st]; __syncthreads(); }
    if (tid == 0) bc = rsqrtf(red[0] * (1.0f / DIMC) + EPS_BIT);
    __syncthreads();
    float r2 = bc;
    float n0 = z0*r2*pv.x, n1 = z1*r2*pv.y, n2 = z2*r2*pv.z, n3 = z3*r2*pv.w;
    float amax = fmaxf(fmaxf(fabsf(n0), fabsf(n1)), fmaxf(fabsf(n2), fabsf(n3)));
    red[tid] = amax; __syncthreads();
    for (int st = 128; st > 0; st >>= 1) { if (tid < st) red[tid] = fmaxf(red[tid], red[tid + st]); __syncthreads(); }
    if (tid == 0) {
        float mx = fmaxf(red[0], 1e-5f);
        bc = 127.0f / mx;
        g_adeq2[row] = mx * (1.0f / 127.0f);
    }
    __syncthreads();
    float sc = bc;
    __nv_bfloat162 p0, p1;
    p0.x = __float2bfloat16(fminf(fmaxf(rintf(n0 * sc), -128.f), 127.f));
    p0.y = __float2bfloat16(fminf(fmaxf(rintf(n1 * sc), -128.f), 127.f));
    p1.x = __float2bfloat16(fminf(fmaxf(rintf(n2 * sc), -128.f), 127.f));
    p1.y = __float2bfloat16(fminf(fmaxf(rintf(n3 * sc), -128.f), 127.f));
    __nv_bfloat16* out = g_xq2 + tile_idx(row, tid * 4);
    *(__nv_bfloat162*)(out)     = p0;
    *(__nv_bfloat162*)(out + 2) = p1;
}

// ---------------- bf16 raw-mma GEMM: block 128x256, warp tile 64x64 ----------------
// raw mma.sync.m16n8k16 + ldmatrix (half the LDSM of WMMA); bulk 3-stage ring,
// producer/consumer mbarriers; epilogue direct from registers (no smem staging).
#define BSTAGE (3 * TILE_BYTES)
#define MBAR_OFF (3 * BSTAGE)
#define GEMM_SMEM (MBAR_OFF + 128)
template<bool QKV>
__global__ void __launch_bounds__(256) gemm_bf16_t(
    const __nv_bfloat16* __restrict__ A, const __nv_bfloat16* __restrict__ W,
    float* __restrict__ C, int N,
    const float* __restrict__ adeq, int wslot, const float* __restrict__ bias,
    const float* __restrict__ cosb, const float* __restrict__ sinb)
{
    extern __shared__ __align__(16) char gsm[];
    uint32_t sb = smem_u32(gsm);
    uint32_t fullb  = sb + MBAR_OFF;
    uint32_t emptyb = sb + MBAR_OFF + 24;

    int tid = threadIdx.x;
    int wid = tid >> 5, lane = tid & 31;
    int wm = wid >> 2, wn = wid & 3;            // warp tile 64(M) x 64(N)
    int bm = blockIdx.y * 128;
    int bn = blockIdx.x * 256;

    const __nv_bfloat16* Asrc  = A + (size_t)blockIdx.y * 16 * TILE_ELEMS;
    const __nv_bfloat16* Bsrc0 = W + (size_t)(2 * blockIdx.x)     * 16 * TILE_ELEMS;
    const __nv_bfloat16* Bsrc1 = W + (size_t)(2 * blockIdx.x + 1) * 16 * TILE_ELEMS;

    float c[4][8][4];
    #pragma unroll
    for (int mi = 0; mi < 4; mi++)
        #pragma unroll
        for (int nj = 0; nj < 8; nj++)
            #pragma unroll
            for (int e = 0; e < 4; e++) c[mi][nj][e] = 0.0f;

    if (tid == 0) {
        #pragma unroll
        for (int s = 0; s < 3; s++) {
            MBAR_INIT(fullb  + s * 8, 1);
            MBAR_INIT(emptyb + s * 8, 8);
        }
    }
    __syncthreads();
    if (tid == 0) {
        #pragma unroll
        for (int s = 0; s < 2; s++) {
            MBAR_EXPECT_TX(fullb + s * 8, BSTAGE);
            BULK_G2S(sb + s * BSTAGE,                  Asrc  + s * TILE_ELEMS, TILE_BYTES, fullb + s * 8);
            BULK_G2S(sb + s * BSTAGE + TILE_BYTES,     Bsrc0 + s * TILE_ELEMS, TILE_BYTES, fullb + s * 8);
            BULK_G2S(sb + s * BSTAGE + 2 * TILE_BYTES, Bsrc1 + s * TILE_ELEMS, TILE_BYTES, fullb + s * 8);
        }
    }

    int m0 = wm * 64;
    int bhalf = (wn >> 1);
    int n0 = (wn & 1) * 64;
    uint32_t aoff = (uint32_t)(lane & 15) * 144 + (lane >> 4) * 16;
    uint32_t boff = (uint32_t)(((lane >> 4) & 1) * 8 + (lane & 7)) * 144 + ((lane >> 3) & 1) * 16;

    for (int kt = 0; kt < 16; kt++) {
        int sRead = kt % 3;
        if (tid == 0 && kt + 2 < 16) {
            int sW = (kt + 2) % 3;
            if (kt >= 1) MBAR_WAIT_PARITY(emptyb + sW * 8, ((kt - 1) / 3) & 1);
            MBAR_EXPECT_TX(fullb + sW * 8, BSTAGE);
            BULK_G2S(sb + sW * BSTAGE,                  Asrc  + (kt + 2) * TILE_ELEMS, TILE_BYTES, fullb + sW * 8);
            BULK_G2S(sb + sW * BSTAGE + TILE_BYTES,     Bsrc0 + (kt + 2) * TILE_ELEMS, TILE_BYTES, fullb + sW * 8);
            BULK_G2S(sb + sW * BSTAGE + 2 * TILE_BYTES, Bsrc1 + (kt + 2) * TILE_ELEMS, TILE_BYTES, fullb + sW * 8);
        }
        MBAR_WAIT_PARITY(fullb + sRead * 8, (kt / 3) & 1);
        uint32_t as = sb + sRead * BSTAGE;
        uint32_t bs = as + TILE_BYTES + bhalf * TILE_BYTES;
        #pragma unroll
        for (int sk = 0; sk < 4; sk++) {
            uint32_t kb2 = sk * 32;
            uint32_t a[4][4];
            #pragma unroll
            for (int mi = 0; mi < 4; mi++)
                ldm_x4(as + (uint32_t)(m0 + mi * 16) * 144 + aoff + kb2, a[mi]);
            #pragma unroll
            for (int nj2 = 0; nj2 < 4; nj2++) {
                uint32_t bfr[4];
                ldm_x4(bs + (uint32_t)(n0 + nj2 * 16) * 144 + boff + kb2, bfr);
                #pragma unroll
                for (int mi = 0; mi < 4; mi++) {
                    mma_bf16(c[mi][2*nj2],   a[mi], bfr[0], bfr[1]);
                    mma_bf16(c[mi][2*nj2+1], a[mi], bfr[2], bfr[3]);
                }
            }
        }
        if (lane == 0) MBAR_ARRIVE(emptyb + sRead * 8);
    }

    // epilogue: directly from accumulator registers (rows g/g+8, cols 2tq/2tq+1)
    float wdeq = g_wdeq[wslot];
    int g = lane >> 2, tq = lane & 3;
    #pragma unroll
    for (int mi = 0; mi < 4; mi++) {
        int row_lo = bm + m0 + mi * 16 + g;
        int row_hi = row_lo + 8;
        float sc_lo = adeq[row_lo] * wdeq;
        float sc_hi = adeq[row_hi] * wdeq;
        #pragma unroll
        for (int nj = 0; nj < 8; nj++) {
            int col = bn + wn * 64 + nj * 8 + 2 * tq;
            float2 bb = *(const float2*)(bias + col);
            float v0 = c[mi][nj][0] * sc_lo + bb.x;
            float v1 = c[mi][nj][1] * sc_lo + bb.y;
            float v2 = c[mi][nj][2] * sc_hi + bb.x;
            float v3 = c[mi][nj][3] * sc_hi + bb.y;
            if (QKV) {
                int which = col >> 10;
                int rem = col & 1023;
                int hh = rem >> 6, d = rem & 63;
                int b_lo = row_lo >> 13, n_lo = row_lo & 8191;
                int b_hi = row_hi >> 13, n_hi = row_hi & 8191;
                if (which < 2) {
                    int i0 = d >> 1;
                    float cl = cosb[n_lo * 32 + i0], sl = sinb[n_lo * 32 + i0];
                    float ch = cosb[n_hi * 32 + i0], sh = sinb[n_hi * 32 + i0];
                    float e = v0, o = v1;
                    v0 = e * cl - o * sl; v1 = o * cl + e * sl;
                    e = v2; o = v3;
                    v2 = e * ch - o * sh; v3 = o * ch + e * sh;
                }
                float* dstbase = (which == 0) ? g_q : (which == 1) ? g_k : g_v;
                int t_lo = n_lo >> 7, rr_lo = n_lo & 127;
                int t_hi = n_hi >> 7, rr_hi = n_hi & 127;
                float* dst_lo = dstbase + (((size_t)b_lo * NH + hh) * NT + t_lo) * (CHUNK * HD)
                              + (size_t)rr_lo * 64 + d;
                float* dst_hi = dstbase + (((size_t)b_hi * NH + hh) * NT + t_hi) * (CHUNK * HD)
                              + (size_t)rr_hi * 64 + d;
                *(float2*)dst_lo = make_float2(v0, v1);
                *(float2*)dst_hi = make_float2(v2, v3);
            } else {
                *(float2*)(C + (size_t)row_lo * N + col) = make_float2(v0, v1);
                *(float2*)(C + (size_t)row_hi * N + col) = make_float2(v2, v3);
            }
        }
    }
}

// ---------------- intra-chunk attention: raw mma, S/P register-resident ----------------
#define ATT_SMEM (4 * 128 * 72 * 2)
__global__ void __launch_bounds__(256, 2) attn_intra() {
    int t = blockIdx.x, h = blockIdx.y, b = blockIdx.z;
    extern __shared__ __align__(16) char smraw[];
    __nv_bfloat16* sQhi = (__nv_bfloat16*)smraw;
    __nv_bfloat16* sQlo = sQhi + 128 * 72;
    __nv_bfloat16* sKhi = sQhi + 2 * 128 * 72;
    __nv_bfloat16* sKlo = sQhi + 3 * 128 * 72;
    uint32_t qhi = smem_u32(sQhi), qlo = qhi + TILE_BYTES;
    uint32_t khi = qhi + 2 * TILE_BYTES, klo = qhi + 3 * TILE_BYTES;

    size_t base = (((size_t)b * NH + h) * NT + t) * (CHUNK * HD);
    int tid = threadIdx.x;
    int wid = tid >> 5, lane = tid & 31;
    int g = lane >> 2, tq = lane & 3;

    #pragma unroll
    for (int u = 0; u < 8; u++) {
        int i = tid + u * 256;
        int r = i >> 4, c4 = (i & 15) * 4;
        float4 qv = *(const float4*)(g_q + base + (size_t)r * 64 + c4);
        float4 kv = *(const float4*)(g_k + base + (size_t)r * 64 + c4);
        __nv_bfloat162 h01, l01, h23, l23;
        split4(qv, h01, l01, h23, l23);
        *(__nv_bfloat162*)(sQhi + r*72 + c4)     = h01;
        *(__nv_bfloat162*)(sQhi + r*72 + c4 + 2) = h23;
        *(__nv_bfloat162*)(sQlo + r*72 + c4)     = l01;
        *(__nv_bfloat162*)(sQlo + r*72 + c4 + 2) = l23;
        split4(kv, h01, l01, h23, l23);
        *(__nv_bfloat162*)(sKhi + r*72 + c4)     = h01;
        *(__nv_bfloat162*)(sKhi + r*72 + c4 + 2) = h23;
        *(__nv_bfloat162*)(sKlo + r*72 + c4)     = l01;
        *(__nv_bfloat162*)(sKlo + r*72 + c4 + 2) = l23;
    }
    __syncthreads();

    int r0 = wid * 16;
    int row_lo = r0 + g, row_hi = r0 + g + 8;
    float sacc[16][4];
    #pragma unroll
    for (int nt = 0; nt < 16; nt++)
        #pragma unroll
        for (int e = 0; e < 4; e++) sacc[nt][e] = 0.0f;

    uint32_t a_off = (uint32_t)(r0 + (lane & 15)) * 144 + (lane >> 4) * 16;
    uint32_t b_off = (uint32_t)(((lane >> 4) & 1) * 8 + (lane & 7)) * 144 + ((lane >> 3) & 1) * 16;
    #pragma unroll
    for (int kc = 0; kc < 4; kc++) {
        uint32_t kb2 = kc * 32;
        uint32_t ah[4], al[4];
        ldm_x4(qhi + a_off + kb2, ah);
        ldm_x4(qlo + a_off + kb2, al);
        #pragma unroll
        for (int nt2 = 0; nt2 < 8; nt2++) {
            if (nt2 <= wid) {
                uint32_t baddr = (uint32_t)(nt2 * 16) * 144 + b_off + kb2;
                uint32_t bh[4], bl[4];
                ldm_x4(khi + baddr, bh);
                ldm_x4(klo + baddr, bl);
                mma_bf16(sacc[2*nt2],   ah, bh[0], bh[1]);
                mma_bf16(sacc[2*nt2],   ah, bl[0], bl[1]);
                mma_bf16(sacc[2*nt2],   al, bh[0], bh[1]);
                mma_bf16(sacc[2*nt2+1], ah, bh[2], bh[3]);
                mma_bf16(sacc[2*nt2+1], ah, bl[2], bl[3]);
                mma_bf16(sacc[2*nt2+1], al, bh[2], bh[3]);
            }
        }
    }

    float mx_lo = -3.0e38f, mx_hi = -3.0e38f;
    #pragma unroll
    for (int nt = 0; nt < 16; nt++) {
        if ((nt >> 1) <= wid) {
            int c0 = nt * 8 + 2 * tq;
            if (c0     <= row_lo) mx_lo = fmaxf(mx_lo, sacc[nt][0] * SCALE_ATTN);
            if (c0 + 1 <= row_lo) mx_lo = fmaxf(mx_lo, sacc[nt][1] * SCALE_ATTN);
            if (c0     <= row_hi) mx_hi = fmaxf(mx_hi, sacc[nt][2] * SCALE_ATTN);
            if (c0 + 1 <= row_hi) mx_hi = fmaxf(mx_hi, sacc[nt][3] * SCALE_ATTN);
        }
    }
    mx_lo = fmaxf(mx_lo, __shfl_xor_sync(0xffffffffu, mx_lo, 1));
    mx_lo = fmaxf(mx_lo, __shfl_xor_sync(0xffffffffu, mx_lo, 2));
    mx_hi = fmaxf(mx_hi, __shfl_xor_sync(0xffffffffu, mx_hi, 1));
    mx_hi = fmaxf(mx_hi, __shfl_xor_sync(0xffffffffu, mx_hi, 2));

    float sum_lo = 0.f, sum_hi = 0.f;
    #pragma unroll
    for (int nt = 0; nt < 16; nt++) {
        if ((nt >> 1) <= wid) {
            int c0 = nt * 8 + 2 * tq;
            float e0 = (c0     <= row_lo) ? fexp(sacc[nt][0] * SCALE_ATTN - mx_lo) : 0.f;
            float e1 = (c0 + 1 <= row_lo) ? fexp(sacc[nt][1] * SCALE_ATTN - mx_lo) : 0.f;
            float e2 = (c0     <= row_hi) ? fexp(sacc[nt][2] * SCALE_ATTN - mx_hi) : 0.f;
            float e3 = (c0 + 1 <= row_hi) ? fexp(sacc[nt][3] * SCALE_ATTN - mx_hi) : 0.f;
            sum_lo += e0 + e1;
            sum_hi += e2 + e3;
            __nv_bfloat16 h0, l0, h1, l1;
            split2(e0, h0, l0); split2(e1, h1, l1);
            __nv_bfloat162 ph; ph.x = h0; ph.y = h1;
            __nv_bfloat162 pl; pl.x = l0; pl.y = l1;
            sacc[nt][0] = __uint_as_float(*(uint32_t*)&ph);
            sacc[nt][1] = __uint_as_float(*(uint32_t*)&pl);
            split2(e2, h0, l0); split2(e3, h1, l1);
            ph.x = h0; ph.y = h1; pl.x = l0; pl.y = l1;
            sacc[nt][2] = __uint_as_float(*(uint32_t*)&ph);
            sacc[nt][3] = __uint_as_float(*(uint32_t*)&pl);
        }
    }
    sum_lo += __shfl_xor_sync(0xffffffffu, sum_lo, 1);
    sum_lo += __shfl_xor_sync(0xffffffffu, sum_lo, 2);
    sum_hi += __shfl_xor_sync(0xffffffffu, sum_hi, 1);
    sum_hi += __shfl_xor_sync(0xffffffffu, sum_hi, 2);

    __syncthreads();
    #pragma unroll
    for (int u = 0; u < 8; u++) {
        int i = tid + u * 256;
        int r = i >> 4, c4 = (i & 15) * 4;
        float4 vv = *(const float4*)(g_v + base + (size_t)r * 64 + c4);
        __nv_bfloat162 h01, l01, h23, l23;
        split4(vv, h01, l01, h23, l23);
        *(__nv_bfloat162*)(sQhi + r*72 + c4)     = h01;
        *(__nv_bfloat162*)(sQhi + r*72 + c4 + 2) = h23;
        *(__nv_bfloat162*)(sQlo + r*72 + c4)     = l01;
        *(__nv_bfloat162*)(sQlo + r*72 + c4 + 2) = l23;
    }
    __syncthreads();
    uint32_t vhi = qhi, vlo = qlo;

    uint32_t vt_off = (uint32_t)(((lane >> 3) & 1) * 8 + (lane & 7)) * 144 + ((lane >> 4) & 1) * 16;
    float o[8][4];
    #pragma unroll
    for (int j = 0; j < 8; j++)
        #pragma unroll
        for (int e = 0; e < 4; e++) o[j][e] = 0.f;
    #pragma unroll
    for (int q = 0; q < 8; q++) {
        if (q <= wid) {
            uint32_t pa_h[4] = { __float_as_uint(sacc[2*q][0]), __float_as_uint(sacc[2*q][2]),
                                 __float_as_uint(sacc[2*q+1][0]), __float_as_uint(sacc[2*q+1][2]) };
            uint32_t pa_l[4] = { __float_as_uint(sacc[2*q][1]), __float_as_uint(sacc[2*q][3]),
                                 __float_as_uint(sacc[2*q+1][1]), __float_as_uint(sacc[2*q+1][3]) };
            uint32_t kbytes = (uint32_t)(q * 16) * 144;
            #pragma unroll
            for (int nt2 = 0; nt2 < 4; nt2++) {
                uint32_t vaddr = kbytes + vt_off + (nt2 * 16) * 2;
                uint32_t vh[4], vl[4];
                ldm_x4_t(vhi + vaddr, vh);
                ldm_x4_t(vlo + vaddr, vl);
                mma_bf16(o[2*nt2],   pa_h, vh[0], vh[1]);
                mma_bf16(o[2*nt2],   pa_h, vl[0], vl[1]);
                mma_bf16(o[2*nt2],   pa_l, vh[0], vh[1]);
                mma_bf16(o[2*nt2+1], pa_h, vh[2], vh[3]);
                mma_bf16(o[2*nt2+1], pa_h, vl[2], vl[3]);
                mma_bf16(o[2*nt2+1], pa_l, vh[2], vh[3]);
            }
        }
    }
    {
        float inv_lo = 1.0f / sum_lo, inv_hi = 1.0f / sum_hi;
        float* dlo = g_attn + ((size_t)b * SEQ + (size_t)t * CHUNK + row_lo) * DIMC + h * 64;
        float* dhi = g_attn + ((size_t)b * SEQ + (size_t)t * CHUNK + row_hi) * DIMC + h * 64;
        #pragma unroll
        for (int j = 0; j < 8; j++) {
            int col = j * 8 + 2 * tq;
            *(float2*)(dlo + col) = make_float2(o[j][0] * inv_lo, o[j][1] * inv_lo);
            *(float2*)(dhi + col) = make_float2(o[j][2] * inv_hi, o[j][3] * inv_hi);
        }
    }

    {
        int d0 = (wid >> 1) * 16;
        int e0 = (wid & 1) * 32;
        float kv[4][4];
        #pragma unroll
        for (int j = 0; j < 4; j++)
            #pragma unroll
            for (int e = 0; e < 4; e++) kv[j][e] = 0.f;
        uint32_t kt_off = (uint32_t)(((lane >> 4) & 1) * 8 + (lane & 7)) * 144 + ((lane >> 3) & 1) * 16;
        #pragma unroll
        for (int kc = 0; kc < 8; kc++) {
            uint32_t kbytes = (uint32_t)(kc * 16) * 144;
            uint32_t ah[4], al[4];
            ldm_x4_t(khi + kbytes + kt_off + d0 * 2, ah);
            ldm_x4_t(klo + kbytes + kt_off + d0 * 2, al);
            #pragma unroll
            for (int nt2 = 0; nt2 < 2; nt2++) {
                uint32_t vaddr = kbytes + vt_off + (e0 + nt2 * 16) * 2;
                uint32_t vh[4], vl[4];
                ldm_x4_t(vhi + vaddr, vh);
                ldm_x4_t(vlo + vaddr, vl);
                mma_bf16(kv[2*nt2],   ah, vh[0], vh[1]);
                mma_bf16(kv[2*nt2],   ah, vl[0], vl[1]);
                mma_bf16(kv[2*nt2],   al, vh[0], vh[1]);
                mma_bf16(kv[2*nt2+1], ah, vh[2], vh[3]);
                mma_bf16(kv[2*nt2+1], ah, vl[2], vl[3]);
                mma_bf16(kv[2*nt2+1], al, vh[2], vh[3]);
            }
        }
        size_t kb = (((size_t)b * NH + h) * NT + t) * (HD * HD);
        float* klo_p = g_kvsum + kb + (size_t)(d0 + g) * 64 + e0;
        float* khi_p = g_kvsum + kb + (size_t)(d0 + g + 8) * 64 + e0;
        #pragma unroll
        for (int j = 0; j < 4; j++) {
            int col = j * 8 + 2 * tq;
            *(float2*)(klo_p + col) = make_float2(kv[j][0], kv[j][1]);
            *(float2*)(khi_p + col) = make_float2(kv[j][2], kv[j][3]);
        }
    }
}

// ---------------- exclusive prefix-sum of chunk KV matrices ----------------
__global__ void __launch_bounds__(256) kv_prefix() {
    int blk = blockIdx.x;
    int bh = blk >> 3, s = blk & 7;
    int tid = threadIdx.x;
    size_t base = (size_t)bh * NT * (HD * HD) + s * 512 + tid * 2;
    float2 acc = make_float2(0.f, 0.f);
    for (int t = 0; t < NT; t++) {
        size_t off = base + (size_t)t * (HD * HD);
        float2 v = *(const float2*)(g_kvsum + off);
        *(float2*)(g_kvpre + off) = acc;
        acc.x += v.x; acc.y += v.y;
    }
}

// ---------------- o_inter = q @ kv_prefix ----------------
#define IQHI 0
#define IQLO (128*72)
#define IKHI (2*128*72)
#define IKLO (2*128*72 + 64*72)
#define IBF_TOTAL (2*128*72 + 2*64*72)
__global__ void __launch_bounds__(256) attn_inter() {
    int t = blockIdx.x, h = blockIdx.y, b = blockIdx.z;
    extern __shared__ __align__(16) char smraw2[];
    __nv_bfloat16* bfm = (__nv_bfloat16*)smraw2;
    float* sO = (float*)(smraw2 + (size_t)IBF_TOTAL * 2);

    __nv_bfloat16* sQhi = bfm + IQHI;
    __nv_bfloat16* sQlo = bfm + IQLO;
    __nv_bfloat16* sKhi = bfm + IKHI;
    __nv_bfloat16* sKlo = bfm + IKLO;

    size_t base = (((size_t)b * NH + h) * NT + t) * (CHUNK * HD);
    size_t kb   = (((size_t)b * NH + h) * NT + t) * (HD * HD);
    int tid = threadIdx.x;
    int wid = tid >> 5;

    #pragma unroll
    for (int u = 0; u < 8; u++) {
        int i = tid + u * 256;
        int r = i >> 4, c4 = (i & 15) * 4;
        float4 qv = *(const float4*)(g_q + base + (size_t)r * 64 + c4);
        __nv_bfloat162 h01, l01, h23, l23;
        split4(qv, h01, l01, h23, l23);
        *(__nv_bfloat162*)(sQhi + r*72 + c4)     = h01;
        *(__nv_bfloat162*)(sQhi + r*72 + c4 + 2) = h23;
        *(__nv_bfloat162*)(sQlo + r*72 + c4)     = l01;
        *(__nv_bfloat162*)(sQlo + r*72 + c4 + 2) = l23;
    }
    #pragma unroll
    for (int u = 0; u < 4; u++) {
        int i = tid + u * 256;
        int r = i >> 4, c4 = (i & 15) * 4;
        float4 kv = *(const float4*)(g_kvpre + kb + (size_t)r * 64 + c4);
        __nv_bfloat162 h01, l01, h23, l23;
        split4(kv, h01, l01, h23, l23);
        *(__nv_bfloat162*)(sKhi + r*72 + c4)     = h01;
        *(__nv_bfloat162*)(sKhi + r*72 + c4 + 2) = h23;
        *(__nv_bfloat162*)(sKlo + r*72 + c4)     = l01;
        *(__nv_bfloat162*)(sKlo + r*72 + c4 + 2) = l23;
    }
    __syncthreads();

    {
        int r0 = wid * 16;
        wmma::fragment<wmma::accumulator, 16, 16, 16, float> c[4];
        #pragma unroll
        for (int j = 0; j < 4; j++) wmma::fill_fragment(c[j], 0.0f);
        #pragma unroll
        for (int sk = 0; sk < 4; sk++) {
            int k0 = sk * 16;
            wmma::fragment<wmma::matrix_a, 16, 16, 16, __nv_bfloat16, wmma::row_major> ah, al;
            wmma::load_matrix_sync(ah, &sQhi[r0 * 72 + k0], 72);
            wmma::load_matrix_sync(al, &sQlo[r0 * 72 + k0], 72);
            #pragma unroll
            for (int j = 0; j < 4; j++) {
                int col0 = j * 16;
                wmma::fragment<wmma::matrix_b, 16, 16, 16, __nv_bfloat16, wmma::row_major> bh, bl;
                wmma::load_matrix_sync(bh, &sKhi[k0 * 72 + col0], 72);
                wmma::load_matrix_sync(bl, &sKlo[k0 * 72 + col0], 72);
                wmma::mma_sync(c[j], ah, bh, c[j]);
                wmma::mma_sync(c[j], ah, bl, c[j]);
                wmma::mma_sync(c[j], al, bh, c[j]);
            }
        }
        #pragma unroll
        for (int j = 0; j < 4; j++)
            wmma::store_matrix_sync(&sO[r0 * 68 + j * 16], c[j], 68, wmma::mem_row_major);
    }
    __syncthreads();

    #pragma unroll
    for (int u = 0; u < 8; u++) {
        int i = tid + u * 256;
        int r = i >> 4, c4 = (i & 15) * 4;
        size_t grow = (size_t)b * SEQ + (size_t)t * CHUNK + r;
        float* dst = g_attn + grow * DIMC + h * 64 + c4;
        float4 old = *(float4*)dst;
        old.x += sO[r * 68 + c4 + 0];
        old.y += sO[r * 68 + c4 + 1];
        old.z += sO[r * 68 + c4 + 2];
        old.w += sO[r * 68 + c4 + 3];
        *(float4*)dst = old;
    }
}

// ---------------- launch ----------------
extern "C" void kernel_launch(void* const* d_in, const int* in_sizes, int n_in,
                              void* d_out, int out_size) {
    const float* x       = (const float*)d_in[0];
    const float* cosb    = (const float*)d_in[1];
    const float* sinb    = (const float*)d_in[2];
    const float* qkv_w   = (const float*)d_in[3];
    const float* qkv_b   = (const float*)d_in[4];
    const float* qkv_nw  = (const float*)d_in[5];
    const float* proj_w  = (const float*)d_in[6];
    const float* proj_b  = (const float*)d_in[7];
    const float* proj_nw = (const float*)d_in[8];
    const float* norm_w  = (const float*)d_in[9];
    float* out = (float*)d_out;

    size_t smem_inter = (size_t)IBF_TOTAL * 2 + (128 * 68) * sizeof(float);

    static bool attr_done = false;
    if (!attr_done) {
        cudaFuncSetAttribute(attn_intra, cudaFuncAttributeMaxDynamicSharedMemorySize, ATT_SMEM);
        cudaFuncSetAttribute(attn_inter, cudaFuncAttributeMaxDynamicSharedMemorySize, (int)smem_inter);
        cudaFuncSetAttribute(gemm_bf16_t<true>,  cudaFuncAttributeMaxDynamicSharedMemorySize, GEMM_SMEM);
        cudaFuncSetAttribute(gemm_bf16_t<false>, cudaFuncAttributeMaxDynamicSharedMemorySize, GEMM_SMEM);
        attr_done = true;
    }

    __nv_bfloat16 *xq_p, *wqkv_p, *wproj_p, *xq2_p;
    float *adeq_p, *adeq2_p;
    cudaGetSymbolAddress((void**)&xq_p,    g_xq);
    cudaGetSymbolAddress((void**)&wqkv_p,  g_wq_qkv);
    cudaGetSymbolAddress((void**)&wproj_p, g_wq_proj);
    cudaGetSymbolAddress((void**)&xq2_p,   g_xq2);
    cudaGetSymbolAddress((void**)&adeq_p,  g_adeq);
    cudaGetSymbolAddress((void**)&adeq2_p, g_adeq2);

    // Launch order: gemm<QKV> is launch #4 -> ncu capture slot.
    absmean_partial<<<256, 256>>>(qkv_w, QKVN * DIMC);                                    // 1
    quant_weight_fused<<<QKVN * DIMC / 1024, 256>>>(qkv_w, wqkv_p, QKVN * DIMC, 0);       // 2
    act_quant_x<<<NROWS, 256>>>(x, qkv_nw);                                               // 3
    {
        dim3 grid(QKVN / 256, NROWS / 128);
        gemm_bf16_t<true><<<grid, 256, GEMM_SMEM>>>(xq_p, wqkv_p, nullptr, QKVN,
                                                    adeq_p, 0, qkv_b, cosb, sinb);        // 4 <- profiled
    }
    absmean_partial<<<256, 256>>>(proj_w, DIMC * DIMC);                                   // 5
    quant_weight_fused<<<DIMC * DIMC / 1024, 256>>>(proj_w, wproj_p, DIMC * DIMC, 1);     // 6

    {
        dim3 grid(NT, NH, BATCH);
        attn_intra<<<grid, 256, ATT_SMEM>>>();                                            // 7
    }
    kv_prefix<<<256, 256>>>();                                                            // 8
    {
        dim3 grid(NT, NH, BATCH);
        attn_inter<<<grid, 256, smem_inter>>>();                                          // 9
    }

    norm2_quant<<<NROWS, 256>>>(norm_w, proj_nw);                                         // 10
    {
        dim3 grid(DIMC / 256, NROWS / 128);
        gemm_bf16_t<false><<<grid, 256, GEMM_SMEM>>>(xq2_p, wproj_p, out, DIMC,
                                                     adeq2_p, 1, proj_b, cosb, sinb);     // 11
    }
}